// round 10
// baseline (speedup 1.0000x reference)
#include <cuda_runtime.h>
#include <cuda_bf16.h>
#include <math.h>
#include <stdint.h>

#define K 128
#define KK (K*K)
#define NN 10000
#define EE 160000
#define NE_ 10
#define NB_ 8
#define GG 16
#define NK (NN*K)
#define TM 64
#define TN 256
#define GT_PER_Z 40          /* CDIV(NN,TN) */

#define SQ3F 1.7320508075688772f
#define INV_SQ3 0.5773502691896258f
#define PI_F 3.14159265358979323846f
#define CB_F 0.6324555320336759f
#define ALPHA_ (1.0f/16.0f)
#define CDIV(a,b) (((a)+(b)-1)/(b))

/* ---- smem layout for tensor GEMM: W full, A in 64-row quarters ---------- */
#define PITCH_B 272
#define W_H_B 0
#define W_L_B 34816
#define A_H_B 69632
#define A_L_B 87040
#define ROWIDX_B 104448      /* 256 ints */
#define TG_SMEM 105472       /* 103 KB -> 2 CTAs/SM, 1024 thr/SM */

__device__ __forceinline__ uint32_t smem_u32(const void* p){
  uint32_t a;
  asm("{ .reg .u64 t; cvta.to.shared.u64 t, %1; cvt.u32.u64 %0, t; }" : "=r"(a) : "l"(p));
  return a;
}
#define LDM4(r, addr) \
  asm volatile("ldmatrix.sync.aligned.m8n8.x4.shared.b16 {%0,%1,%2,%3}, [%4];" \
    : "=r"((r)[0]),"=r"((r)[1]),"=r"((r)[2]),"=r"((r)[3]) : "r"(addr))
#define MMA16816(c, a, b0, b1) \
  asm volatile("mma.sync.aligned.m16n8k16.row.col.f32.bf16.bf16.f32 " \
    "{%0,%1,%2,%3}, {%4,%5,%6,%7}, {%8,%9}, {%0,%1,%2,%3};" \
    : "+f"((c)[0]),"+f"((c)[1]),"+f"((c)[2]),"+f"((c)[3]) \
    : "r"((a)[0]),"r"((a)[1]),"r"((a)[2]),"r"((a)[3]), "r"(b0),"r"(b1))

__device__ __forceinline__ uint32_t pk_bf2(__nv_bfloat16 a, __nv_bfloat16 b){
  return (uint32_t)__bfloat16_as_ushort(a) | ((uint32_t)__bfloat16_as_ushort(b) << 16);
}

/* ------------------- device scratch (no allocs allowed) ------------------ */
__device__ float g_sU1[NE_*K];
__device__ float g_tabU2[NE_*K];
__device__ float g_tabS2[NE_*K];
__device__ float g_t1[NE_];
__device__ float g_u[K];
__device__ float g_r[EE];
__device__ float g_Y1[EE*3];
__device__ float g_ef[EE*NB_];
__device__ int   g_esnd[EE], g_ercv[EE], g_ezsnd[EE];
__device__ int   g_nact;
__device__ float g_A0[NK];
__device__ float g_A1[3*NK];
__device__ float g_sU2[NK];
__device__ float g_vU2[3*NK];
__device__ float g_A2[NK];
__device__ float g_s2[NK];
__device__ float g_ds2[NK];
__device__ float g_dA2[NK];
__device__ float g_Dsj2[NK];
__device__ float g_Dvj[3*NK];
__device__ float g_dA0[NK];
__device__ float g_dA1[3*NK];
__device__ float g_def[EE*NB_];
__device__ float g_dY1b[EE*3];
__device__ float g_e0[GG], g_e1[GG], g_e2[GG];
__device__ float g_WF[12*KK];     /* [0]=WF1, [1]=Wfuse, [2+z]=WF2z */
__device__ __nv_bfloat16 g_Bh[26*KK];
__device__ __nv_bfloat16 g_Bl[26*KK];
__device__ int g_zoff[NE_+1], g_zperm[NN];

/* -------- fp32 multi-op GEMM struct (weight precompute) ------------------ */
#define MAXG 12
struct GOps {
  int count;
  int tiles[MAXG];
  const float* A[MAXG];
  const float* B[MAXG];
  float* C[MAXG];
  int M[MAXG];
};

/* ================= init: zero + per-z tables + weight GEMMs ============== */
#define ZB 2048
__global__ void __launch_bounds__(256) init_kernel(float* __restrict__ out, int out_size, GOps P,
    const float* __restrict__ We, const float* __restrict__ Wu1, const float* __restrict__ Wsk1,
    const float* __restrict__ Wu2s, const float* __restrict__ Wsk2, const float* __restrict__ Wms1,
    const float* __restrict__ wr1){
  __shared__ char ubuf[32768];
  int b = blockIdx.x;
  int tid = threadIdx.x;
  if (b < ZB){
    int total = 3*NK;
    if (out_size > total) total = out_size;
    for (int i = b*256 + tid; i < total; i += ZB*256){
      if (i < 3*NK){ g_A1[i]=0.f; g_Dvj[i]=0.f; }
      if (i < NK){ g_A0[i]=0.f; g_A2[i]=0.f; g_Dsj2[i]=0.f; }
      if (i < out_size) out[i]=0.f;
      if (i < GG){ g_e0[i]=0.f; g_e1[i]=0.f; g_e2[i]=0.f; }
      if (i == 0) g_nact = 0;
    }
    return;
  }
  if (b < ZB + 11){
    int z = b - ZB;
    if (tid >= 128) return;
    int d = tid;
    float* sh  = (float*)ubuf;
    float* red = (float*)(ubuf + 512);
    if (z == NE_){
      float a = 0.f;
      for (int m = 0; m < K; m++) a = fmaf(Wms1[d*K + m], wr1[m], a);
      g_u[d] = a;
      return;
    }
    float a = 0.f, bb = 0.f;
    for (int c = 0; c < K; c++){
      float s = We[z*K + c];
      a  = fmaf(s, Wu1[c*K + d], a);
      bb = fmaf(s, Wsk1[(z*K + c)*K + d], bb);
    }
    g_sU1[z*K + d] = a;
    sh[d] = bb;
    __syncthreads();
    float t2 = 0.f, t3 = 0.f;
    for (int c = 0; c < K; c++){
      float s = sh[c];
      t2 = fmaf(s, Wu2s[c*K + d], t2);
      t3 = fmaf(s, Wsk2[(z*K + c)*K + d], t3);
    }
    g_tabU2[z*K + d] = t2;
    g_tabS2[z*K + d] = t3;
    float p = sh[d]*wr1[d];
    #pragma unroll
    for (int o = 16; o; o >>= 1) p += __shfl_down_sync(0xffffffffu, p, o);
    if ((d & 31) == 0) red[d >> 5] = p;
    __syncthreads();
    if (d == 0) g_t1[z] = red[0] + red[1] + red[2] + red[3];
    return;
  }
  b -= (ZB + 11);
  int op = 0;
  while (b >= P.tiles[op]){ b -= P.tiles[op]; op++; }
  typedef float (*AsT)[K];
  AsT As = (AsT)ubuf;
  int d = tid & 127;
  int g = tid >> 7;
  int M = P.M[op];
  const float* __restrict__ A = P.A[op];
  int base0 = b*TM;
  #pragma unroll 4
  for (int i = 0; i < 32; i++){
    int r = g*32 + i;
    As[r][d] = (base0 + r < M) ? A[(base0 + r)*K + d] : 0.f;
  }
  __syncthreads();
  const float* __restrict__ B = P.B[op];
  float acc[32];
  #pragma unroll
  for (int i = 0; i < 32; i++) acc[i] = 0.f;
  for (int c = 0; c < K; c += 4){
    float b0=B[c*K+d], b1=B[(c+1)*K+d], b2=B[(c+2)*K+d], b3=B[(c+3)*K+d];
    #pragma unroll
    for (int i = 0; i < 32; i++){
      float4 av = *(const float4*)&As[g*32 + i][c];
      acc[i] = fmaf(av.x,b0,fmaf(av.y,b1,fmaf(av.z,b2,fmaf(av.w,b3,acc[i]))));
    }
  }
  float* __restrict__ C = P.C[op];
  int base = base0 + g*32;
  for (int i = 0; i < 32; i++){
    int n = base + i;
    if (n >= M) break;
    C[n*K + d] = acc[i];
  }
}

/* ============ work1: geom + conv (split bf16) + z count/scan/scatter ===== */
__global__ void __launch_bounds__(256) work1_kernel(const float* __restrict__ pos,
    const float* __restrict__ shifts, const int* __restrict__ ei, const int* __restrict__ nz,
    const float* __restrict__ WF, const float* __restrict__ Wms2){
  int b = blockIdx.x;
  if (b < 625){
    int e = b*256 + threadIdx.x;
    if (e >= EE) return;
    int s = ei[e], rc = ei[EE + e];
    float vx = pos[rc*3+0] - pos[s*3+0] + shifts[e*3+0];
    float vy = pos[rc*3+1] - pos[s*3+1] + shifts[e*3+1];
    float vz = pos[rc*3+2] - pos[s*3+2] + shifts[e*3+2];
    float rr = sqrtf(vx*vx + vy*vy + vz*vz + 1e-12f);
    if (rr < 5.0f){
      int i = atomicAdd(&g_nact, 1);
      g_esnd[i]=s; g_ercv[i]=rc; g_ezsnd[i]=nz[s];
      g_r[i]=rr;
      float inv = SQ3F / rr;
      g_Y1[i*3+0]=vx*inv; g_Y1[i*3+1]=vy*inv; g_Y1[i*3+2]=vz*inv;
      float x = rr*0.2f;
      float x2=x*x, x4=x2*x2, x5=x4*x;
      float fc = 1.f + x5*(-21.f + x*(35.f - 15.f*x));
      float invr = 1.f/rr;
      float cf = CB_F*invr*fc;
      float s1_, c1_;
      sincosf(PI_F*0.2f*rr, &s1_, &c1_);
      float sb = s1_, cb = c1_;
      #pragma unroll
      for (int bb = 0; bb < NB_; bb++){
        g_ef[i*NB_ + bb] = cf*sb;
        float ns = sb*c1_ + cb*s1_;
        float nc = cb*c1_ - sb*s1_;
        sb = ns; cb = nc;
      }
    }
    return;
  }
  if (b == 625){
    __shared__ int cnt[NE_];
    __shared__ int off[NE_+1];
    __shared__ int fill[NE_];
    int tid = threadIdx.x;
    if (tid < NE_) cnt[tid] = 0;
    __syncthreads();
    for (int n = tid; n < NN; n += 256) atomicAdd(&cnt[nz[n]], 1);
    __syncthreads();
    if (tid == 0){
      int acc = 0;
      for (int z = 0; z < NE_; z++){ off[z] = acc; g_zoff[z] = acc; acc += cnt[z]; }
      off[NE_] = acc; g_zoff[NE_] = acc;
    }
    __syncthreads();
    if (tid < NE_) fill[tid] = off[tid];
    __syncthreads();
    for (int n = tid; n < NN; n += 256){
      int p = atomicAdd(&fill[nz[n]], 1);
      g_zperm[p] = n;
    }
    return;
  }
  int bb = b - 626;
  for (int id = bb*256 + threadIdx.x; id < 26*KK; id += 52*256){
    int j = id >> 14;
    int rem = id & (KK-1);
    int n = rem >> 7, k = rem & 127;
    const float* W; int trans;
    if (j < 12){ W = WF + j*KK; trans = 0; }
    else if (j == 12){ W = Wms2; trans = 0; }
    else if (j < 25){ W = WF + (j-13)*KK; trans = 1; }
    else { W = Wms2; trans = 1; }
    float v = trans ? W[n*K + k] : W[k*K + n];
    __nv_bfloat16 h = __float2bfloat16(v);
    __nv_bfloat16 l = __float2bfloat16(v - __bfloat162float(h));
    g_Bh[(size_t)j*KK + rem] = h;
    g_Bl[(size_t)j*KK + rem] = l;
  }
}

/* ------------- tensor-core GEMM core (mma.sync bf16, 512 thr) ------------ */
/* 256-row tile, A staged in four 64-row quarters; 16 warps = 4 rows x 4 cols */
__device__ __forceinline__ void tgemm_core(char* smc, const int* __restrict__ rowIdx,
    const float* __restrict__ A, float* __restrict__ C, int bidx, float alpha, int accum,
    const float* __restrict__ tab, const int* __restrict__ nz, const float* __restrict__ bias){
  int tid = threadIdx.x;
  {
    const uint4* gh = (const uint4*)(g_Bh + (size_t)bidx*KK);
    const uint4* gl = (const uint4*)(g_Bl + (size_t)bidx*KK);
    #pragma unroll
    for (int i = 0; i < 4; i++){
      int idx = tid + i*512;
      int row = idx >> 4, q = idx & 15;
      uint4 vh = gh[idx], vl = gl[idx];
      *(uint4*)(smc + W_H_B + row*PITCH_B + q*16) = vh;
      *(uint4*)(smc + W_L_B + row*PITCH_B + q*16) = vl;
    }
  }

  int warp = tid >> 5, lane = tid & 31;
  int mrow0 = (warp & 3)*16;          /* 16-row group within 64-row quarter */
  int ncol0 = (warp >> 2)*32;         /* 32-col group */
  int quad = lane >> 3, rin = lane & 7;
  uint32_t smbase = smem_u32(smc);
  uint32_t aoff = (uint32_t)(rin + (quad & 1)*8)*PITCH_B + (uint32_t)((quad >> 1)*8)*2;
  uint32_t ahb = smbase + A_H_B + (uint32_t)mrow0*PITCH_B + aoff;
  uint32_t alb = smbase + A_L_B + (uint32_t)mrow0*PITCH_B + aoff;
  uint32_t boff = (uint32_t)(rin + (quad >> 1)*8)*PITCH_B + (uint32_t)((quad & 1)*8)*2;
  uint32_t whb = smbase + W_H_B + (uint32_t)ncol0*PITCH_B + boff;
  uint32_t wlb = smbase + W_L_B + (uint32_t)ncol0*PITCH_B + boff;
  int g = lane >> 2, tg = lane & 3;

  #pragma unroll
  for (int qtr = 0; qtr < 4; qtr++){
    #pragma unroll
    for (int i = 0; i < 4; i++){
      int idx = tid + i*512;
      int row = idx >> 5, c4 = (idx & 31)*4;
      int gr = rowIdx[qtr*64 + row];
      float4 v = (gr >= 0) ? *(const float4*)&A[(size_t)gr*K + c4] : make_float4(0.f,0.f,0.f,0.f);
      __nv_bfloat16 h0=__float2bfloat16(v.x), h1=__float2bfloat16(v.y);
      __nv_bfloat16 h2=__float2bfloat16(v.z), h3=__float2bfloat16(v.w);
      __nv_bfloat16 l0=__float2bfloat16(v.x-__bfloat162float(h0));
      __nv_bfloat16 l1=__float2bfloat16(v.y-__bfloat162float(h1));
      __nv_bfloat16 l2=__float2bfloat16(v.z-__bfloat162float(h2));
      __nv_bfloat16 l3=__float2bfloat16(v.w-__bfloat162float(h3));
      *(uint2*)(smc + A_H_B + row*PITCH_B + c4*2) = make_uint2(pk_bf2(h0,h1), pk_bf2(h2,h3));
      *(uint2*)(smc + A_L_B + row*PITCH_B + c4*2) = make_uint2(pk_bf2(l0,l1), pk_bf2(l2,l3));
    }
    __syncthreads();

    float c[4][4];
    #pragma unroll
    for (int nt = 0; nt < 4; nt++){ c[nt][0]=0.f; c[nt][1]=0.f; c[nt][2]=0.f; c[nt][3]=0.f; }

    #pragma unroll
    for (int kt = 0; kt < 8; kt++){
      uint32_t kb = (uint32_t)kt*32;
      uint32_t ah[4], al[4];
      LDM4(ah, ahb + kb);
      LDM4(al, alb + kb);
      #pragma unroll
      for (int s = 0; s < 2; s++){
        uint32_t bh[4], bl[4];
        LDM4(bh, whb + kb + (uint32_t)s*16*PITCH_B);
        LDM4(bl, wlb + kb + (uint32_t)s*16*PITCH_B);
        MMA16816(c[s*2],   ah, bh[0], bh[1]);
        MMA16816(c[s*2],   ah, bl[0], bl[1]);
        MMA16816(c[s*2],   al, bh[0], bh[1]);
        MMA16816(c[s*2+1], ah, bh[2], bh[3]);
        MMA16816(c[s*2+1], ah, bl[2], bl[3]);
        MMA16816(c[s*2+1], al, bh[2], bh[3]);
      }
    }

    #pragma unroll
    for (int hr = 0; hr < 2; hr++){
      int lrow = mrow0 + g + hr*8;
      int grow = rowIdx[qtr*64 + lrow];
      if (grow >= 0){
        const float* trow = 0;
        if (tab) trow = nz ? tab + (size_t)nz[grow]*K : tab;
        #pragma unroll
        for (int nt = 0; nt < 4; nt++){
          int col = ncol0 + nt*8 + tg*2;
          float v0 = alpha*c[nt][hr*2+0];
          float v1 = alpha*c[nt][hr*2+1];
          if (trow){ v0 += trow[col]; v1 += trow[col+1]; }
          if (bias){ v0 += alpha*bias[col]; v1 += alpha*bias[col+1]; }
          if (accum){ float2 o = *(const float2*)&C[(size_t)grow*K + col]; v0 += o.x; v1 += o.y; }
          *(float2*)&C[(size_t)grow*K + col] = make_float2(v0, v1);
        }
      }
    }
    __syncthreads();
  }
}

/* ------ multi-op tensor GEMM launch: kind 0=linear 1=grouped 2=e1 -------- */
#define MAXOPS 4
struct TOps {
  int count;
  int tiles[MAXOPS];
  int kind[MAXOPS];
  int bidx[MAXOPS];
  const float* A[MAXOPS];
  float* C[MAXOPS];
  const float* table[MAXOPS];
  const float* bias[MAXOPS];
  int M[MAXOPS];
  int accum[MAXOPS];
  int useNz[MAXOPS];
  float alpha[MAXOPS];
};

__global__ void __launch_bounds__(512) tgemm_kernel(TOps P, const int* __restrict__ node_z,
    const int* __restrict__ batch, const float* __restrict__ ae){
  int b = blockIdx.x, op = 0;
  while (b >= P.tiles[op]){ b -= P.tiles[op]; op++; }
  int kind = P.kind[op];
  if (kind == 2){
    int gt = b*512 + threadIdx.x;
    int n = gt >> 5, lane = gt & 31;
    if (n >= NN) return;
    float acc = 0.f;
    #pragma unroll
    for (int c = lane; c < K; c += 32) acc = fmaf(g_A0[n*K + c], g_u[c], acc);
    #pragma unroll
    for (int o = 16; o; o >>= 1) acc += __shfl_down_sync(0xffffffffu, acc, o);
    if (lane == 0){
      int zz = node_z[n];
      atomicAdd(&g_e1[batch[n]], ALPHA_*acc + g_t1[zz]);
      atomicAdd(&g_e0[batch[n]], ae[zz]);
    }
    return;
  }
  extern __shared__ char smc[];
  int* rowIdx = (int*)(smc + ROWIDX_B);
  int bidx = P.bidx[op];
  const float* tab = P.table[op];
  const int* nz = 0;
  if (kind == 0){
    int base = b*TN, M = P.M[op];
    if (threadIdx.x < TN) rowIdx[threadIdx.x] = (base + (int)threadIdx.x < M) ? base + threadIdx.x : -1;
    nz = P.useNz[op] ? node_z : 0;
  } else {
    int z = b / GT_PER_Z;
    int m0 = (b - z*GT_PER_Z)*TN;
    int start = g_zoff[z], cnt = g_zoff[z+1] - start;
    if (m0 >= cnt) return;
    if (threadIdx.x < TN) rowIdx[threadIdx.x] = (m0 + (int)threadIdx.x < cnt) ? g_zperm[start + m0 + threadIdx.x] : -1;
    bidx += z;
    if (tab) tab = tab + (size_t)z*K;
  }
  __syncthreads();
  tgemm_core(smc, rowIdx, P.A[op], P.C[op], bidx, P.alpha[op], P.accum[op], tab, nz, P.bias[op]);
}

/* --------------- layer-1 messages: 2 edges per 256-thread block ---------- */
__global__ void __launch_bounds__(256) msg1_kernel(const float* __restrict__ R1){
  int c = threadIdx.x & 127;
  int sub = threadIdx.x >> 7;
  float r1a[NB_], r1b[NB_];
  #pragma unroll
  for (int b = 0; b < NB_; b++){ r1a[b]=R1[b*256 + c]; r1b[b]=R1[b*256 + 128 + c]; }
  int nact = g_nact;
  for (int e = blockIdx.x*2 + sub; e < nact; e += gridDim.x*2){
    int rcv = g_ercv[e], zs = g_ezsnd[e];
    float y0=g_Y1[e*3+0], y1=g_Y1[e*3+1], y2=g_Y1[e*3+2];
    float w0=0.f, w1=0.f;
    #pragma unroll
    for (int b = 0; b < NB_; b++){ float efb=g_ef[e*NB_+b]; w0=fmaf(efb,r1a[b],w0); w1=fmaf(efb,r1b[b],w1); }
    float sj = g_sU1[zs*K + c];
    atomicAdd(&g_A0[rcv*K + c], w0*sj);
    float t = w1*sj;
    atomicAdd(&g_A1[rcv*K + c],        t*y0);
    atomicAdd(&g_A1[NK + rcv*K + c],   t*y1);
    atomicAdd(&g_A1[2*NK + rcv*K + c], t*y2);
  }
}

/* --------------- layer-2 messages: 2 edges per 256-thread block ---------- */
__global__ void __launch_bounds__(256) msg2_kernel(const float* __restrict__ R2){
  int c = threadIdx.x & 127;
  int sub = threadIdx.x >> 7;
  float r2a[NB_], r2b[NB_];
  #pragma unroll
  for (int b = 0; b < NB_; b++){ r2a[b]=R2[b*512 + c]; r2b[b]=R2[b*512 + 128 + c]; }
  int nact = g_nact;
  for (int e = blockIdx.x*2 + sub; e < nact; e += gridDim.x*2){
    int snd = g_esnd[e], rcv = g_ercv[e];
    float y0=g_Y1[e*3+0], y1=g_Y1[e*3+1], y2=g_Y1[e*3+2];
    float w00=0.f, w110=0.f;
    #pragma unroll
    for (int b = 0; b < NB_; b++){ float efb=g_ef[e*NB_+b]; w00=fmaf(efb,r2a[b],w00); w110=fmaf(efb,r2b[b],w110); }
    float sj = g_sU2[snd*K + c];
    float vj0=g_vU2[snd*K+c], vj1=g_vU2[NK+snd*K+c], vj2=g_vU2[2*NK+snd*K+c];
    float dot = vj0*y0 + vj1*y1 + vj2*y2;
    float m = fmaf(w00, sj, w110*dot*INV_SQ3);
    atomicAdd(&g_A2[rcv*K + c], m);
  }
}

/* ----------------------- MLP head: e2 + ds2 ------------------------------ */
__global__ void __launch_bounds__(128) mlp_kernel(const float* __restrict__ Wmlp,
    const float* __restrict__ wout, const int* __restrict__ batch){
  __shared__ float srow[K];
  __shared__ float gj[16];
  __shared__ float hpart[16];
  int tid = threadIdx.x;
  for (int n = blockIdx.x; n < NN; n += gridDim.x){
    srow[tid] = g_s2[n*K + tid];
    __syncthreads();
    if (tid < 16){
      float uu = 0.f;
      for (int c = 0; c < K; c++) uu = fmaf(srow[c], Wmlp[c*16 + tid], uu);
      float sig = 1.f/(1.f + __expf(-uu));
      hpart[tid] = uu*sig*wout[tid];
      gj[tid] = wout[tid]*sig*(1.f + uu*(1.f - sig));
    }
    __syncthreads();
    if (tid == 0){
      float s = 0.f;
      #pragma unroll
      for (int j = 0; j < 16; j++) s += hpart[j];
      atomicAdd(&g_e2[batch[n]], s);
    }
    float ds = 0.f;
    #pragma unroll
    for (int j = 0; j < 16; j++) ds = fmaf(Wmlp[tid*16 + j], gj[j], ds);
    g_ds2[n*K + tid] = ds;
    __syncthreads();
  }
}

/* --------------- backward layer-2: 2 edges per 256-thread block ---------- */
__device__ __forceinline__ float warpsum(float v){
  #pragma unroll
  for (int o = 16; o; o >>= 1) v += __shfl_down_sync(0xffffffffu, v, o);
  return v;
}

__global__ void __launch_bounds__(256) bwd2_kernel(const float* __restrict__ R2){
  __shared__ float red[2][4][11];
  int tid = threadIdx.x;
  int c = tid & 127;
  int sub = tid >> 7;
  int warp = (tid >> 5) & 3, lane = tid & 31;
  float r2a[NB_], r2b[NB_];
  #pragma unroll
  for (int b = 0; b < NB_; b++){ r2a[b]=R2[b*512 + c]; r2b[b]=R2[b*512 + 128 + c]; }
  int nact = g_nact;
  for (int base = blockIdx.x*2; base < nact; base += gridDim.x*2){
    int e = base + sub;
    bool act = (e < nact);
    float y0=0.f, y1=0.f, y2=0.f, dm=0.f, sj=0.f, vj0=0.f, vj1=0.f, vj2=0.f;
    float w00=0.f, w110=0.f;
    int snd=0;
    if (act){
      snd = g_esnd[e];
      int rcv = g_ercv[e];
      y0=g_Y1[e*3+0]; y1=g_Y1[e*3+1]; y2=g_Y1[e*3+2];
      #pragma unroll
      for (int b = 0; b < NB_; b++){ float efb=g_ef[e*NB_+b]; w00=fmaf(efb,r2a[b],w00); w110=fmaf(efb,r2b[b],w110); }
      dm = g_dA2[rcv*K + c];
      sj = g_sU2[snd*K + c];
      vj0=g_vU2[snd*K+c]; vj1=g_vU2[NK+snd*K+c]; vj2=g_vU2[2*NK+snd*K+c];
    }
    float dot = vj0*y0 + vj1*y1 + vj2*y2;
    float ddot = dm*w110*INV_SQ3;
    if (act){
      atomicAdd(&g_Dsj2[snd*K + c], dm*w00);
      atomicAdd(&g_Dvj[snd*K + c],        ddot*y0);
      atomicAdd(&g_Dvj[NK + snd*K + c],   ddot*y1);
      atomicAdd(&g_Dvj[2*NK + snd*K + c], ddot*y2);
    }
    float p[11];
    float dw00 = dm*sj, dw110 = dm*dot*INV_SQ3;
    #pragma unroll
    for (int b = 0; b < NB_; b++) p[b] = fmaf(dw00, r2a[b], dw110*r2b[b]);
    p[8] = ddot*vj0; p[9] = ddot*vj1; p[10] = ddot*vj2;
    #pragma unroll
    for (int k = 0; k < 11; k++){
      float v = warpsum(p[k]);
      if (lane == 0) red[sub][warp][k] = v;
    }
    __syncthreads();
    if (c < 11 && act){
      float v = red[sub][0][c] + red[sub][1][c] + red[sub][2][c] + red[sub][3][c];
      if (c < 8) g_def[e*NB_ + c] = v;
      else       g_dY1b[e*3 + (c-8)] = v;
    }
    __syncthreads();
  }
}

/* --------------- backward layer-1: 2 edges per 256-thread block ---------- */
__global__ void __launch_bounds__(256) bwd1_kernel(const float* __restrict__ R1){
  __shared__ float red[2][4][11];
  int tid = threadIdx.x;
  int c = tid & 127;
  int sub = tid >> 7;
  int warp = (tid >> 5) & 3, lane = tid & 31;
  float r1a[NB_], r1b[NB_];
  #pragma unroll
  for (int b = 0; b < NB_; b++){ r1a[b]=R1[b*256 + c]; r1b[b]=R1[b*256 + 128 + c]; }
  int nact = g_nact;
  for (int base = blockIdx.x*2; base < nact; base += gridDim.x*2){
    int e = base + sub;
    bool act = (e < nact);
    float y0=0.f, y1=0.f, y2=0.f;
    float w1=0.f, dm0=0.f, dm10=0.f, dm11=0.f, dm12=0.f, sj=0.f;
    if (act){
      int rcv = g_ercv[e], zs = g_ezsnd[e];
      y0=g_Y1[e*3+0]; y1=g_Y1[e*3+1]; y2=g_Y1[e*3+2];
      #pragma unroll
      for (int b = 0; b < NB_; b++){ float efb=g_ef[e*NB_+b]; w1 = fmaf(efb, r1b[b], w1); }
      dm0 = g_dA0[rcv*K + c];
      dm10 = g_dA1[rcv*K + c];
      dm11 = g_dA1[NK + rcv*K + c];
      dm12 = g_dA1[2*NK + rcv*K + c];
      sj = g_sU1[zs*K + c];
    }
    float dw0 = dm0*sj;
    float t = dm10*y0 + dm11*y1 + dm12*y2;
    float dw1 = t*sj;
    float p[11];
    #pragma unroll
    for (int b = 0; b < NB_; b++) p[b] = fmaf(dw0, r1a[b], dw1*r1b[b]);
    float ws = w1*sj;
    p[8] = dm10*ws; p[9] = dm11*ws; p[10] = dm12*ws;
    #pragma unroll
    for (int k = 0; k < 11; k++){
      float v = warpsum(p[k]);
      if (lane == 0) red[sub][warp][k] = v;
    }
    __syncthreads();
    if (c < 11 && act){
      float v = red[sub][0][c] + red[sub][1][c] + red[sub][2][c] + red[sub][3][c];
      if (c < 8) g_def[e*NB_ + c] += v;
      else       g_dY1b[e*3 + (c-8)] += v;
    }
    __syncthreads();
  }
}

/* ---------------- geometry backward + finalize (merged) ------------------ */
__global__ void geom_bwd_fin_kernel(float* __restrict__ F, float* __restrict__ out){
  if (blockIdx.x == gridDim.x - 1){
    int g = threadIdx.x;
    if (g < GG){
      float a = g_e0[g], b = g_e1[g], c = g_e2[g];
      out[g] = a + b + c;
      out[GG + g*3 + 0] = a;
      out[GG + g*3 + 1] = b;
      out[GG + g*3 + 2] = c;
    }
    return;
  }
  int stride = (gridDim.x - 1)*blockDim.x;
  int nact = g_nact;
  for (int e = blockIdx.x*blockDim.x + threadIdx.x; e < nact; e += stride){
    float rr = g_r[e];
    float y0=g_Y1[e*3+0], y1=g_Y1[e*3+1], y2=g_Y1[e*3+2];
    float v0 = y0*rr*INV_SQ3, v1 = y1*rr*INV_SQ3, v2 = y2*rr*INV_SQ3;
    float x = rr*0.2f;
    float x2=x*x, x4=x2*x2, x5=x4*x;
    float fc = 1.f + x5*(-21.f + x*(35.f - 15.f*x));
    float omx = 1.f - x;
    float dfcdr = -21.f*x4*omx*omx;
    float invr = 1.f/rr;
    float s1_, c1_;
    sincosf(PI_F*0.2f*rr, &s1_, &c1_);
    float sb = s1_, cb = c1_;
    float dr = 0.f;
    #pragma unroll
    for (int b = 0; b < NB_; b++){
      float a = (float)(b+1)*(PI_F*0.2f);
      float debdr = CB_F*((a*cb*rr - sb)*invr*invr*fc + sb*invr*dfcdr);
      dr = fmaf(g_def[e*NB_ + b], debdr, dr);
      float ns = sb*c1_ + cb*s1_;
      float nc = cb*c1_ - sb*s1_;
      sb = ns; cb = nc;
    }
    float dY0=g_dY1b[e*3+0], dY1v=g_dY1b[e*3+1], dY2=g_dY1b[e*3+2];
    float vd = v0*dY0 + v1*dY1v + v2*dY2;
    float c1c = SQ3F*invr;
    float c2c = SQ3F*vd*invr*invr*invr;
    float dv0 = dr*v0*invr + c1c*dY0 - c2c*v0;
    float dv1 = dr*v1*invr + c1c*dY1v - c2c*v1;
    float dv2 = dr*v2*invr + c1c*dY2 - c2c*v2;
    int snd = g_esnd[e], rcv = g_ercv[e];
    atomicAdd(&F[snd*3+0],  dv0); atomicAdd(&F[snd*3+1],  dv1); atomicAdd(&F[snd*3+2],  dv2);
    atomicAdd(&F[rcv*3+0], -dv0); atomicAdd(&F[rcv*3+1], -dv1); atomicAdd(&F[rcv*3+2], -dv2);
  }
}

/* ------------------------------ host helpers ----------------------------- */
static void tops_init(TOps& P){ P.count = 0; }
static void tops_add(TOps& P, int kind, int tiles, int bidx, const float* A, float* C,
                     int M, float alpha, int accum, const float* table, int useNz,
                     const float* bias){
  int i = P.count++;
  P.kind[i]=kind; P.tiles[i]=tiles; P.bidx[i]=bidx; P.A[i]=A; P.C[i]=C; P.M[i]=M;
  P.alpha[i]=alpha; P.accum[i]=accum; P.table[i]=table; P.useNz[i]=useNz; P.bias[i]=bias;
}
static int tops_total(const TOps& P){
  int t = 0; for (int i = 0; i < P.count; i++) t += P.tiles[i];
  return t;
}

/* ------------------------------ launch ----------------------------------- */
extern "C" void kernel_launch(void* const* d_in, const int* in_sizes, int n_in,
                              void* d_out, int out_size){
  const float *positions, *shifts, *ae, *We, *R1, *Wu1, *Wms1, *Wmv1, *Wsk1, *wr1;
  const float *R2, *Wu2s, *Wu2v, *Wms2, *Wsk2, *Wmlp, *wout;
  const int *edge_index, *node_z, *batch;

  if (in_sizes[2] == 2*EE){  /* setup_inputs dict order */
    positions=(const float*)d_in[0]; shifts=(const float*)d_in[1];
    edge_index=(const int*)d_in[2]; node_z=(const int*)d_in[3]; batch=(const int*)d_in[4];
    ae=(const float*)d_in[5]; We=(const float*)d_in[6]; R1=(const float*)d_in[7];
    Wu1=(const float*)d_in[8]; Wms1=(const float*)d_in[9]; Wmv1=(const float*)d_in[10];
    Wsk1=(const float*)d_in[11]; wr1=(const float*)d_in[12]; R2=(const float*)d_in[13];
    Wu2s=(const float*)d_in[14]; Wu2v=(const float*)d_in[15]; Wms2=(const float*)d_in[16];
    Wsk2=(const float*)d_in[17]; Wmlp=(const float*)d_in[18]; wout=(const float*)d_in[19];
  } else {                   /* reference signature order */
    positions=(const float*)d_in[0]; shifts=(const float*)d_in[1];
    ae=(const float*)d_in[2]; We=(const float*)d_in[3]; R1=(const float*)d_in[4];
    Wu1=(const float*)d_in[5]; Wms1=(const float*)d_in[6]; Wmv1=(const float*)d_in[7];
    Wsk1=(const float*)d_in[8]; wr1=(const float*)d_in[9]; R2=(const float*)d_in[10];
    Wu2s=(const float*)d_in[11]; Wu2v=(const float*)d_in[12]; Wms2=(const float*)d_in[13];
    Wsk2=(const float*)d_in[14]; Wmlp=(const float*)d_in[15]; wout=(const float*)d_in[16];
    edge_index=(const int*)d_in[17]; node_z=(const int*)d_in[18]; batch=(const int*)d_in[19];
  }
  float* out = (float*)d_out;

  float *p_A0,*p_A1,*p_sU2,*p_vU2,*p_A2,*p_s2,*p_ds2,*p_dA2,*p_Dsj2,*p_Dvj,*p_dA0,*p_dA1;
  float *p_WF,*p_tabU2,*p_tabS2,*p_u;
  cudaGetSymbolAddress((void**)&p_A0, g_A0);     cudaGetSymbolAddress((void**)&p_A1, g_A1);
  cudaGetSymbolAddress((void**)&p_sU2, g_sU2);   cudaGetSymbolAddress((void**)&p_vU2, g_vU2);
  cudaGetSymbolAddress((void**)&p_A2, g_A2);     cudaGetSymbolAddress((void**)&p_s2, g_s2);
  cudaGetSymbolAddress((void**)&p_ds2, g_ds2);   cudaGetSymbolAddress((void**)&p_dA2, g_dA2);
  cudaGetSymbolAddress((void**)&p_Dsj2, g_Dsj2); cudaGetSymbolAddress((void**)&p_Dvj, g_Dvj);
  cudaGetSymbolAddress((void**)&p_dA0, g_dA0);   cudaGetSymbolAddress((void**)&p_dA1, g_dA1);
  cudaGetSymbolAddress((void**)&p_WF, g_WF);     cudaGetSymbolAddress((void**)&p_tabU2, g_tabU2);
  cudaGetSymbolAddress((void**)&p_tabS2, g_tabS2); cudaGetSymbolAddress((void**)&p_u, g_u);

  cudaFuncSetAttribute(tgemm_kernel, cudaFuncAttributeMaxDynamicSharedMemorySize, TG_SMEM);

  /* 1: init = zero + tables + fp32 weight GEMMs */
  {
    GOps P; P.count = 0;
    int i;
    i = P.count++; P.A[i]=Wms1; P.B[i]=Wu2s; P.C[i]=p_WF;      P.M[i]=K; P.tiles[i]=2;
    i = P.count++; P.A[i]=Wmv1; P.B[i]=Wu2v; P.C[i]=p_WF + KK; P.M[i]=K; P.tiles[i]=2;
    for (int z = 0; z < NE_; z++){
      i = P.count++; P.A[i]=Wms1; P.B[i]=Wsk2 + z*KK; P.C[i]=p_WF + (2+z)*KK; P.M[i]=K; P.tiles[i]=2;
    }
    init_kernel<<<ZB + 11 + 24, 256>>>(out, out_size, P, We, Wu1, Wsk1, Wu2s, Wsk2, Wms1, wr1);
  }
  /* 2: work1 = geom + z-prep + weight conversion */
  work1_kernel<<<625 + 1 + 52, 256>>>(positions, shifts, edge_index, node_z, p_WF, Wms2);
  /* 3 */
  msg1_kernel<<<1024, 256>>>(R1);
  /* 4: stage C = sU2, vU2, grouped s2, e1+e0 */
  {
    TOps P; tops_init(P);
    tops_add(P, 0, CDIV(NN,TN),   0, p_A0, p_sU2, NN,   ALPHA_, 0, p_tabU2, 1, 0);
    tops_add(P, 0, CDIV(3*NN,TN), 1, p_A1, p_vU2, 3*NN, ALPHA_, 0, 0, 0, 0);
    tops_add(P, 1, GT_PER_Z*NE_,  2, p_A0, p_s2,  NN,   ALPHA_, 0, p_tabS2, 0, 0);
    tops_add(P, 2, CDIV(NN*32,512), 0, 0, 0, NN, 0.f, 0, 0, 0, 0);
    tgemm_kernel<<<tops_total(P), 512, TG_SMEM>>>(P, node_z, batch, ae);
  }
  /* 5 */
  msg2_kernel<<<1024, 256>>>(R2);
  /* 6: s2 += a*A2@Wms2 */
  {
    TOps P; tops_init(P);
    tops_add(P, 0, CDIV(NN,TN), 12, p_A2, p_s2, NN, ALPHA_, 1, 0, 0, 0);
    tgemm_kernel<<<tops_total(P), 512, TG_SMEM>>>(P, node_z, batch, ae);
  }
  /* 7 */
  mlp_kernel<<<2048, 128>>>(Wmlp, wout, batch);
  /* 8: dA2 = a*ds2@Wms2^T ; grouped dA0 = a*ds2@WF2z^T */
  {
    TOps P; tops_init(P);
    tops_add(P, 0, CDIV(NN,TN),  25, p_ds2, p_dA2, NN, ALPHA_, 0, 0, 0, 0);
    tops_add(P, 1, GT_PER_Z*NE_, 15, p_ds2, p_dA0, NN, ALPHA_, 0, 0, 0, 0);
    tgemm_kernel<<<tops_total(P), 512, TG_SMEM>>>(P, node_z, batch, ae);
  }
  /* 9 */
  bwd2_kernel<<<1024, 256>>>(R2);
  /* 10: dA0 += a*(Dsj2@WF1^T + u^T) ; dA1 = a*Dvj@Wfuse^T */
  {
    TOps P; tops_init(P);
    tops_add(P, 0, CDIV(NN,TN),   13, p_Dsj2, p_dA0, NN,   ALPHA_, 1, 0, 0, p_u);
    tops_add(P, 0, CDIV(3*NN,TN), 14, p_Dvj,  p_dA1, 3*NN, ALPHA_, 0, 0, 0, 0);
    tgemm_kernel<<<tops_total(P), 512, TG_SMEM>>>(P, node_z, batch, ae);
  }
  /* 11 */
  bwd1_kernel<<<1024, 256>>>(R1);
  /* 12: geometry backward + finalize */
  geom_bwd_fin_kernel<<<1025, 256>>>(out + GG + 3*GG, out);
}

// round 12
// speedup vs baseline: 1.0419x; 1.0419x over previous
#include <cuda_runtime.h>
#include <cuda_bf16.h>
#include <math.h>
#include <stdint.h>

#define K 128
#define KK (K*K)
#define NN 10000
#define EE 160000
#define NE_ 10
#define NB_ 8
#define GG 16
#define NK (NN*K)
#define TM 64
#define TNB 256              /* big tile rows */
#define TNS 128              /* small tile rows */
#define GTZ_BIG 40           /* CDIV(NN,TNB) */
#define GTZ_SM  79           /* CDIV(NN,TNS) */

#define SQ3F 1.7320508075688772f
#define INV_SQ3 0.5773502691896258f
#define PI_F 3.14159265358979323846f
#define CB_F 0.6324555320336759f
#define ALPHA_ (1.0f/16.0f)
#define CDIV(a,b) (((a)+(b)-1)/(b))

/* ---- smem layout for tensor GEMM: W full, A in 64-row buffers ----------- */
#define PITCH_B 272
#define W_H_B 0
#define W_L_B 34816
#define A_H_B 69632
#define A_L_B 87040
#define ROWIDX_B 104448      /* up to 256 ints */
#define TG_SMEM 105472       /* 103 KB -> 2 CTAs/SM */

__device__ __forceinline__ uint32_t smem_u32(const void* p){
  uint32_t a;
  asm("{ .reg .u64 t; cvta.to.shared.u64 t, %1; cvt.u32.u64 %0, t; }" : "=r"(a) : "l"(p));
  return a;
}
#define LDM4(r, addr) \
  asm volatile("ldmatrix.sync.aligned.m8n8.x4.shared.b16 {%0,%1,%2,%3}, [%4];" \
    : "=r"((r)[0]),"=r"((r)[1]),"=r"((r)[2]),"=r"((r)[3]) : "r"(addr))
#define MMA16816(c, a, b0, b1) \
  asm volatile("mma.sync.aligned.m16n8k16.row.col.f32.bf16.bf16.f32 " \
    "{%0,%1,%2,%3}, {%4,%5,%6,%7}, {%8,%9}, {%0,%1,%2,%3};" \
    : "+f"((c)[0]),"+f"((c)[1]),"+f"((c)[2]),"+f"((c)[3]) \
    : "r"((a)[0]),"r"((a)[1]),"r"((a)[2]),"r"((a)[3]), "r"(b0),"r"(b1))

__device__ __forceinline__ uint32_t pk_bf2(__nv_bfloat16 a, __nv_bfloat16 b){
  return (uint32_t)__bfloat16_as_ushort(a) | ((uint32_t)__bfloat16_as_ushort(b) << 16);
}

/* ------------------- device scratch (no allocs allowed) ------------------ */
__device__ float g_sU1[NE_*K];
__device__ float g_tabU2[NE_*K];
__device__ float g_tabS2[NE_*K];
__device__ float g_t1[NE_];
__device__ float g_u[K];
__device__ float g_r[EE];
__device__ float g_Y1[EE*3];
__device__ float g_ef[EE*NB_];
__device__ int   g_esnd[EE], g_ercv[EE], g_ezsnd[EE];
__device__ int   g_nact;
__device__ float g_A0[NK];
__device__ float g_A1[3*NK];
__device__ float g_sU2[NK];
__device__ float g_vU2[3*NK];
__device__ float g_A2[NK];
__device__ float g_s2[NK];
__device__ float g_ds2[NK];
__device__ float g_dA2[NK];
__device__ float g_Dsj2[NK];
__device__ float g_Dvj[3*NK];
__device__ float g_dA0[NK];
__device__ float g_dA1[3*NK];
__device__ float g_def[EE*NB_];
__device__ float g_dY1b[EE*3];
__device__ float g_e0[GG], g_e1[GG], g_e2[GG];
__device__ float g_WF[12*KK];
__device__ __nv_bfloat16 g_Bh[26*KK];
__device__ __nv_bfloat16 g_Bl[26*KK];
__device__ int g_zoff[NE_+1], g_zperm[NN];

/* -------- fp32 multi-op GEMM struct (weight precompute) ------------------ */
#define MAXG 12
struct GOps {
  int count;
  int tiles[MAXG];
  const float* A[MAXG];
  const float* B[MAXG];
  float* C[MAXG];
  int M[MAXG];
};

/* ================= init: zero + per-z tables + weight GEMMs ============== */
#define ZB 2048
__global__ void __launch_bounds__(256) init_kernel(float* __restrict__ out, int out_size, GOps P,
    const float* __restrict__ We, const float* __restrict__ Wu1, const float* __restrict__ Wsk1,
    const float* __restrict__ Wu2s, const float* __restrict__ Wsk2, const float* __restrict__ Wms1,
    const float* __restrict__ wr1){
  __shared__ char ubuf[32768];
  int b = blockIdx.x;
  int tid = threadIdx.x;
  if (b < ZB){
    int total = 3*NK;
    if (out_size > total) total = out_size;
    for (int i = b*256 + tid; i < total; i += ZB*256){
      if (i < 3*NK){ g_A1[i]=0.f; g_Dvj[i]=0.f; }
      if (i < NK){ g_A0[i]=0.f; g_A2[i]=0.f; g_Dsj2[i]=0.f; }
      if (i < out_size) out[i]=0.f;
      if (i < GG){ g_e0[i]=0.f; g_e1[i]=0.f; g_e2[i]=0.f; }
      if (i == 0) g_nact = 0;
    }
    return;
  }
  if (b < ZB + 11){
    int z = b - ZB;
    if (tid >= 128) return;
    int d = tid;
    float* sh  = (float*)ubuf;
    float* red = (float*)(ubuf + 512);
    if (z == NE_){
      float a = 0.f;
      for (int m = 0; m < K; m++) a = fmaf(Wms1[d*K + m], wr1[m], a);
      g_u[d] = a;
      return;
    }
    float a = 0.f, bb = 0.f;
    for (int c = 0; c < K; c++){
      float s = We[z*K + c];
      a  = fmaf(s, Wu1[c*K + d], a);
      bb = fmaf(s, Wsk1[(z*K + c)*K + d], bb);
    }
    g_sU1[z*K + d] = a;
    sh[d] = bb;
    __syncthreads();
    float t2 = 0.f, t3 = 0.f;
    for (int c = 0; c < K; c++){
      float s = sh[c];
      t2 = fmaf(s, Wu2s[c*K + d], t2);
      t3 = fmaf(s, Wsk2[(z*K + c)*K + d], t3);
    }
    g_tabU2[z*K + d] = t2;
    g_tabS2[z*K + d] = t3;
    float p = sh[d]*wr1[d];
    #pragma unroll
    for (int o = 16; o; o >>= 1) p += __shfl_down_sync(0xffffffffu, p, o);
    if ((d & 31) == 0) red[d >> 5] = p;
    __syncthreads();
    if (d == 0) g_t1[z] = red[0] + red[1] + red[2] + red[3];
    return;
  }
  b -= (ZB + 11);
  int op = 0;
  while (b >= P.tiles[op]){ b -= P.tiles[op]; op++; }
  typedef float (*AsT)[K];
  AsT As = (AsT)ubuf;
  int d = tid & 127;
  int g = tid >> 7;
  int M = P.M[op];
  const float* __restrict__ A = P.A[op];
  int base0 = b*TM;
  #pragma unroll 4
  for (int i = 0; i < 32; i++){
    int r = g*32 + i;
    As[r][d] = (base0 + r < M) ? A[(base0 + r)*K + d] : 0.f;
  }
  __syncthreads();
  const float* __restrict__ B = P.B[op];
  float acc[32];
  #pragma unroll
  for (int i = 0; i < 32; i++) acc[i] = 0.f;
  for (int c = 0; c < K; c += 4){
    float b0=B[c*K+d], b1=B[(c+1)*K+d], b2=B[(c+2)*K+d], b3=B[(c+3)*K+d];
    #pragma unroll
    for (int i = 0; i < 32; i++){
      float4 av = *(const float4*)&As[g*32 + i][c];
      acc[i] = fmaf(av.x,b0,fmaf(av.y,b1,fmaf(av.z,b2,fmaf(av.w,b3,acc[i]))));
    }
  }
  float* __restrict__ C = P.C[op];
  int base = base0 + g*32;
  for (int i = 0; i < 32; i++){
    int n = base + i;
    if (n >= M) break;
    C[n*K + d] = acc[i];
  }
}

/* ============ work1: geom + conv (split bf16) + z count/scan/scatter ===== */
__global__ void __launch_bounds__(256) work1_kernel(const float* __restrict__ pos,
    const float* __restrict__ shifts, const int* __restrict__ ei, const int* __restrict__ nz,
    const float* __restrict__ WF, const float* __restrict__ Wms2){
  int b = blockIdx.x;
  if (b < 625){
    int e = b*256 + threadIdx.x;
    if (e >= EE) return;
    int s = ei[e], rc = ei[EE + e];
    float vx = pos[rc*3+0] - pos[s*3+0] + shifts[e*3+0];
    float vy = pos[rc*3+1] - pos[s*3+1] + shifts[e*3+1];
    float vz = pos[rc*3+2] - pos[s*3+2] + shifts[e*3+2];
    float rr = sqrtf(vx*vx + vy*vy + vz*vz + 1e-12f);
    if (rr < 5.0f){
      int i = atomicAdd(&g_nact, 1);
      g_esnd[i]=s; g_ercv[i]=rc; g_ezsnd[i]=nz[s];
      g_r[i]=rr;
      float inv = SQ3F / rr;
      g_Y1[i*3+0]=vx*inv; g_Y1[i*3+1]=vy*inv; g_Y1[i*3+2]=vz*inv;
      float x = rr*0.2f;
      float x2=x*x, x4=x2*x2, x5=x4*x;
      float fc = 1.f + x5*(-21.f + x*(35.f - 15.f*x));
      float invr = 1.f/rr;
      float cf = CB_F*invr*fc;
      float s1_, c1_;
      sincosf(PI_F*0.2f*rr, &s1_, &c1_);
      float sb = s1_, cb = c1_;
      #pragma unroll
      for (int bb = 0; bb < NB_; bb++){
        g_ef[i*NB_ + bb] = cf*sb;
        float ns = sb*c1_ + cb*s1_;
        float nc = cb*c1_ - sb*s1_;
        sb = ns; cb = nc;
      }
    }
    return;
  }
  if (b == 625){
    __shared__ int cnt[NE_];
    __shared__ int off[NE_+1];
    __shared__ int fill[NE_];
    int tid = threadIdx.x;
    if (tid < NE_) cnt[tid] = 0;
    __syncthreads();
    for (int n = tid; n < NN; n += 256) atomicAdd(&cnt[nz[n]], 1);
    __syncthreads();
    if (tid == 0){
      int acc = 0;
      for (int z = 0; z < NE_; z++){ off[z] = acc; g_zoff[z] = acc; acc += cnt[z]; }
      off[NE_] = acc; g_zoff[NE_] = acc;
    }
    __syncthreads();
    if (tid < NE_) fill[tid] = off[tid];
    __syncthreads();
    for (int n = tid; n < NN; n += 256){
      int p = atomicAdd(&fill[nz[n]], 1);
      g_zperm[p] = n;
    }
    return;
  }
  int bb = b - 626;
  for (int id = bb*256 + threadIdx.x; id < 26*KK; id += 52*256){
    int j = id >> 14;
    int rem = id & (KK-1);
    int n = rem >> 7, k = rem & 127;
    const float* W; int trans;
    if (j < 12){ W = WF + j*KK; trans = 0; }
    else if (j == 12){ W = Wms2; trans = 0; }
    else if (j < 25){ W = WF + (j-13)*KK; trans = 1; }
    else { W = Wms2; trans = 1; }
    float v = trans ? W[n*K + k] : W[k*K + n];
    __nv_bfloat16 h = __float2bfloat16(v);
    __nv_bfloat16 l = __float2bfloat16(v - __bfloat162float(h));
    g_Bh[(size_t)j*KK + rem] = h;
    g_Bl[(size_t)j*KK + rem] = l;
  }
}

/* ---------- big tensor GEMM core (512 thr, 256-row tile, 4 quarters) ----- */
__device__ __forceinline__ void tgemm_core_big(char* smc, const int* __restrict__ rowIdx,
    const float* __restrict__ A, float* __restrict__ C, int bidx, float alpha, int accum,
    const float* __restrict__ tab, const int* __restrict__ nz, const float* __restrict__ bias){
  int tid = threadIdx.x;
  {
    const uint4* gh = (const uint4*)(g_Bh + (size_t)bidx*KK);
    const uint4* gl = (const uint4*)(g_Bl + (size_t)bidx*KK);
    #pragma unroll
    for (int i = 0; i < 4; i++){
      int idx = tid + i*512;
      int row = idx >> 4, q = idx & 15;
      uint4 vh = gh[idx], vl = gl[idx];
      *(uint4*)(smc + W_H_B + row*PITCH_B + q*16) = vh;
      *(uint4*)(smc + W_L_B + row*PITCH_B + q*16) = vl;
    }
  }
  int warp = tid >> 5, lane = tid & 31;
  int mrow0 = (warp & 3)*16;
  int ncol0 = (warp >> 2)*32;
  int quad = lane >> 3, rin = lane & 7;
  uint32_t smbase = smem_u32(smc);
  uint32_t aoff = (uint32_t)(rin + (quad & 1)*8)*PITCH_B + (uint32_t)((quad >> 1)*8)*2;
  uint32_t ahb = smbase + A_H_B + (uint32_t)mrow0*PITCH_B + aoff;
  uint32_t alb = smbase + A_L_B + (uint32_t)mrow0*PITCH_B + aoff;
  uint32_t boff = (uint32_t)(rin + (quad >> 1)*8)*PITCH_B + (uint32_t)((quad & 1)*8)*2;
  uint32_t whb = smbase + W_H_B + (uint32_t)ncol0*PITCH_B + boff;
  uint32_t wlb = smbase + W_L_B + (uint32_t)ncol0*PITCH_B + boff;
  int g = lane >> 2, tg = lane & 3;

  #pragma unroll
  for (int qtr = 0; qtr < 4; qtr++){
    #pragma unroll
    for (int i = 0; i < 4; i++){
      int idx = tid + i*512;
      int row = idx >> 5, c4 = (idx & 31)*4;
      int gr = rowIdx[qtr*64 + row];
      float4 v = (gr >= 0) ? *(const float4*)&A[(size_t)gr*K + c4] : make_float4(0.f,0.f,0.f,0.f);
      __nv_bfloat16 h0=__float2bfloat16(v.x), h1=__float2bfloat16(v.y);
      __nv_bfloat16 h2=__float2bfloat16(v.z), h3=__float2bfloat16(v.w);
      __nv_bfloat16 l0=__float2bfloat16(v.x-__bfloat162float(h0));
      __nv_bfloat16 l1=__float2bfloat16(v.y-__bfloat162float(h1));
      __nv_bfloat16 l2=__float2bfloat16(v.z-__bfloat162float(h2));
      __nv_bfloat16 l3=__float2bfloat16(v.w-__bfloat162float(h3));
      *(uint2*)(smc + A_H_B + row*PITCH_B + c4*2) = make_uint2(pk_bf2(h0,h1), pk_bf2(h2,h3));
      *(uint2*)(smc + A_L_B + row*PITCH_B + c4*2) = make_uint2(pk_bf2(l0,l1), pk_bf2(l2,l3));
    }
    __syncthreads();

    float c[4][4];
    #pragma unroll
    for (int nt = 0; nt < 4; nt++){ c[nt][0]=0.f; c[nt][1]=0.f; c[nt][2]=0.f; c[nt][3]=0.f; }

    #pragma unroll
    for (int kt = 0; kt < 8; kt++){
      uint32_t kb = (uint32_t)kt*32;
      uint32_t ah[4], al[4];
      LDM4(ah, ahb + kb);
      LDM4(al, alb + kb);
      #pragma unroll
      for (int s = 0; s < 2; s++){
        uint32_t bh[4], bl[4];
        LDM4(bh, whb + kb + (uint32_t)s*16*PITCH_B);
        LDM4(bl, wlb + kb + (uint32_t)s*16*PITCH_B);
        MMA16816(c[s*2],   ah, bh[0], bh[1]);
        MMA16816(c[s*2],   ah, bl[0], bl[1]);
        MMA16816(c[s*2],   al, bh[0], bh[1]);
        MMA16816(c[s*2+1], ah, bh[2], bh[3]);
        MMA16816(c[s*2+1], ah, bl[2], bl[3]);
        MMA16816(c[s*2+1], al, bh[2], bh[3]);
      }
    }

    #pragma unroll
    for (int hr = 0; hr < 2; hr++){
      int lrow = mrow0 + g + hr*8;
      int grow = rowIdx[qtr*64 + lrow];
      if (grow >= 0){
        const float* trow = 0;
        if (tab) trow = nz ? tab + (size_t)nz[grow]*K : tab;
        #pragma unroll
        for (int nt = 0; nt < 4; nt++){
          int col = ncol0 + nt*8 + tg*2;
          float v0 = alpha*c[nt][hr*2+0];
          float v1 = alpha*c[nt][hr*2+1];
          if (trow){ v0 += trow[col]; v1 += trow[col+1]; }
          if (bias){ v0 += alpha*bias[col]; v1 += alpha*bias[col+1]; }
          if (accum){ float2 o = *(const float2*)&C[(size_t)grow*K + col]; v0 += o.x; v1 += o.y; }
          *(float2*)&C[(size_t)grow*K + col] = make_float2(v0, v1);
        }
      }
    }
    __syncthreads();
  }
}

/* ---------- small tensor GEMM core (256 thr, 128-row tile, 2 halves) ----- */
__device__ __forceinline__ void tgemm_core_sm(char* smc, const int* __restrict__ rowIdx,
    const float* __restrict__ A, float* __restrict__ C, int bidx, float alpha, int accum,
    const float* __restrict__ tab, const int* __restrict__ nz, const float* __restrict__ bias){
  int tid = threadIdx.x;
  {
    const uint4* gh = (const uint4*)(g_Bh + (size_t)bidx*KK);
    const uint4* gl = (const uint4*)(g_Bl + (size_t)bidx*KK);
    #pragma unroll
    for (int i = 0; i < 8; i++){
      int idx = tid + i*256;
      int row = idx >> 4, q = idx & 15;
      uint4 vh = gh[idx], vl = gl[idx];
      *(uint4*)(smc + W_H_B + row*PITCH_B + q*16) = vh;
      *(uint4*)(smc + W_L_B + row*PITCH_B + q*16) = vl;
    }
  }
  int warp = tid >> 5, lane = tid & 31;
  int mrow0 = (warp & 3)*16;
  int ncol0 = (warp >> 2)*64;
  int quad = lane >> 3, rin = lane & 7;
  uint32_t smbase = smem_u32(smc);
  uint32_t aoff = (uint32_t)(rin + (quad & 1)*8)*PITCH_B + (uint32_t)((quad >> 1)*8)*2;
  uint32_t ahb = smbase + A_H_B + (uint32_t)mrow0*PITCH_B + aoff;
  uint32_t alb = smbase + A_L_B + (uint32_t)mrow0*PITCH_B + aoff;
  uint32_t boff = (uint32_t)(rin + (quad >> 1)*8)*PITCH_B + (uint32_t)((quad & 1)*8)*2;
  uint32_t whb = smbase + W_H_B + (uint32_t)ncol0*PITCH_B + boff;
  uint32_t wlb = smbase + W_L_B + (uint32_t)ncol0*PITCH_B + boff;
  int g = lane >> 2, tg = lane & 3;

  #pragma unroll
  for (int half = 0; half < 2; half++){
    #pragma unroll
    for (int i = 0; i < 8; i++){
      int idx = tid + i*256;
      int row = idx >> 5, c4 = (idx & 31)*4;
      int gr = rowIdx[half*64 + row];
      float4 v = (gr >= 0) ? *(const float4*)&A[(size_t)gr*K + c4] : make_float4(0.f,0.f,0.f,0.f);
      __nv_bfloat16 h0=__float2bfloat16(v.x), h1=__float2bfloat16(v.y);
      __nv_bfloat16 h2=__float2bfloat16(v.z), h3=__float2bfloat16(v.w);
      __nv_bfloat16 l0=__float2bfloat16(v.x-__bfloat162float(h0));
      __nv_bfloat16 l1=__float2bfloat16(v.y-__bfloat162float(h1));
      __nv_bfloat16 l2=__float2bfloat16(v.z-__bfloat162float(h2));
      __nv_bfloat16 l3=__float2bfloat16(v.w-__bfloat162float(h3));
      *(uint2*)(smc + A_H_B + row*PITCH_B + c4*2) = make_uint2(pk_bf2(h0,h1), pk_bf2(h2,h3));
      *(uint2*)(smc + A_L_B + row*PITCH_B + c4*2) = make_uint2(pk_bf2(l0,l1), pk_bf2(l2,l3));
    }
    __syncthreads();

    float c[8][4];
    #pragma unroll
    for (int nt = 0; nt < 8; nt++){ c[nt][0]=0.f; c[nt][1]=0.f; c[nt][2]=0.f; c[nt][3]=0.f; }

    #pragma unroll
    for (int kt = 0; kt < 8; kt++){
      uint32_t kb = (uint32_t)kt*32;
      uint32_t ah[4], al[4];
      LDM4(ah, ahb + kb);
      LDM4(al, alb + kb);
      #pragma unroll
      for (int nt2 = 0; nt2 < 4; nt2++){
        uint32_t bh[4], bl[4];
        LDM4(bh, whb + kb + (uint32_t)nt2*16*PITCH_B);
        LDM4(bl, wlb + kb + (uint32_t)nt2*16*PITCH_B);
        MMA16816(c[nt2*2],   ah, bh[0], bh[1]);
        MMA16816(c[nt2*2],   ah, bl[0], bl[1]);
        MMA16816(c[nt2*2],   al, bh[0], bh[1]);
        MMA16816(c[nt2*2+1], ah, bh[2], bh[3]);
        MMA16816(c[nt2*2+1], ah, bl[2], bl[3]);
        MMA16816(c[nt2*2+1], al, bh[2], bh[3]);
      }
    }

    #pragma unroll
    for (int hr = 0; hr < 2; hr++){
      int lrow = mrow0 + g + hr*8;
      int grow = rowIdx[half*64 + lrow];
      if (grow >= 0){
        const float* trow = 0;
        if (tab) trow = nz ? tab + (size_t)nz[grow]*K : tab;
        #pragma unroll
        for (int nt = 0; nt < 8; nt++){
          int col = ncol0 + nt*8 + tg*2;
          float v0 = alpha*c[nt][hr*2+0];
          float v1 = alpha*c[nt][hr*2+1];
          if (trow){ v0 += trow[col]; v1 += trow[col+1]; }
          if (bias){ v0 += alpha*bias[col]; v1 += alpha*bias[col+1]; }
          if (accum){ float2 o = *(const float2*)&C[(size_t)grow*K + col]; v0 += o.x; v1 += o.y; }
          *(float2*)&C[(size_t)grow*K + col] = make_float2(v0, v1);
        }
      }
    }
    __syncthreads();
  }
}

/* ------ multi-op tensor GEMM: kind 0=linear 1=grouped 2=e1 --------------- */
#define MAXOPS 4
struct TOps {
  int count;
  int tiles[MAXOPS];
  int kind[MAXOPS];
  int bidx[MAXOPS];
  const float* A[MAXOPS];
  float* C[MAXOPS];
  const float* table[MAXOPS];
  const float* bias[MAXOPS];
  int M[MAXOPS];
  int accum[MAXOPS];
  int useNz[MAXOPS];
  float alpha[MAXOPS];
};

__global__ void __launch_bounds__(512) tgemm_big_kernel(TOps P, const int* __restrict__ node_z,
    const int* __restrict__ batch, const float* __restrict__ ae){
  int b = blockIdx.x, op = 0;
  while (b >= P.tiles[op]){ b -= P.tiles[op]; op++; }
  int kind = P.kind[op];
  if (kind == 2){
    int gt = b*512 + threadIdx.x;
    int n = gt >> 5, lane = gt & 31;
    if (n >= NN) return;
    float acc = 0.f;
    #pragma unroll
    for (int c = lane; c < K; c += 32) acc = fmaf(g_A0[n*K + c], g_u[c], acc);
    #pragma unroll
    for (int o = 16; o; o >>= 1) acc += __shfl_down_sync(0xffffffffu, acc, o);
    if (lane == 0){
      int zz = node_z[n];
      atomicAdd(&g_e1[batch[n]], ALPHA_*acc + g_t1[zz]);
      atomicAdd(&g_e0[batch[n]], ae[zz]);
    }
    return;
  }
  extern __shared__ char smc[];
  int* rowIdx = (int*)(smc + ROWIDX_B);
  int bidx = P.bidx[op];
  const float* tab = P.table[op];
  const int* nz = 0;
  if (kind == 0){
    int base = b*TNB, M = P.M[op];
    if (threadIdx.x < TNB) rowIdx[threadIdx.x] = (base + (int)threadIdx.x < M) ? base + threadIdx.x : -1;
    nz = P.useNz[op] ? node_z : 0;
  } else {
    int z = b / GTZ_BIG;
    int m0 = (b - z*GTZ_BIG)*TNB;
    int start = g_zoff[z], cnt = g_zoff[z+1] - start;
    if (m0 >= cnt) return;
    if (threadIdx.x < TNB) rowIdx[threadIdx.x] = (m0 + (int)threadIdx.x < cnt) ? g_zperm[start + m0 + threadIdx.x] : -1;
    bidx += z;
    if (tab) tab = tab + (size_t)z*K;
  }
  __syncthreads();
  tgemm_core_big(smc, rowIdx, P.A[op], P.C[op], bidx, P.alpha[op], P.accum[op], tab, nz, P.bias[op]);
}

__global__ void __launch_bounds__(256) tgemm_sm_kernel(TOps P, const int* __restrict__ node_z){
  int b = blockIdx.x, op = 0;
  while (b >= P.tiles[op]){ b -= P.tiles[op]; op++; }
  int kind = P.kind[op];
  extern __shared__ char smc[];
  int* rowIdx = (int*)(smc + ROWIDX_B);
  int bidx = P.bidx[op];
  const float* tab = P.table[op];
  const int* nz = 0;
  if (kind == 0){
    int base = b*TNS, M = P.M[op];
    if (threadIdx.x < TNS) rowIdx[threadIdx.x] = (base + (int)threadIdx.x < M) ? base + threadIdx.x : -1;
    nz = P.useNz[op] ? node_z : 0;
  } else {
    int z = b / GTZ_SM;
    int m0 = (b - z*GTZ_SM)*TNS;
    int start = g_zoff[z], cnt = g_zoff[z+1] - start;
    if (m0 >= cnt) return;
    if (threadIdx.x < TNS) rowIdx[threadIdx.x] = (m0 + (int)threadIdx.x < cnt) ? g_zperm[start + m0 + threadIdx.x] : -1;
    bidx += z;
    if (tab) tab = tab + (size_t)z*K;
  }
  __syncthreads();
  tgemm_core_sm(smc, rowIdx, P.A[op], P.C[op], bidx, P.alpha[op], P.accum[op], tab, nz, P.bias[op]);
}

/* --------------- layer-1 messages: 2 edges per 256-thread block ---------- */
__global__ void __launch_bounds__(256) msg1_kernel(const float* __restrict__ R1){
  int c = threadIdx.x & 127;
  int sub = threadIdx.x >> 7;
  float r1a[NB_], r1b[NB_];
  #pragma unroll
  for (int b = 0; b < NB_; b++){ r1a[b]=R1[b*256 + c]; r1b[b]=R1[b*256 + 128 + c]; }
  int nact = g_nact;
  for (int e = blockIdx.x*2 + sub; e < nact; e += gridDim.x*2){
    int rcv = g_ercv[e], zs = g_ezsnd[e];
    float y0=g_Y1[e*3+0], y1=g_Y1[e*3+1], y2=g_Y1[e*3+2];
    float w0=0.f, w1=0.f;
    #pragma unroll
    for (int b = 0; b < NB_; b++){ float efb=g_ef[e*NB_+b]; w0=fmaf(efb,r1a[b],w0); w1=fmaf(efb,r1b[b],w1); }
    float sj = g_sU1[zs*K + c];
    atomicAdd(&g_A0[rcv*K + c], w0*sj);
    float t = w1*sj;
    atomicAdd(&g_A1[rcv*K + c],        t*y0);
    atomicAdd(&g_A1[NK + rcv*K + c],   t*y1);
    atomicAdd(&g_A1[2*NK + rcv*K + c], t*y2);
  }
}

/* --------------- layer-2 messages: 2 edges per 256-thread block ---------- */
__global__ void __launch_bounds__(256) msg2_kernel(const float* __restrict__ R2){
  int c = threadIdx.x & 127;
  int sub = threadIdx.x >> 7;
  float r2a[NB_], r2b[NB_];
  #pragma unroll
  for (int b = 0; b < NB_; b++){ r2a[b]=R2[b*512 + c]; r2b[b]=R2[b*512 + 128 + c]; }
  int nact = g_nact;
  for (int e = blockIdx.x*2 + sub; e < nact; e += gridDim.x*2){
    int snd = g_esnd[e], rcv = g_ercv[e];
    float y0=g_Y1[e*3+0], y1=g_Y1[e*3+1], y2=g_Y1[e*3+2];
    float w00=0.f, w110=0.f;
    #pragma unroll
    for (int b = 0; b < NB_; b++){ float efb=g_ef[e*NB_+b]; w00=fmaf(efb,r2a[b],w00); w110=fmaf(efb,r2b[b],w110); }
    float sj = g_sU2[snd*K + c];
    float vj0=g_vU2[snd*K+c], vj1=g_vU2[NK+snd*K+c], vj2=g_vU2[2*NK+snd*K+c];
    float dot = vj0*y0 + vj1*y1 + vj2*y2;
    float m = fmaf(w00, sj, w110*dot*INV_SQ3);
    atomicAdd(&g_A2[rcv*K + c], m);
  }
}

/* ----------------------- MLP head: e2 + ds2 ------------------------------ */
__global__ void __launch_bounds__(128) mlp_kernel(const float* __restrict__ Wmlp,
    const float* __restrict__ wout, const int* __restrict__ batch){
  __shared__ float srow[K];
  __shared__ float gj[16];
  __shared__ float hpart[16];
  int tid = threadIdx.x;
  for (int n = blockIdx.x; n < NN; n += gridDim.x){
    srow[tid] = g_s2[n*K + tid];
    __syncthreads();
    if (tid < 16){
      float uu = 0.f;
      for (int c = 0; c < K; c++) uu = fmaf(srow[c], Wmlp[c*16 + tid], uu);
      float sig = 1.f/(1.f + __expf(-uu));
      hpart[tid] = uu*sig*wout[tid];
      gj[tid] = wout[tid]*sig*(1.f + uu*(1.f - sig));
    }
    __syncthreads();
    if (tid == 0){
      float s = 0.f;
      #pragma unroll
      for (int j = 0; j < 16; j++) s += hpart[j];
      atomicAdd(&g_e2[batch[n]], s);
    }
    float ds = 0.f;
    #pragma unroll
    for (int j = 0; j < 16; j++) ds = fmaf(Wmlp[tid*16 + j], gj[j], ds);
    g_ds2[n*K + tid] = ds;
    __syncthreads();
  }
}

/* --------------- backward layer-2: 2 edges per 256-thread block ---------- */
__device__ __forceinline__ float warpsum(float v){
  #pragma unroll
  for (int o = 16; o; o >>= 1) v += __shfl_down_sync(0xffffffffu, v, o);
  return v;
}

__global__ void __launch_bounds__(256) bwd2_kernel(const float* __restrict__ R2){
  __shared__ float red[2][4][11];
  int tid = threadIdx.x;
  int c = tid & 127;
  int sub = tid >> 7;
  int warp = (tid >> 5) & 3, lane = tid & 31;
  float r2a[NB_], r2b[NB_];
  #pragma unroll
  for (int b = 0; b < NB_; b++){ r2a[b]=R2[b*512 + c]; r2b[b]=R2[b*512 + 128 + c]; }
  int nact = g_nact;
  for (int base = blockIdx.x*2; base < nact; base += gridDim.x*2){
    int e = base + sub;
    bool act = (e < nact);
    float y0=0.f, y1=0.f, y2=0.f, dm=0.f, sj=0.f, vj0=0.f, vj1=0.f, vj2=0.f;
    float w00=0.f, w110=0.f;
    int snd=0;
    if (act){
      snd = g_esnd[e];
      int rcv = g_ercv[e];
      y0=g_Y1[e*3+0]; y1=g_Y1[e*3+1]; y2=g_Y1[e*3+2];
      #pragma unroll
      for (int b = 0; b < NB_; b++){ float efb=g_ef[e*NB_+b]; w00=fmaf(efb,r2a[b],w00); w110=fmaf(efb,r2b[b],w110); }
      dm = g_dA2[rcv*K + c];
      sj = g_sU2[snd*K + c];
      vj0=g_vU2[snd*K+c]; vj1=g_vU2[NK+snd*K+c]; vj2=g_vU2[2*NK+snd*K+c];
    }
    float dot = vj0*y0 + vj1*y1 + vj2*y2;
    float ddot = dm*w110*INV_SQ3;
    if (act){
      atomicAdd(&g_Dsj2[snd*K + c], dm*w00);
      atomicAdd(&g_Dvj[snd*K + c],        ddot*y0);
      atomicAdd(&g_Dvj[NK + snd*K + c],   ddot*y1);
      atomicAdd(&g_Dvj[2*NK + snd*K + c], ddot*y2);
    }
    float p[11];
    float dw00 = dm*sj, dw110 = dm*dot*INV_SQ3;
    #pragma unroll
    for (int b = 0; b < NB_; b++) p[b] = fmaf(dw00, r2a[b], dw110*r2b[b]);
    p[8] = ddot*vj0; p[9] = ddot*vj1; p[10] = ddot*vj2;
    #pragma unroll
    for (int k = 0; k < 11; k++){
      float v = warpsum(p[k]);
      if (lane == 0) red[sub][warp][k] = v;
    }
    __syncthreads();
    if (c < 11 && act){
      float v = red[sub][0][c] + red[sub][1][c] + red[sub][2][c] + red[sub][3][c];
      if (c < 8) g_def[e*NB_ + c] = v;
      else       g_dY1b[e*3 + (c-8)] = v;
    }
    __syncthreads();
  }
}

/* --------------- backward layer-1: 2 edges per 256-thread block ---------- */
__global__ void __launch_bounds__(256) bwd1_kernel(const float* __restrict__ R1){
  __shared__ float red[2][4][11];
  int tid = threadIdx.x;
  int c = tid & 127;
  int sub = tid >> 7;
  int warp = (tid >> 5) & 3, lane = tid & 31;
  float r1a[NB_], r1b[NB_];
  #pragma unroll
  for (int b = 0; b < NB_; b++){ r1a[b]=R1[b*256 + c]; r1b[b]=R1[b*256 + 128 + c]; }
  int nact = g_nact;
  for (int base = blockIdx.x*2; base < nact; base += gridDim.x*2){
    int e = base + sub;
    bool act = (e < nact);
    float y0=0.f, y1=0.f, y2=0.f;
    float w1=0.f, dm0=0.f, dm10=0.f, dm11=0.f, dm12=0.f, sj=0.f;
    if (act){
      int rcv = g_ercv[e], zs = g_ezsnd[e];
      y0=g_Y1[e*3+0]; y1=g_Y1[e*3+1]; y2=g_Y1[e*3+2];
      #pragma unroll
      for (int b = 0; b < NB_; b++){ float efb=g_ef[e*NB_+b]; w1 = fmaf(efb, r1b[b], w1); }
      dm0 = g_dA0[rcv*K + c];
      dm10 = g_dA1[rcv*K + c];
      dm11 = g_dA1[NK + rcv*K + c];
      dm12 = g_dA1[2*NK + rcv*K + c];
      sj = g_sU1[zs*K + c];
    }
    float dw0 = dm0*sj;
    float t = dm10*y0 + dm11*y1 + dm12*y2;
    float dw1 = t*sj;
    float p[11];
    #pragma unroll
    for (int b = 0; b < NB_; b++) p[b] = fmaf(dw0, r1a[b], dw1*r1b[b]);
    float ws = w1*sj;
    p[8] = dm10*ws; p[9] = dm11*ws; p[10] = dm12*ws;
    #pragma unroll
    for (int k = 0; k < 11; k++){
      float v = warpsum(p[k]);
      if (lane == 0) red[sub][warp][k] = v;
    }
    __syncthreads();
    if (c < 11 && act){
      float v = red[sub][0][c] + red[sub][1][c] + red[sub][2][c] + red[sub][3][c];
      if (c < 8) g_def[e*NB_ + c] += v;
      else       g_dY1b[e*3 + (c-8)] += v;
    }
    __syncthreads();
  }
}

/* ---------------- geometry backward + finalize (merged) ------------------ */
__global__ void geom_bwd_fin_kernel(float* __restrict__ F, float* __restrict__ out){
  if (blockIdx.x == gridDim.x - 1){
    int g = threadIdx.x;
    if (g < GG){
      float a = g_e0[g], b = g_e1[g], c = g_e2[g];
      out[g] = a + b + c;
      out[GG + g*3 + 0] = a;
      out[GG + g*3 + 1] = b;
      out[GG + g*3 + 2] = c;
    }
    return;
  }
  int stride = (gridDim.x - 1)*blockDim.x;
  int nact = g_nact;
  for (int e = blockIdx.x*blockDim.x + threadIdx.x; e < nact; e += stride){
    float rr = g_r[e];
    float y0=g_Y1[e*3+0], y1=g_Y1[e*3+1], y2=g_Y1[e*3+2];
    float v0 = y0*rr*INV_SQ3, v1 = y1*rr*INV_SQ3, v2 = y2*rr*INV_SQ3;
    float x = rr*0.2f;
    float x2=x*x, x4=x2*x2, x5=x4*x;
    float fc = 1.f + x5*(-21.f + x*(35.f - 15.f*x));
    float omx = 1.f - x;
    float dfcdr = -21.f*x4*omx*omx;
    float invr = 1.f/rr;
    float s1_, c1_;
    sincosf(PI_F*0.2f*rr, &s1_, &c1_);
    float sb = s1_, cb = c1_;
    float dr = 0.f;
    #pragma unroll
    for (int b = 0; b < NB_; b++){
      float a = (float)(b+1)*(PI_F*0.2f);
      float debdr = CB_F*((a*cb*rr - sb)*invr*invr*fc + sb*invr*dfcdr);
      dr = fmaf(g_def[e*NB_ + b], debdr, dr);
      float ns = sb*c1_ + cb*s1_;
      float nc = cb*c1_ - sb*s1_;
      sb = ns; cb = nc;
    }
    float dY0=g_dY1b[e*3+0], dY1v=g_dY1b[e*3+1], dY2=g_dY1b[e*3+2];
    float vd = v0*dY0 + v1*dY1v + v2*dY2;
    float c1c = SQ3F*invr;
    float c2c = SQ3F*vd*invr*invr*invr;
    float dv0 = dr*v0*invr + c1c*dY0 - c2c*v0;
    float dv1 = dr*v1*invr + c1c*dY1v - c2c*v1;
    float dv2 = dr*v2*invr + c1c*dY2 - c2c*v2;
    int snd = g_esnd[e], rcv = g_ercv[e];
    atomicAdd(&F[snd*3+0],  dv0); atomicAdd(&F[snd*3+1],  dv1); atomicAdd(&F[snd*3+2],  dv2);
    atomicAdd(&F[rcv*3+0], -dv0); atomicAdd(&F[rcv*3+1], -dv1); atomicAdd(&F[rcv*3+2], -dv2);
  }
}

/* ------------------------------ host helpers ----------------------------- */
static void tops_init(TOps& P){ P.count = 0; }
static void tops_add(TOps& P, int kind, int tiles, int bidx, const float* A, float* C,
                     int M, float alpha, int accum, const float* table, int useNz,
                     const float* bias){
  int i = P.count++;
  P.kind[i]=kind; P.tiles[i]=tiles; P.bidx[i]=bidx; P.A[i]=A; P.C[i]=C; P.M[i]=M;
  P.alpha[i]=alpha; P.accum[i]=accum; P.table[i]=table; P.useNz[i]=useNz; P.bias[i]=bias;
}
static int tops_total(const TOps& P){
  int t = 0; for (int i = 0; i < P.count; i++) t += P.tiles[i];
  return t;
}

/* ------------------------------ launch ----------------------------------- */
extern "C" void kernel_launch(void* const* d_in, const int* in_sizes, int n_in,
                              void* d_out, int out_size){
  const float *positions, *shifts, *ae, *We, *R1, *Wu1, *Wms1, *Wmv1, *Wsk1, *wr1;
  const float *R2, *Wu2s, *Wu2v, *Wms2, *Wsk2, *Wmlp, *wout;
  const int *edge_index, *node_z, *batch;

  if (in_sizes[2] == 2*EE){  /* setup_inputs dict order */
    positions=(const float*)d_in[0]; shifts=(const float*)d_in[1];
    edge_index=(const int*)d_in[2]; node_z=(const int*)d_in[3]; batch=(const int*)d_in[4];
    ae=(const float*)d_in[5]; We=(const float*)d_in[6]; R1=(const float*)d_in[7];
    Wu1=(const float*)d_in[8]; Wms1=(const float*)d_in[9]; Wmv1=(const float*)d_in[10];
    Wsk1=(const float*)d_in[11]; wr1=(const float*)d_in[12]; R2=(const float*)d_in[13];
    Wu2s=(const float*)d_in[14]; Wu2v=(const float*)d_in[15]; Wms2=(const float*)d_in[16];
    Wsk2=(const float*)d_in[17]; Wmlp=(const float*)d_in[18]; wout=(const float*)d_in[19];
  } else {                   /* reference signature order */
    positions=(const float*)d_in[0]; shifts=(const float*)d_in[1];
    ae=(const float*)d_in[2]; We=(const float*)d_in[3]; R1=(const float*)d_in[4];
    Wu1=(const float*)d_in[5]; Wms1=(const float*)d_in[6]; Wmv1=(const float*)d_in[7];
    Wsk1=(const float*)d_in[8]; wr1=(const float*)d_in[9]; R2=(const float*)d_in[10];
    Wu2s=(const float*)d_in[11]; Wu2v=(const float*)d_in[12]; Wms2=(const float*)d_in[13];
    Wsk2=(const float*)d_in[14]; Wmlp=(const float*)d_in[15]; wout=(const float*)d_in[16];
    edge_index=(const int*)d_in[17]; node_z=(const int*)d_in[18]; batch=(const int*)d_in[19];
  }
  float* out = (float*)d_out;

  float *p_A0,*p_A1,*p_sU2,*p_vU2,*p_A2,*p_s2,*p_ds2,*p_dA2,*p_Dsj2,*p_Dvj,*p_dA0,*p_dA1;
  float *p_WF,*p_tabU2,*p_tabS2,*p_u;
  cudaGetSymbolAddress((void**)&p_A0, g_A0);     cudaGetSymbolAddress((void**)&p_A1, g_A1);
  cudaGetSymbolAddress((void**)&p_sU2, g_sU2);   cudaGetSymbolAddress((void**)&p_vU2, g_vU2);
  cudaGetSymbolAddress((void**)&p_A2, g_A2);     cudaGetSymbolAddress((void**)&p_s2, g_s2);
  cudaGetSymbolAddress((void**)&p_ds2, g_ds2);   cudaGetSymbolAddress((void**)&p_dA2, g_dA2);
  cudaGetSymbolAddress((void**)&p_Dsj2, g_Dsj2); cudaGetSymbolAddress((void**)&p_Dvj, g_Dvj);
  cudaGetSymbolAddress((void**)&p_dA0, g_dA0);   cudaGetSymbolAddress((void**)&p_dA1, g_dA1);
  cudaGetSymbolAddress((void**)&p_WF, g_WF);     cudaGetSymbolAddress((void**)&p_tabU2, g_tabU2);
  cudaGetSymbolAddress((void**)&p_tabS2, g_tabS2); cudaGetSymbolAddress((void**)&p_u, g_u);

  cudaFuncSetAttribute(tgemm_big_kernel, cudaFuncAttributeMaxDynamicSharedMemorySize, TG_SMEM);
  cudaFuncSetAttribute(tgemm_sm_kernel,  cudaFuncAttributeMaxDynamicSharedMemorySize, TG_SMEM);

  /* 1: init = zero + tables + fp32 weight GEMMs */
  {
    GOps P; P.count = 0;
    int i;
    i = P.count++; P.A[i]=Wms1; P.B[i]=Wu2s; P.C[i]=p_WF;      P.M[i]=K; P.tiles[i]=2;
    i = P.count++; P.A[i]=Wmv1; P.B[i]=Wu2v; P.C[i]=p_WF + KK; P.M[i]=K; P.tiles[i]=2;
    for (int z = 0; z < NE_; z++){
      i = P.count++; P.A[i]=Wms1; P.B[i]=Wsk2 + z*KK; P.C[i]=p_WF + (2+z)*KK; P.M[i]=K; P.tiles[i]=2;
    }
    init_kernel<<<ZB + 11 + 24, 256>>>(out, out_size, P, We, Wu1, Wsk1, Wu2s, Wsk2, Wms1, wr1);
  }
  /* 2: work1 = geom + z-prep + weight conversion */
  work1_kernel<<<625 + 1 + 52, 256>>>(positions, shifts, edge_index, node_z, p_WF, Wms2);
  /* 3 */
  msg1_kernel<<<1024, 256>>>(R1);
  /* 4: stage C = sU2, vU2, grouped s2, e1+e0 — BIG tiles (measured faster) */
  {
    TOps P; tops_init(P);
    tops_add(P, 0, CDIV(NN,TNB),   0, p_A0, p_sU2, NN,   ALPHA_, 0, p_tabU2, 1, 0);
    tops_add(P, 0, CDIV(3*NN,TNB), 1, p_A1, p_vU2, 3*NN, ALPHA_, 0, 0, 0, 0);
    tops_add(P, 1, GTZ_BIG*NE_,    2, p_A0, p_s2,  NN,   ALPHA_, 0, p_tabS2, 0, 0);
    tops_add(P, 2, CDIV(NN*32,512), 0, 0, 0, NN, 0.f, 0, 0, 0, 0);
    tgemm_big_kernel<<<tops_total(P), 512, TG_SMEM>>>(P, node_z, batch, ae);
  }
  /* 5 */
  msg2_kernel<<<1024, 256>>>(R2);
  /* 6: s2 += a*A2@Wms2 — SMALL tiles (more blocks, better fill) */
  {
    TOps P; tops_init(P);
    tops_add(P, 0, CDIV(NN,TNS), 12, p_A2, p_s2, NN, ALPHA_, 1, 0, 0, 0);
    tgemm_sm_kernel<<<tops_total(P), 256, TG_SMEM>>>(P, node_z);
  }
  /* 7 */
  mlp_kernel<<<2048, 128>>>(Wmlp, wout, batch);
  /* 8: dA2 = a*ds2@Wms2^T ; grouped dA0 = a*ds2@WF2z^T — SMALL tiles */
  {
    TOps P; tops_init(P);
    tops_add(P, 0, CDIV(NN,TNS), 25, p_ds2, p_dA2, NN, ALPHA_, 0, 0, 0, 0);
    tops_add(P, 1, GTZ_SM*NE_,   15, p_ds2, p_dA0, NN, ALPHA_, 0, 0, 0, 0);
    tgemm_sm_kernel<<<tops_total(P), 256, TG_SMEM>>>(P, node_z);
  }
  /* 9 */
  bwd2_kernel<<<1024, 256>>>(R2);
  /* 10: dA0 += a*(Dsj2@WF1^T + u^T) ; dA1 = a*Dvj@Wfuse^T — SMALL tiles */
  {
    TOps P; tops_init(P);
    tops_add(P, 0, CDIV(NN,TNS),   13, p_Dsj2, p_dA0, NN,   ALPHA_, 1, 0, 0, p_u);
    tops_add(P, 0, CDIV(3*NN,TNS), 14, p_Dvj,  p_dA1, 3*NN, ALPHA_, 0, 0, 0, 0);
    tgemm_sm_kernel<<<tops_total(P), 256, TG_SMEM>>>(P, node_z);
  }
  /* 11 */
  bwd1_kernel<<<1024, 256>>>(R1);
  /* 12: geometry backward + finalize */
  geom_bwd_fin_kernel<<<1025, 256>>>(out + GG + 3*GG, out);
}

// round 13
// speedup vs baseline: 1.0517x; 1.0094x over previous
#include <cuda_runtime.h>
#include <cuda_bf16.h>
#include <math.h>
#include <stdint.h>

#define K 128
#define KK (K*K)
#define NN 10000
#define EE 160000
#define NE_ 10
#define NB_ 8
#define GG 16
#define NK (NN*K)
#define TM 64
#define TNB 256              /* big tile rows */
#define TNS 128              /* small tile rows */
#define GTZ_BIG 40           /* CDIV(NN,TNB) */
#define GTZ_SM  79           /* CDIV(NN,TNS) */

#define SQ3F 1.7320508075688772f
#define INV_SQ3 0.5773502691896258f
#define PI_F 3.14159265358979323846f
#define CB_F 0.6324555320336759f
#define ALPHA_ (1.0f/16.0f)
#define CDIV(a,b) (((a)+(b)-1)/(b))

/* ---- smem layout for tensor GEMM: W full, A in 64-row buffers ----------- */
#define PITCH_B 272
#define W_H_B 0
#define W_L_B 34816
#define A_H_B 69632
#define A_L_B 87040
#define ROWIDX_B 104448      /* up to 256 ints */
#define TG_SMEM 105472       /* 103 KB -> 2 CTAs/SM */

__device__ __forceinline__ uint32_t smem_u32(const void* p){
  uint32_t a;
  asm("{ .reg .u64 t; cvta.to.shared.u64 t, %1; cvt.u32.u64 %0, t; }" : "=r"(a) : "l"(p));
  return a;
}
#define LDM4(r, addr) \
  asm volatile("ldmatrix.sync.aligned.m8n8.x4.shared.b16 {%0,%1,%2,%3}, [%4];" \
    : "=r"((r)[0]),"=r"((r)[1]),"=r"((r)[2]),"=r"((r)[3]) : "r"(addr))
#define MMA16816(c, a, b0, b1) \
  asm volatile("mma.sync.aligned.m16n8k16.row.col.f32.bf16.bf16.f32 " \
    "{%0,%1,%2,%3}, {%4,%5,%6,%7}, {%8,%9}, {%0,%1,%2,%3};" \
    : "+f"((c)[0]),"+f"((c)[1]),"+f"((c)[2]),"+f"((c)[3]) \
    : "r"((a)[0]),"r"((a)[1]),"r"((a)[2]),"r"((a)[3]), "r"(b0),"r"(b1))
#define BARSYNC(id, cnt) asm volatile("bar.sync %0, %1;" :: "r"(id), "r"(cnt) : "memory")

__device__ __forceinline__ uint32_t pk_bf2(__nv_bfloat16 a, __nv_bfloat16 b){
  return (uint32_t)__bfloat16_as_ushort(a) | ((uint32_t)__bfloat16_as_ushort(b) << 16);
}

/* ------------------- device scratch (no allocs allowed) ------------------ */
__device__ float g_sU1[NE_*K];
__device__ float g_tabU2[NE_*K];
__device__ float g_tabS2[NE_*K];
__device__ float g_t1[NE_];
__device__ float g_u[K];
__device__ float g_r[EE];
__device__ float g_Y1[EE*3];
__device__ float g_ef[EE*NB_];
__device__ int   g_esnd[EE], g_ercv[EE], g_ezsnd[EE];
__device__ int   g_nact;
__device__ float g_A0[NK];
__device__ float g_A1[3*NK];
__device__ float g_sU2[NK];
__device__ float g_vU2[3*NK];
__device__ float g_A2[NK];
__device__ float g_s2[NK];
__device__ float g_ds2[NK];
__device__ float g_dA2[NK];
__device__ float g_Dsj2[NK];
__device__ float g_Dvj[3*NK];
__device__ float g_dA0[NK];
__device__ float g_dA1[3*NK];
__device__ float g_def[EE*NB_];
__device__ float g_dY1b[EE*3];
__device__ float g_e0[GG], g_e1[GG], g_e2[GG];
__device__ float g_WF[12*KK];
__device__ __nv_bfloat16 g_Bh[26*KK];
__device__ __nv_bfloat16 g_Bl[26*KK];
__device__ int g_zoff[NE_+1], g_zperm[NN];

/* -------- fp32 multi-op GEMM struct (weight precompute) ------------------ */
#define MAXG 12
struct GOps {
  int count;
  int tiles[MAXG];
  const float* A[MAXG];
  const float* B[MAXG];
  float* C[MAXG];
  int M[MAXG];
};

/* ================= init: zero + per-z tables + weight GEMMs ============== */
#define ZB 2048
__global__ void __launch_bounds__(256) init_kernel(float* __restrict__ out, int out_size, GOps P,
    const float* __restrict__ We, const float* __restrict__ Wu1, const float* __restrict__ Wsk1,
    const float* __restrict__ Wu2s, const float* __restrict__ Wsk2, const float* __restrict__ Wms1,
    const float* __restrict__ wr1){
  __shared__ char ubuf[32768];
  int b = blockIdx.x;
  int tid = threadIdx.x;
  if (b < ZB){
    int total = 3*NK;
    if (out_size > total) total = out_size;
    for (int i = b*256 + tid; i < total; i += ZB*256){
      if (i < 3*NK){ g_A1[i]=0.f; g_Dvj[i]=0.f; }
      if (i < NK){ g_A0[i]=0.f; g_A2[i]=0.f; g_Dsj2[i]=0.f; }
      if (i < out_size) out[i]=0.f;
      if (i < GG){ g_e0[i]=0.f; g_e1[i]=0.f; g_e2[i]=0.f; }
      if (i == 0) g_nact = 0;
    }
    return;
  }
  if (b < ZB + 11){
    int z = b - ZB;
    if (tid >= 128) return;
    int d = tid;
    float* sh  = (float*)ubuf;
    float* red = (float*)(ubuf + 512);
    if (z == NE_){
      float a = 0.f;
      for (int m = 0; m < K; m++) a = fmaf(Wms1[d*K + m], wr1[m], a);
      g_u[d] = a;
      return;
    }
    float a = 0.f, bb = 0.f;
    for (int c = 0; c < K; c++){
      float s = We[z*K + c];
      a  = fmaf(s, Wu1[c*K + d], a);
      bb = fmaf(s, Wsk1[(z*K + c)*K + d], bb);
    }
    g_sU1[z*K + d] = a;
    sh[d] = bb;
    __syncthreads();
    float t2 = 0.f, t3 = 0.f;
    for (int c = 0; c < K; c++){
      float s = sh[c];
      t2 = fmaf(s, Wu2s[c*K + d], t2);
      t3 = fmaf(s, Wsk2[(z*K + c)*K + d], t3);
    }
    g_tabU2[z*K + d] = t2;
    g_tabS2[z*K + d] = t3;
    float p = sh[d]*wr1[d];
    #pragma unroll
    for (int o = 16; o; o >>= 1) p += __shfl_down_sync(0xffffffffu, p, o);
    if ((d & 31) == 0) red[d >> 5] = p;
    __syncthreads();
    if (d == 0) g_t1[z] = red[0] + red[1] + red[2] + red[3];
    return;
  }
  b -= (ZB + 11);
  int op = 0;
  while (b >= P.tiles[op]){ b -= P.tiles[op]; op++; }
  typedef float (*AsT)[K];
  AsT As = (AsT)ubuf;
  int d = tid & 127;
  int g = tid >> 7;
  int M = P.M[op];
  const float* __restrict__ A = P.A[op];
  int base0 = b*TM;
  #pragma unroll 4
  for (int i = 0; i < 32; i++){
    int r = g*32 + i;
    As[r][d] = (base0 + r < M) ? A[(base0 + r)*K + d] : 0.f;
  }
  __syncthreads();
  const float* __restrict__ B = P.B[op];
  float acc[32];
  #pragma unroll
  for (int i = 0; i < 32; i++) acc[i] = 0.f;
  for (int c = 0; c < K; c += 4){
    float b0=B[c*K+d], b1=B[(c+1)*K+d], b2=B[(c+2)*K+d], b3=B[(c+3)*K+d];
    #pragma unroll
    for (int i = 0; i < 32; i++){
      float4 av = *(const float4*)&As[g*32 + i][c];
      acc[i] = fmaf(av.x,b0,fmaf(av.y,b1,fmaf(av.z,b2,fmaf(av.w,b3,acc[i]))));
    }
  }
  float* __restrict__ C = P.C[op];
  int base = base0 + g*32;
  for (int i = 0; i < 32; i++){
    int n = base + i;
    if (n >= M) break;
    C[n*K + d] = acc[i];
  }
}

/* ============ work1: geom + conv (split bf16) + z count/scan/scatter ===== */
__global__ void __launch_bounds__(256) work1_kernel(const float* __restrict__ pos,
    const float* __restrict__ shifts, const int* __restrict__ ei, const int* __restrict__ nz,
    const float* __restrict__ WF, const float* __restrict__ Wms2){
  int b = blockIdx.x;
  if (b < 625){
    int e = b*256 + threadIdx.x;
    if (e >= EE) return;
    int s = ei[e], rc = ei[EE + e];
    float vx = pos[rc*3+0] - pos[s*3+0] + shifts[e*3+0];
    float vy = pos[rc*3+1] - pos[s*3+1] + shifts[e*3+1];
    float vz = pos[rc*3+2] - pos[s*3+2] + shifts[e*3+2];
    float rr = sqrtf(vx*vx + vy*vy + vz*vz + 1e-12f);
    if (rr < 5.0f){
      int i = atomicAdd(&g_nact, 1);
      g_esnd[i]=s; g_ercv[i]=rc; g_ezsnd[i]=nz[s];
      g_r[i]=rr;
      float inv = SQ3F / rr;
      g_Y1[i*3+0]=vx*inv; g_Y1[i*3+1]=vy*inv; g_Y1[i*3+2]=vz*inv;
      float x = rr*0.2f;
      float x2=x*x, x4=x2*x2, x5=x4*x;
      float fc = 1.f + x5*(-21.f + x*(35.f - 15.f*x));
      float invr = 1.f/rr;
      float cf = CB_F*invr*fc;
      float s1_, c1_;
      sincosf(PI_F*0.2f*rr, &s1_, &c1_);
      float sb = s1_, cb = c1_;
      #pragma unroll
      for (int bb = 0; bb < NB_; bb++){
        g_ef[i*NB_ + bb] = cf*sb;
        float ns = sb*c1_ + cb*s1_;
        float nc = cb*c1_ - sb*s1_;
        sb = ns; cb = nc;
      }
    }
    return;
  }
  if (b == 625){
    __shared__ int cnt[NE_];
    __shared__ int off[NE_+1];
    __shared__ int fill[NE_];
    int tid = threadIdx.x;
    if (tid < NE_) cnt[tid] = 0;
    __syncthreads();
    for (int n = tid; n < NN; n += 256) atomicAdd(&cnt[nz[n]], 1);
    __syncthreads();
    if (tid == 0){
      int acc = 0;
      for (int z = 0; z < NE_; z++){ off[z] = acc; g_zoff[z] = acc; acc += cnt[z]; }
      off[NE_] = acc; g_zoff[NE_] = acc;
    }
    __syncthreads();
    if (tid < NE_) fill[tid] = off[tid];
    __syncthreads();
    for (int n = tid; n < NN; n += 256){
      int p = atomicAdd(&fill[nz[n]], 1);
      g_zperm[p] = n;
    }
    return;
  }
  int bb = b - 626;
  for (int id = bb*256 + threadIdx.x; id < 26*KK; id += 52*256){
    int j = id >> 14;
    int rem = id & (KK-1);
    int n = rem >> 7, k = rem & 127;
    const float* W; int trans;
    if (j < 12){ W = WF + j*KK; trans = 0; }
    else if (j == 12){ W = Wms2; trans = 0; }
    else if (j < 25){ W = WF + (j-13)*KK; trans = 1; }
    else { W = Wms2; trans = 1; }
    float v = trans ? W[n*K + k] : W[k*K + n];
    __nv_bfloat16 h = __float2bfloat16(v);
    __nv_bfloat16 l = __float2bfloat16(v - __bfloat162float(h));
    g_Bh[(size_t)j*KK + rem] = h;
    g_Bl[(size_t)j*KK + rem] = l;
  }
}

/* ---------- big tensor GEMM core (512 thr, 256-row tile, 4 quarters) -----
   per-row-group named barriers: the 4 warps sharing a 16-row group stage
   their own rows and sync only among themselves -> groups pipeline freely  */
__device__ __forceinline__ void tgemm_core_big(char* smc, const int* __restrict__ rowIdx,
    const float* __restrict__ A, float* __restrict__ C, int bidx, float alpha, int accum,
    const float* __restrict__ tab, const int* __restrict__ nz, const float* __restrict__ bias){
  int tid = threadIdx.x;
  {
    const uint4* gh = (const uint4*)(g_Bh + (size_t)bidx*KK);
    const uint4* gl = (const uint4*)(g_Bl + (size_t)bidx*KK);
    #pragma unroll
    for (int i = 0; i < 4; i++){
      int idx = tid + i*512;
      int row = idx >> 4, q = idx & 15;
      uint4 vh = gh[idx], vl = gl[idx];
      *(uint4*)(smc + W_H_B + row*PITCH_B + q*16) = vh;
      *(uint4*)(smc + W_L_B + row*PITCH_B + q*16) = vl;
    }
  }
  __syncthreads();

  int warp = tid >> 5, lane = tid & 31;
  int grp = warp & 3;
  int mrow0 = grp*16;
  int ncol0 = (warp >> 2)*32;
  int gtid = (warp >> 2)*32 + lane;   /* 0..127 within row-group */
  int barid = grp + 1;
  int quad = lane >> 3, rin = lane & 7;
  uint32_t smbase = smem_u32(smc);
  uint32_t aoff = (uint32_t)(rin + (quad & 1)*8)*PITCH_B + (uint32_t)((quad >> 1)*8)*2;
  uint32_t ahb = smbase + A_H_B + (uint32_t)mrow0*PITCH_B + aoff;
  uint32_t alb = smbase + A_L_B + (uint32_t)mrow0*PITCH_B + aoff;
  uint32_t boff = (uint32_t)(rin + (quad >> 1)*8)*PITCH_B + (uint32_t)((quad & 1)*8)*2;
  uint32_t whb = smbase + W_H_B + (uint32_t)ncol0*PITCH_B + boff;
  uint32_t wlb = smbase + W_L_B + (uint32_t)ncol0*PITCH_B + boff;
  int g = lane >> 2, tg = lane & 3;

  #pragma unroll
  for (int qtr = 0; qtr < 4; qtr++){
    /* stage this group's 16 rows: 16x32 float4 chunks / 128 threads = 4 ea */
    #pragma unroll
    for (int i = 0; i < 4; i++){
      int idx = gtid + i*128;
      int row16 = idx >> 5, c4 = (idx & 31)*4;
      int row = mrow0 + row16;
      int gr = rowIdx[qtr*64 + row];
      float4 v = (gr >= 0) ? *(const float4*)&A[(size_t)gr*K + c4] : make_float4(0.f,0.f,0.f,0.f);
      __nv_bfloat16 h0=__float2bfloat16(v.x), h1=__float2bfloat16(v.y);
      __nv_bfloat16 h2=__float2bfloat16(v.z), h3=__float2bfloat16(v.w);
      __nv_bfloat16 l0=__float2bfloat16(v.x-__bfloat162float(h0));
      __nv_bfloat16 l1=__float2bfloat16(v.y-__bfloat162float(h1));
      __nv_bfloat16 l2=__float2bfloat16(v.z-__bfloat162float(h2));
      __nv_bfloat16 l3=__float2bfloat16(v.w-__bfloat162float(h3));
      *(uint2*)(smc + A_H_B + row*PITCH_B + c4*2) = make_uint2(pk_bf2(h0,h1), pk_bf2(h2,h3));
      *(uint2*)(smc + A_L_B + row*PITCH_B + c4*2) = make_uint2(pk_bf2(l0,l1), pk_bf2(l2,l3));
    }
    BARSYNC(barid, 128);

    float c[4][4];
    #pragma unroll
    for (int nt = 0; nt < 4; nt++){ c[nt][0]=0.f; c[nt][1]=0.f; c[nt][2]=0.f; c[nt][3]=0.f; }

    #pragma unroll
    for (int kt = 0; kt < 8; kt++){
      uint32_t kb = (uint32_t)kt*32;
      uint32_t ah[4], al[4];
      LDM4(ah, ahb + kb);
      LDM4(al, alb + kb);
      #pragma unroll
      for (int s = 0; s < 2; s++){
        uint32_t bh[4], bl[4];
        LDM4(bh, whb + kb + (uint32_t)s*16*PITCH_B);
        LDM4(bl, wlb + kb + (uint32_t)s*16*PITCH_B);
        MMA16816(c[s*2],   ah, bh[0], bh[1]);
        MMA16816(c[s*2],   ah, bl[0], bl[1]);
        MMA16816(c[s*2],   al, bh[0], bh[1]);
        MMA16816(c[s*2+1], ah, bh[2], bh[3]);
        MMA16816(c[s*2+1], ah, bl[2], bl[3]);
        MMA16816(c[s*2+1], al, bh[2], bh[3]);
      }
    }

    #pragma unroll
    for (int hr = 0; hr < 2; hr++){
      int lrow = mrow0 + g + hr*8;
      int grow = rowIdx[qtr*64 + lrow];
      if (grow >= 0){
        const float* trow = 0;
        if (tab) trow = nz ? tab + (size_t)nz[grow]*K : tab;
        #pragma unroll
        for (int nt = 0; nt < 4; nt++){
          int col = ncol0 + nt*8 + tg*2;
          float v0 = alpha*c[nt][hr*2+0];
          float v1 = alpha*c[nt][hr*2+1];
          if (trow){ v0 += trow[col]; v1 += trow[col+1]; }
          if (bias){ v0 += alpha*bias[col]; v1 += alpha*bias[col+1]; }
          if (accum){ float2 o = *(const float2*)&C[(size_t)grow*K + col]; v0 += o.x; v1 += o.y; }
          *(float2*)&C[(size_t)grow*K + col] = make_float2(v0, v1);
        }
      }
    }
    if (qtr < 3) BARSYNC(barid, 128);   /* guard restage of this group's rows */
  }
}

/* ---------- small tensor GEMM core (256 thr, 128-row tile, 2 halves) -----
   same per-group pipelining: 2 warps per 16-row group, 64-thread barriers  */
__device__ __forceinline__ void tgemm_core_sm(char* smc, const int* __restrict__ rowIdx,
    const float* __restrict__ A, float* __restrict__ C, int bidx, float alpha, int accum,
    const float* __restrict__ tab, const int* __restrict__ nz, const float* __restrict__ bias){
  int tid = threadIdx.x;
  {
    const uint4* gh = (const uint4*)(g_Bh + (size_t)bidx*KK);
    const uint4* gl = (const uint4*)(g_Bl + (size_t)bidx*KK);
    #pragma unroll
    for (int i = 0; i < 8; i++){
      int idx = tid + i*256;
      int row = idx >> 4, q = idx & 15;
      uint4 vh = gh[idx], vl = gl[idx];
      *(uint4*)(smc + W_H_B + row*PITCH_B + q*16) = vh;
      *(uint4*)(smc + W_L_B + row*PITCH_B + q*16) = vl;
    }
  }
  __syncthreads();

  int warp = tid >> 5, lane = tid & 31;
  int grp = warp & 3;
  int mrow0 = grp*16;
  int ncol0 = (warp >> 2)*64;
  int gtid = (warp >> 2)*32 + lane;   /* 0..63 within row-group */
  int barid = grp + 1;
  int quad = lane >> 3, rin = lane & 7;
  uint32_t smbase = smem_u32(smc);
  uint32_t aoff = (uint32_t)(rin + (quad & 1)*8)*PITCH_B + (uint32_t)((quad >> 1)*8)*2;
  uint32_t ahb = smbase + A_H_B + (uint32_t)mrow0*PITCH_B + aoff;
  uint32_t alb = smbase + A_L_B + (uint32_t)mrow0*PITCH_B + aoff;
  uint32_t boff = (uint32_t)(rin + (quad >> 1)*8)*PITCH_B + (uint32_t)((quad & 1)*8)*2;
  uint32_t whb = smbase + W_H_B + (uint32_t)ncol0*PITCH_B + boff;
  uint32_t wlb = smbase + W_L_B + (uint32_t)ncol0*PITCH_B + boff;
  int g = lane >> 2, tg = lane & 3;

  #pragma unroll
  for (int half = 0; half < 2; half++){
    /* stage this group's 16 rows: 512 chunks / 64 threads = 8 ea */
    #pragma unroll
    for (int i = 0; i < 8; i++){
      int idx = gtid + i*64;
      int row16 = idx >> 5, c4 = (idx & 31)*4;
      int row = mrow0 + row16;
      int gr = rowIdx[half*64 + row];
      float4 v = (gr >= 0) ? *(const float4*)&A[(size_t)gr*K + c4] : make_float4(0.f,0.f,0.f,0.f);
      __nv_bfloat16 h0=__float2bfloat16(v.x), h1=__float2bfloat16(v.y);
      __nv_bfloat16 h2=__float2bfloat16(v.z), h3=__float2bfloat16(v.w);
      __nv_bfloat16 l0=__float2bfloat16(v.x-__bfloat162float(h0));
      __nv_bfloat16 l1=__float2bfloat16(v.y-__bfloat162float(h1));
      __nv_bfloat16 l2=__float2bfloat16(v.z-__bfloat162float(h2));
      __nv_bfloat16 l3=__float2bfloat16(v.w-__bfloat162float(h3));
      *(uint2*)(smc + A_H_B + row*PITCH_B + c4*2) = make_uint2(pk_bf2(h0,h1), pk_bf2(h2,h3));
      *(uint2*)(smc + A_L_B + row*PITCH_B + c4*2) = make_uint2(pk_bf2(l0,l1), pk_bf2(l2,l3));
    }
    BARSYNC(barid, 64);

    float c[8][4];
    #pragma unroll
    for (int nt = 0; nt < 8; nt++){ c[nt][0]=0.f; c[nt][1]=0.f; c[nt][2]=0.f; c[nt][3]=0.f; }

    #pragma unroll
    for (int kt = 0; kt < 8; kt++){
      uint32_t kb = (uint32_t)kt*32;
      uint32_t ah[4], al[4];
      LDM4(ah, ahb + kb);
      LDM4(al, alb + kb);
      #pragma unroll
      for (int nt2 = 0; nt2 < 4; nt2++){
        uint32_t bh[4], bl[4];
        LDM4(bh, whb + kb + (uint32_t)nt2*16*PITCH_B);
        LDM4(bl, wlb + kb + (uint32_t)nt2*16*PITCH_B);
        MMA16816(c[nt2*2],   ah, bh[0], bh[1]);
        MMA16816(c[nt2*2],   ah, bl[0], bl[1]);
        MMA16816(c[nt2*2],   al, bh[0], bh[1]);
        MMA16816(c[nt2*2+1], ah, bh[2], bh[3]);
        MMA16816(c[nt2*2+1], ah, bl[2], bl[3]);
        MMA16816(c[nt2*2+1], al, bh[2], bh[3]);
      }
    }

    #pragma unroll
    for (int hr = 0; hr < 2; hr++){
      int lrow = mrow0 + g + hr*8;
      int grow = rowIdx[half*64 + lrow];
      if (grow >= 0){
        const float* trow = 0;
        if (tab) trow = nz ? tab + (size_t)nz[grow]*K : tab;
        #pragma unroll
        for (int nt = 0; nt < 8; nt++){
          int col = ncol0 + nt*8 + tg*2;
          float v0 = alpha*c[nt][hr*2+0];
          float v1 = alpha*c[nt][hr*2+1];
          if (trow){ v0 += trow[col]; v1 += trow[col+1]; }
          if (bias){ v0 += alpha*bias[col]; v1 += alpha*bias[col+1]; }
          if (accum){ float2 o = *(const float2*)&C[(size_t)grow*K + col]; v0 += o.x; v1 += o.y; }
          *(float2*)&C[(size_t)grow*K + col] = make_float2(v0, v1);
        }
      }
    }
    if (half < 1) BARSYNC(barid, 64);
  }
}

/* ------ multi-op tensor GEMM: kind 0=linear 1=grouped 2=e1 --------------- */
#define MAXOPS 4
struct TOps {
  int count;
  int tiles[MAXOPS];
  int kind[MAXOPS];
  int bidx[MAXOPS];
  const float* A[MAXOPS];
  float* C[MAXOPS];
  const float* table[MAXOPS];
  const float* bias[MAXOPS];
  int M[MAXOPS];
  int accum[MAXOPS];
  int useNz[MAXOPS];
  float alpha[MAXOPS];
};

__global__ void __launch_bounds__(512) tgemm_big_kernel(TOps P, const int* __restrict__ node_z,
    const int* __restrict__ batch, const float* __restrict__ ae){
  int b = blockIdx.x, op = 0;
  while (b >= P.tiles[op]){ b -= P.tiles[op]; op++; }
  int kind = P.kind[op];
  if (kind == 2){
    int gt = b*512 + threadIdx.x;
    int n = gt >> 5, lane = gt & 31;
    if (n >= NN) return;
    float acc = 0.f;
    #pragma unroll
    for (int c = lane; c < K; c += 32) acc = fmaf(g_A0[n*K + c], g_u[c], acc);
    #pragma unroll
    for (int o = 16; o; o >>= 1) acc += __shfl_down_sync(0xffffffffu, acc, o);
    if (lane == 0){
      int zz = node_z[n];
      atomicAdd(&g_e1[batch[n]], ALPHA_*acc + g_t1[zz]);
      atomicAdd(&g_e0[batch[n]], ae[zz]);
    }
    return;
  }
  extern __shared__ char smc[];
  int* rowIdx = (int*)(smc + ROWIDX_B);
  int bidx = P.bidx[op];
  const float* tab = P.table[op];
  const int* nz = 0;
  if (kind == 0){
    int base = b*TNB, M = P.M[op];
    if (threadIdx.x < TNB) rowIdx[threadIdx.x] = (base + (int)threadIdx.x < M) ? base + threadIdx.x : -1;
    nz = P.useNz[op] ? node_z : 0;
  } else {
    int z = b / GTZ_BIG;
    int m0 = (b - z*GTZ_BIG)*TNB;
    int start = g_zoff[z], cnt = g_zoff[z+1] - start;
    if (m0 >= cnt) return;
    if (threadIdx.x < TNB) rowIdx[threadIdx.x] = (m0 + (int)threadIdx.x < cnt) ? g_zperm[start + m0 + threadIdx.x] : -1;
    bidx += z;
    if (tab) tab = tab + (size_t)z*K;
  }
  __syncthreads();
  tgemm_core_big(smc, rowIdx, P.A[op], P.C[op], bidx, P.alpha[op], P.accum[op], tab, nz, P.bias[op]);
}

__global__ void __launch_bounds__(256) tgemm_sm_kernel(TOps P, const int* __restrict__ node_z){
  int b = blockIdx.x, op = 0;
  while (b >= P.tiles[op]){ b -= P.tiles[op]; op++; }
  int kind = P.kind[op];
  extern __shared__ char smc[];
  int* rowIdx = (int*)(smc + ROWIDX_B);
  int bidx = P.bidx[op];
  const float* tab = P.table[op];
  const int* nz = 0;
  if (kind == 0){
    int base = b*TNS, M = P.M[op];
    if (threadIdx.x < TNS) rowIdx[threadIdx.x] = (base + (int)threadIdx.x < M) ? base + threadIdx.x : -1;
    nz = P.useNz[op] ? node_z : 0;
  } else {
    int z = b / GTZ_SM;
    int m0 = (b - z*GTZ_SM)*TNS;
    int start = g_zoff[z], cnt = g_zoff[z+1] - start;
    if (m0 >= cnt) return;
    if (threadIdx.x < TNS) rowIdx[threadIdx.x] = (m0 + (int)threadIdx.x < cnt) ? g_zperm[start + m0 + threadIdx.x] : -1;
    bidx += z;
    if (tab) tab = tab + (size_t)z*K;
  }
  __syncthreads();
  tgemm_core_sm(smc, rowIdx, P.A[op], P.C[op], bidx, P.alpha[op], P.accum[op], tab, nz, P.bias[op]);
}

/* --------------- layer-1 messages: 2 edges per 256-thread block ---------- */
__global__ void __launch_bounds__(256) msg1_kernel(const float* __restrict__ R1){
  int c = threadIdx.x & 127;
  int sub = threadIdx.x >> 7;
  float r1a[NB_], r1b[NB_];
  #pragma unroll
  for (int b = 0; b < NB_; b++){ r1a[b]=R1[b*256 + c]; r1b[b]=R1[b*256 + 128 + c]; }
  int nact = g_nact;
  for (int e = blockIdx.x*2 + sub; e < nact; e += gridDim.x*2){
    int rcv = g_ercv[e], zs = g_ezsnd[e];
    float y0=g_Y1[e*3+0], y1=g_Y1[e*3+1], y2=g_Y1[e*3+2];
    float w0=0.f, w1=0.f;
    #pragma unroll
    for (int b = 0; b < NB_; b++){ float efb=g_ef[e*NB_+b]; w0=fmaf(efb,r1a[b],w0); w1=fmaf(efb,r1b[b],w1); }
    float sj = g_sU1[zs*K + c];
    atomicAdd(&g_A0[rcv*K + c], w0*sj);
    float t = w1*sj;
    atomicAdd(&g_A1[rcv*K + c],        t*y0);
    atomicAdd(&g_A1[NK + rcv*K + c],   t*y1);
    atomicAdd(&g_A1[2*NK + rcv*K + c], t*y2);
  }
}

/* --------------- layer-2 messages: 2 edges per 256-thread block ---------- */
__global__ void __launch_bounds__(256) msg2_kernel(const float* __restrict__ R2){
  int c = threadIdx.x & 127;
  int sub = threadIdx.x >> 7;
  float r2a[NB_], r2b[NB_];
  #pragma unroll
  for (int b = 0; b < NB_; b++){ r2a[b]=R2[b*512 + c]; r2b[b]=R2[b*512 + 128 + c]; }
  int nact = g_nact;
  for (int e = blockIdx.x*2 + sub; e < nact; e += gridDim.x*2){
    int snd = g_esnd[e], rcv = g_ercv[e];
    float y0=g_Y1[e*3+0], y1=g_Y1[e*3+1], y2=g_Y1[e*3+2];
    float w00=0.f, w110=0.f;
    #pragma unroll
    for (int b = 0; b < NB_; b++){ float efb=g_ef[e*NB_+b]; w00=fmaf(efb,r2a[b],w00); w110=fmaf(efb,r2b[b],w110); }
    float sj = g_sU2[snd*K + c];
    float vj0=g_vU2[snd*K+c], vj1=g_vU2[NK+snd*K+c], vj2=g_vU2[2*NK+snd*K+c];
    float dot = vj0*y0 + vj1*y1 + vj2*y2;
    float m = fmaf(w00, sj, w110*dot*INV_SQ3);
    atomicAdd(&g_A2[rcv*K + c], m);
  }
}

/* ----------------------- MLP head: e2 + ds2 ------------------------------ */
__global__ void __launch_bounds__(128) mlp_kernel(const float* __restrict__ Wmlp,
    const float* __restrict__ wout, const int* __restrict__ batch){
  __shared__ float srow[K];
  __shared__ float gj[16];
  __shared__ float hpart[16];
  int tid = threadIdx.x;
  for (int n = blockIdx.x; n < NN; n += gridDim.x){
    srow[tid] = g_s2[n*K + tid];
    __syncthreads();
    if (tid < 16){
      float uu = 0.f;
      for (int c = 0; c < K; c++) uu = fmaf(srow[c], Wmlp[c*16 + tid], uu);
      float sig = 1.f/(1.f + __expf(-uu));
      hpart[tid] = uu*sig*wout[tid];
      gj[tid] = wout[tid]*sig*(1.f + uu*(1.f - sig));
    }
    __syncthreads();
    if (tid == 0){
      float s = 0.f;
      #pragma unroll
      for (int j = 0; j < 16; j++) s += hpart[j];
      atomicAdd(&g_e2[batch[n]], s);
    }
    float ds = 0.f;
    #pragma unroll
    for (int j = 0; j < 16; j++) ds = fmaf(Wmlp[tid*16 + j], gj[j], ds);
    g_ds2[n*K + tid] = ds;
    __syncthreads();
  }
}

/* --------------- backward layer-2: 2 edges per 256-thread block ---------- */
__device__ __forceinline__ float warpsum(float v){
  #pragma unroll
  for (int o = 16; o; o >>= 1) v += __shfl_down_sync(0xffffffffu, v, o);
  return v;
}

__global__ void __launch_bounds__(256) bwd2_kernel(const float* __restrict__ R2){
  __shared__ float red[2][4][11];
  int tid = threadIdx.x;
  int c = tid & 127;
  int sub = tid >> 7;
  int warp = (tid >> 5) & 3, lane = tid & 31;
  float r2a[NB_], r2b[NB_];
  #pragma unroll
  for (int b = 0; b < NB_; b++){ r2a[b]=R2[b*512 + c]; r2b[b]=R2[b*512 + 128 + c]; }
  int nact = g_nact;
  for (int base = blockIdx.x*2; base < nact; base += gridDim.x*2){
    int e = base + sub;
    bool act = (e < nact);
    float y0=0.f, y1=0.f, y2=0.f, dm=0.f, sj=0.f, vj0=0.f, vj1=0.f, vj2=0.f;
    float w00=0.f, w110=0.f;
    int snd=0;
    if (act){
      snd = g_esnd[e];
      int rcv = g_ercv[e];
      y0=g_Y1[e*3+0]; y1=g_Y1[e*3+1]; y2=g_Y1[e*3+2];
      #pragma unroll
      for (int b = 0; b < NB_; b++){ float efb=g_ef[e*NB_+b]; w00=fmaf(efb,r2a[b],w00); w110=fmaf(efb,r2b[b],w110); }
      dm = g_dA2[rcv*K + c];
      sj = g_sU2[snd*K + c];
      vj0=g_vU2[snd*K+c]; vj1=g_vU2[NK+snd*K+c]; vj2=g_vU2[2*NK+snd*K+c];
    }
    float dot = vj0*y0 + vj1*y1 + vj2*y2;
    float ddot = dm*w110*INV_SQ3;
    if (act){
      atomicAdd(&g_Dsj2[snd*K + c], dm*w00);
      atomicAdd(&g_Dvj[snd*K + c],        ddot*y0);
      atomicAdd(&g_Dvj[NK + snd*K + c],   ddot*y1);
      atomicAdd(&g_Dvj[2*NK + snd*K + c], ddot*y2);
    }
    float p[11];
    float dw00 = dm*sj, dw110 = dm*dot*INV_SQ3;
    #pragma unroll
    for (int b = 0; b < NB_; b++) p[b] = fmaf(dw00, r2a[b], dw110*r2b[b]);
    p[8] = ddot*vj0; p[9] = ddot*vj1; p[10] = ddot*vj2;
    #pragma unroll
    for (int k = 0; k < 11; k++){
      float v = warpsum(p[k]);
      if (lane == 0) red[sub][warp][k] = v;
    }
    __syncthreads();
    if (c < 11 && act){
      float v = red[sub][0][c] + red[sub][1][c] + red[sub][2][c] + red[sub][3][c];
      if (c < 8) g_def[e*NB_ + c] = v;
      else       g_dY1b[e*3 + (c-8)] = v;
    }
    __syncthreads();
  }
}

/* --------------- backward layer-1: 2 edges per 256-thread block ---------- */
__global__ void __launch_bounds__(256) bwd1_kernel(const float* __restrict__ R1){
  __shared__ float red[2][4][11];
  int tid = threadIdx.x;
  int c = tid & 127;
  int sub = tid >> 7;
  int warp = (tid >> 5) & 3, lane = tid & 31;
  float r1a[NB_], r1b[NB_];
  #pragma unroll
  for (int b = 0; b < NB_; b++){ r1a[b]=R1[b*256 + c]; r1b[b]=R1[b*256 + 128 + c]; }
  int nact = g_nact;
  for (int base = blockIdx.x*2; base < nact; base += gridDim.x*2){
    int e = base + sub;
    bool act = (e < nact);
    float y0=0.f, y1=0.f, y2=0.f;
    float w1=0.f, dm0=0.f, dm10=0.f, dm11=0.f, dm12=0.f, sj=0.f;
    if (act){
      int rcv = g_ercv[e], zs = g_ezsnd[e];
      y0=g_Y1[e*3+0]; y1=g_Y1[e*3+1]; y2=g_Y1[e*3+2];
      #pragma unroll
      for (int b = 0; b < NB_; b++){ float efb=g_ef[e*NB_+b]; w1 = fmaf(efb, r1b[b], w1); }
      dm0 = g_dA0[rcv*K + c];
      dm10 = g_dA1[rcv*K + c];
      dm11 = g_dA1[NK + rcv*K + c];
      dm12 = g_dA1[2*NK + rcv*K + c];
      sj = g_sU1[zs*K + c];
    }
    float dw0 = dm0*sj;
    float t = dm10*y0 + dm11*y1 + dm12*y2;
    float dw1 = t*sj;
    float p[11];
    #pragma unroll
    for (int b = 0; b < NB_; b++) p[b] = fmaf(dw0, r1a[b], dw1*r1b[b]);
    float ws = w1*sj;
    p[8] = dm10*ws; p[9] = dm11*ws; p[10] = dm12*ws;
    #pragma unroll
    for (int k = 0; k < 11; k++){
      float v = warpsum(p[k]);
      if (lane == 0) red[sub][warp][k] = v;
    }
    __syncthreads();
    if (c < 11 && act){
      float v = red[sub][0][c] + red[sub][1][c] + red[sub][2][c] + red[sub][3][c];
      if (c < 8) g_def[e*NB_ + c] += v;
      else       g_dY1b[e*3 + (c-8)] += v;
    }
    __syncthreads();
  }
}

/* ---------------- geometry backward + finalize (merged) ------------------ */
__global__ void geom_bwd_fin_kernel(float* __restrict__ F, float* __restrict__ out){
  if (blockIdx.x == gridDim.x - 1){
    int g = threadIdx.x;
    if (g < GG){
      float a = g_e0[g], b = g_e1[g], c = g_e2[g];
      out[g] = a + b + c;
      out[GG + g*3 + 0] = a;
      out[GG + g*3 + 1] = b;
      out[GG + g*3 + 2] = c;
    }
    return;
  }
  int stride = (gridDim.x - 1)*blockDim.x;
  int nact = g_nact;
  for (int e = blockIdx.x*blockDim.x + threadIdx.x; e < nact; e += stride){
    float rr = g_r[e];
    float y0=g_Y1[e*3+0], y1=g_Y1[e*3+1], y2=g_Y1[e*3+2];
    float v0 = y0*rr*INV_SQ3, v1 = y1*rr*INV_SQ3, v2 = y2*rr*INV_SQ3;
    float x = rr*0.2f;
    float x2=x*x, x4=x2*x2, x5=x4*x;
    float fc = 1.f + x5*(-21.f + x*(35.f - 15.f*x));
    float omx = 1.f - x;
    float dfcdr = -21.f*x4*omx*omx;
    float invr = 1.f/rr;
    float s1_, c1_;
    sincosf(PI_F*0.2f*rr, &s1_, &c1_);
    float sb = s1_, cb = c1_;
    float dr = 0.f;
    #pragma unroll
    for (int b = 0; b < NB_; b++){
      float a = (float)(b+1)*(PI_F*0.2f);
      float debdr = CB_F*((a*cb*rr - sb)*invr*invr*fc + sb*invr*dfcdr);
      dr = fmaf(g_def[e*NB_ + b], debdr, dr);
      float ns = sb*c1_ + cb*s1_;
      float nc = cb*c1_ - sb*s1_;
      sb = ns; cb = nc;
    }
    float dY0=g_dY1b[e*3+0], dY1v=g_dY1b[e*3+1], dY2=g_dY1b[e*3+2];
    float vd = v0*dY0 + v1*dY1v + v2*dY2;
    float c1c = SQ3F*invr;
    float c2c = SQ3F*vd*invr*invr*invr;
    float dv0 = dr*v0*invr + c1c*dY0 - c2c*v0;
    float dv1 = dr*v1*invr + c1c*dY1v - c2c*v1;
    float dv2 = dr*v2*invr + c1c*dY2 - c2c*v2;
    int snd = g_esnd[e], rcv = g_ercv[e];
    atomicAdd(&F[snd*3+0],  dv0); atomicAdd(&F[snd*3+1],  dv1); atomicAdd(&F[snd*3+2],  dv2);
    atomicAdd(&F[rcv*3+0], -dv0); atomicAdd(&F[rcv*3+1], -dv1); atomicAdd(&F[rcv*3+2], -dv2);
  }
}

/* ------------------------------ host helpers ----------------------------- */
static void tops_init(TOps& P){ P.count = 0; }
static void tops_add(TOps& P, int kind, int tiles, int bidx, const float* A, float* C,
                     int M, float alpha, int accum, const float* table, int useNz,
                     const float* bias){
  int i = P.count++;
  P.kind[i]=kind; P.tiles[i]=tiles; P.bidx[i]=bidx; P.A[i]=A; P.C[i]=C; P.M[i]=M;
  P.alpha[i]=alpha; P.accum[i]=accum; P.table[i]=table; P.useNz[i]=useNz; P.bias[i]=bias;
}
static int tops_total(const TOps& P){
  int t = 0; for (int i = 0; i < P.count; i++) t += P.tiles[i];
  return t;
}

/* ------------------------------ launch ----------------------------------- */
extern "C" void kernel_launch(void* const* d_in, const int* in_sizes, int n_in,
                              void* d_out, int out_size){
  const float *positions, *shifts, *ae, *We, *R1, *Wu1, *Wms1, *Wmv1, *Wsk1, *wr1;
  const float *R2, *Wu2s, *Wu2v, *Wms2, *Wsk2, *Wmlp, *wout;
  const int *edge_index, *node_z, *batch;

  if (in_sizes[2] == 2*EE){  /* setup_inputs dict order */
    positions=(const float*)d_in[0]; shifts=(const float*)d_in[1];
    edge_index=(const int*)d_in[2]; node_z=(const int*)d_in[3]; batch=(const int*)d_in[4];
    ae=(const float*)d_in[5]; We=(const float*)d_in[6]; R1=(const float*)d_in[7];
    Wu1=(const float*)d_in[8]; Wms1=(const float*)d_in[9]; Wmv1=(const float*)d_in[10];
    Wsk1=(const float*)d_in[11]; wr1=(const float*)d_in[12]; R2=(const float*)d_in[13];
    Wu2s=(const float*)d_in[14]; Wu2v=(const float*)d_in[15]; Wms2=(const float*)d_in[16];
    Wsk2=(const float*)d_in[17]; Wmlp=(const float*)d_in[18]; wout=(const float*)d_in[19];
  } else {                   /* reference signature order */
    positions=(const float*)d_in[0]; shifts=(const float*)d_in[1];
    ae=(const float*)d_in[2]; We=(const float*)d_in[3]; R1=(const float*)d_in[4];
    Wu1=(const float*)d_in[5]; Wms1=(const float*)d_in[6]; Wmv1=(const float*)d_in[7];
    Wsk1=(const float*)d_in[8]; wr1=(const float*)d_in[9]; R2=(const float*)d_in[10];
    Wu2s=(const float*)d_in[11]; Wu2v=(const float*)d_in[12]; Wms2=(const float*)d_in[13];
    Wsk2=(const float*)d_in[14]; Wmlp=(const float*)d_in[15]; wout=(const float*)d_in[16];
    edge_index=(const int*)d_in[17]; node_z=(const int*)d_in[18]; batch=(const int*)d_in[19];
  }
  float* out = (float*)d_out;

  float *p_A0,*p_A1,*p_sU2,*p_vU2,*p_A2,*p_s2,*p_ds2,*p_dA2,*p_Dsj2,*p_Dvj,*p_dA0,*p_dA1;
  float *p_WF,*p_tabU2,*p_tabS2,*p_u;
  cudaGetSymbolAddress((void**)&p_A0, g_A0);     cudaGetSymbolAddress((void**)&p_A1, g_A1);
  cudaGetSymbolAddress((void**)&p_sU2, g_sU2);   cudaGetSymbolAddress((void**)&p_vU2, g_vU2);
  cudaGetSymbolAddress((void**)&p_A2, g_A2);     cudaGetSymbolAddress((void**)&p_s2, g_s2);
  cudaGetSymbolAddress((void**)&p_ds2, g_ds2);   cudaGetSymbolAddress((void**)&p_dA2, g_dA2);
  cudaGetSymbolAddress((void**)&p_Dsj2, g_Dsj2); cudaGetSymbolAddress((void**)&p_Dvj, g_Dvj);
  cudaGetSymbolAddress((void**)&p_dA0, g_dA0);   cudaGetSymbolAddress((void**)&p_dA1, g_dA1);
  cudaGetSymbolAddress((void**)&p_WF, g_WF);     cudaGetSymbolAddress((void**)&p_tabU2, g_tabU2);
  cudaGetSymbolAddress((void**)&p_tabS2, g_tabS2); cudaGetSymbolAddress((void**)&p_u, g_u);

  cudaFuncSetAttribute(tgemm_big_kernel, cudaFuncAttributeMaxDynamicSharedMemorySize, TG_SMEM);
  cudaFuncSetAttribute(tgemm_sm_kernel,  cudaFuncAttributeMaxDynamicSharedMemorySize, TG_SMEM);

  /* 1: init = zero + tables + fp32 weight GEMMs */
  {
    GOps P; P.count = 0;
    int i;
    i = P.count++; P.A[i]=Wms1; P.B[i]=Wu2s; P.C[i]=p_WF;      P.M[i]=K; P.tiles[i]=2;
    i = P.count++; P.A[i]=Wmv1; P.B[i]=Wu2v; P.C[i]=p_WF + KK; P.M[i]=K; P.tiles[i]=2;
    for (int z = 0; z < NE_; z++){
      i = P.count++; P.A[i]=Wms1; P.B[i]=Wsk2 + z*KK; P.C[i]=p_WF + (2+z)*KK; P.M[i]=K; P.tiles[i]=2;
    }
    init_kernel<<<ZB + 11 + 24, 256>>>(out, out_size, P, We, Wu1, Wsk1, Wu2s, Wsk2, Wms1, wr1);
  }
  /* 2: work1 = geom + z-prep + weight conversion */
  work1_kernel<<<625 + 1 + 52, 256>>>(positions, shifts, edge_index, node_z, p_WF, Wms2);
  /* 3 */
  msg1_kernel<<<1024, 256>>>(R1);
  /* 4: stage C = sU2, vU2, grouped s2, e1+e0 — BIG tiles */
  {
    TOps P; tops_init(P);
    tops_add(P, 0, CDIV(NN,TNB),   0, p_A0, p_sU2, NN,   ALPHA_, 0, p_tabU2, 1, 0);
    tops_add(P, 0, CDIV(3*NN,TNB), 1, p_A1, p_vU2, 3*NN, ALPHA_, 0, 0, 0, 0);
    tops_add(P, 1, GTZ_BIG*NE_,    2, p_A0, p_s2,  NN,   ALPHA_, 0, p_tabS2, 0, 0);
    tops_add(P, 2, CDIV(NN*32,512), 0, 0, 0, NN, 0.f, 0, 0, 0, 0);
    tgemm_big_kernel<<<tops_total(P), 512, TG_SMEM>>>(P, node_z, batch, ae);
  }
  /* 5 */
  msg2_kernel<<<1024, 256>>>(R2);
  /* 6: s2 += a*A2@Wms2 — SMALL tiles */
  {
    TOps P; tops_init(P);
    tops_add(P, 0, CDIV(NN,TNS), 12, p_A2, p_s2, NN, ALPHA_, 1, 0, 0, 0);
    tgemm_sm_kernel<<<tops_total(P), 256, TG_SMEM>>>(P, node_z);
  }
  /* 7 */
  mlp_kernel<<<2048, 128>>>(Wmlp, wout, batch);
  /* 8: dA2 = a*ds2@Wms2^T ; grouped dA0 = a*ds2@WF2z^T — SMALL tiles */
  {
    TOps P; tops_init(P);
    tops_add(P, 0, CDIV(NN,TNS), 25, p_ds2, p_dA2, NN, ALPHA_, 0, 0, 0, 0);
    tops_add(P, 1, GTZ_SM*NE_,   15, p_ds2, p_dA0, NN, ALPHA_, 0, 0, 0, 0);
    tgemm_sm_kernel<<<tops_total(P), 256, TG_SMEM>>>(P, node_z);
  }
  /* 9 */
  bwd2_kernel<<<1024, 256>>>(R2);
  /* 10: dA0 += a*(Dsj2@WF1^T + u^T) ; dA1 = a*Dvj@Wfuse^T — SMALL tiles */
  {
    TOps P; tops_init(P);
    tops_add(P, 0, CDIV(NN,TNS),   13, p_Dsj2, p_dA0, NN,   ALPHA_, 1, 0, 0, p_u);
    tops_add(P, 0, CDIV(3*NN,TNS), 14, p_Dvj,  p_dA1, 3*NN, ALPHA_, 0, 0, 0, 0);
    tgemm_sm_kernel<<<tops_total(P), 256, TG_SMEM>>>(P, node_z);
  }
  /* 11 */
  bwd1_kernel<<<1024, 256>>>(R1);
  /* 12: geometry backward + finalize */
  geom_bwd_fin_kernel<<<1025, 256>>>(out + GG + 3*GG, out);
}

// round 14
// speedup vs baseline: 1.0685x; 1.0160x over previous
#include <cuda_runtime.h>
#include <cuda_bf16.h>
#include <math.h>
#include <stdint.h>

#define K 128
#define KK (K*K)
#define NN 10000
#define EE 160000
#define NE_ 10
#define NB_ 8
#define GG 16
#define NK (NN*K)
#define TM 64
#define TNB 256
#define TNS 128
#define GTZ_BIG 40
#define GTZ_SM  79

#define SQ3F 1.7320508075688772f
#define INV_SQ3 0.5773502691896258f
#define PI_F 3.14159265358979323846f
#define CB_F 0.6324555320336759f
#define ALPHA_ (1.0f/16.0f)
#define CDIV(a,b) (((a)+(b)-1)/(b))

/* ---- smem layout for tensor GEMM: W full, A in 64-row buffers ----------- */
#define PITCH_B 272
#define W_H_B 0
#define W_L_B 34816
#define A_H_B 69632
#define A_L_B 87040
#define ROWIDX_B 104448
#define TG_SMEM 105472       /* 103 KB -> 2 CTAs/SM */

__device__ __forceinline__ uint32_t smem_u32(const void* p){
  uint32_t a;
  asm("{ .reg .u64 t; cvta.to.shared.u64 t, %1; cvt.u32.u64 %0, t; }" : "=r"(a) : "l"(p));
  return a;
}
#define LDM4(r, addr) \
  asm volatile("ldmatrix.sync.aligned.m8n8.x4.shared.b16 {%0,%1,%2,%3}, [%4];" \
    : "=r"((r)[0]),"=r"((r)[1]),"=r"((r)[2]),"=r"((r)[3]) : "r"(addr))
#define MMA16816(c, a, b0, b1) \
  asm volatile("mma.sync.aligned.m16n8k16.row.col.f32.bf16.bf16.f32 " \
    "{%0,%1,%2,%3}, {%4,%5,%6,%7}, {%8,%9}, {%0,%1,%2,%3};" \
    : "+f"((c)[0]),"+f"((c)[1]),"+f"((c)[2]),"+f"((c)[3]) \
    : "r"((a)[0]),"r"((a)[1]),"r"((a)[2]),"r"((a)[3]), "r"(b0),"r"(b1))
#define BARSYNC(id, cnt) asm volatile("bar.sync %0, %1;" :: "r"(id), "r"(cnt) : "memory")

__device__ __forceinline__ uint32_t pk_bf2(__nv_bfloat16 a, __nv_bfloat16 b){
  return (uint32_t)__bfloat16_as_ushort(a) | ((uint32_t)__bfloat16_as_ushort(b) << 16);
}

/* ------------------- device scratch (no allocs allowed) ------------------ */
__device__ float g_sU1[NE_*K];
__device__ float g_tabU2[NE_*K];
__device__ float g_tabS2[NE_*K];
__device__ float g_t1[NE_];
__device__ float g_u[K];
__device__ float g_r[EE];
__device__ float g_Y1[EE*3];
__device__ float g_ef[EE*NB_];
__device__ int   g_esnd[EE], g_ercv[EE], g_ezsnd[EE];
__device__ int   g_nact;
__device__ float g_A0[NK];
__device__ float g_A1[3*NK];
__device__ float g_sU2[NK];
__device__ float g_vU2[3*NK];
__device__ float g_A2[NK];
__device__ float g_s2[NK];
__device__ float g_ds2[NK];
__device__ float g_dA2[NK];
__device__ float g_Dsj2[NK];
__device__ float g_Dvj[3*NK];
__device__ float g_dA0[NK];
__device__ float g_dA1[3*NK];
__device__ float g_def[EE*NB_];
__device__ float g_dY1b[EE*3];
__device__ float g_e0[GG], g_e1[GG], g_e2[GG];
__device__ float g_WF[12*KK];
__device__ __nv_bfloat16 g_Bh[26*KK];
__device__ __nv_bfloat16 g_Bl[26*KK];
__device__ int g_zoff[NE_+1], g_zperm[NN];

/* -------- fp32 multi-op GEMM struct (weight precompute) ------------------ */
#define MAXG 12
struct GOps {
  int count;
  int tiles[MAXG];
  const float* A[MAXG];
  const float* B[MAXG];
  float* C[MAXG];
  int M[MAXG];
};

/* ==== init: zero (A0/A1/A2/out/e, NOT Dsj2/Dvj) + tables + weight GEMMs == */
#define ZB 1536
__global__ void __launch_bounds__(256) init_kernel(float* __restrict__ out, int out_size, GOps P,
    const float* __restrict__ We, const float* __restrict__ Wu1, const float* __restrict__ Wsk1,
    const float* __restrict__ Wu2s, const float* __restrict__ Wsk2, const float* __restrict__ Wms1,
    const float* __restrict__ wr1){
  __shared__ char ubuf[32768];
  int b = blockIdx.x;
  int tid = threadIdx.x;
  if (b < ZB){
    int total = 3*NK;
    if (out_size > total) total = out_size;
    for (int i = b*256 + tid; i < total; i += ZB*256){
      if (i < 3*NK) g_A1[i]=0.f;
      if (i < NK){ g_A0[i]=0.f; g_A2[i]=0.f; }
      if (i < out_size) out[i]=0.f;
      if (i < GG){ g_e0[i]=0.f; g_e1[i]=0.f; g_e2[i]=0.f; }
      if (i == 0) g_nact = 0;
    }
    return;
  }
  if (b < ZB + 11){
    int z = b - ZB;
    if (tid >= 128) return;
    int d = tid;
    float* sh  = (float*)ubuf;
    float* red = (float*)(ubuf + 512);
    if (z == NE_){
      float a = 0.f;
      for (int m = 0; m < K; m++) a = fmaf(Wms1[d*K + m], wr1[m], a);
      g_u[d] = a;
      return;
    }
    float a = 0.f, bb = 0.f;
    for (int c = 0; c < K; c++){
      float s = We[z*K + c];
      a  = fmaf(s, Wu1[c*K + d], a);
      bb = fmaf(s, Wsk1[(z*K + c)*K + d], bb);
    }
    g_sU1[z*K + d] = a;
    sh[d] = bb;
    __syncthreads();
    float t2 = 0.f, t3 = 0.f;
    for (int c = 0; c < K; c++){
      float s = sh[c];
      t2 = fmaf(s, Wu2s[c*K + d], t2);
      t3 = fmaf(s, Wsk2[(z*K + c)*K + d], t3);
    }
    g_tabU2[z*K + d] = t2;
    g_tabS2[z*K + d] = t3;
    float p = sh[d]*wr1[d];
    #pragma unroll
    for (int o = 16; o; o >>= 1) p += __shfl_down_sync(0xffffffffu, p, o);
    if ((d & 31) == 0) red[d >> 5] = p;
    __syncthreads();
    if (d == 0) g_t1[z] = red[0] + red[1] + red[2] + red[3];
    return;
  }
  b -= (ZB + 11);
  int op = 0;
  while (b >= P.tiles[op]){ b -= P.tiles[op]; op++; }
  typedef float (*AsT)[K];
  AsT As = (AsT)ubuf;
  int d = tid & 127;
  int g = tid >> 7;
  int M = P.M[op];
  const float* __restrict__ A = P.A[op];
  int base0 = b*TM;
  #pragma unroll 4
  for (int i = 0; i < 32; i++){
    int r = g*32 + i;
    As[r][d] = (base0 + r < M) ? A[(base0 + r)*K + d] : 0.f;
  }
  __syncthreads();
  const float* __restrict__ B = P.B[op];
  float acc[32];
  #pragma unroll
  for (int i = 0; i < 32; i++) acc[i] = 0.f;
  for (int c = 0; c < K; c += 4){
    float b0=B[c*K+d], b1=B[(c+1)*K+d], b2=B[(c+2)*K+d], b3=B[(c+3)*K+d];
    #pragma unroll
    for (int i = 0; i < 32; i++){
      float4 av = *(const float4*)&As[g*32 + i][c];
      acc[i] = fmaf(av.x,b0,fmaf(av.y,b1,fmaf(av.z,b2,fmaf(av.w,b3,acc[i]))));
    }
  }
  float* __restrict__ C = P.C[op];
  int base = base0 + g*32;
  for (int i = 0; i < 32; i++){
    int n = base + i;
    if (n >= M) break;
    C[n*K + d] = acc[i];
  }
}

/* ============ work1: geom + conv (split bf16) + z count/scan/scatter ===== */
__global__ void __launch_bounds__(256) work1_kernel(const float* __restrict__ pos,
    const float* __restrict__ shifts, const int* __restrict__ ei, const int* __restrict__ nz,
    const float* __restrict__ WF, const float* __restrict__ Wms2){
  int b = blockIdx.x;
  if (b < 625){
    int e = b*256 + threadIdx.x;
    if (e >= EE) return;
    int s = ei[e], rc = ei[EE + e];
    float vx = pos[rc*3+0] - pos[s*3+0] + shifts[e*3+0];
    float vy = pos[rc*3+1] - pos[s*3+1] + shifts[e*3+1];
    float vz = pos[rc*3+2] - pos[s*3+2] + shifts[e*3+2];
    float rr = sqrtf(vx*vx + vy*vy + vz*vz + 1e-12f);
    if (rr < 5.0f){
      int i = atomicAdd(&g_nact, 1);
      g_esnd[i]=s; g_ercv[i]=rc; g_ezsnd[i]=nz[s];
      g_r[i]=rr;
      float inv = SQ3F / rr;
      g_Y1[i*3+0]=vx*inv; g_Y1[i*3+1]=vy*inv; g_Y1[i*3+2]=vz*inv;
      float x = rr*0.2f;
      float x2=x*x, x4=x2*x2, x5=x4*x;
      float fc = 1.f + x5*(-21.f + x*(35.f - 15.f*x));
      float invr = 1.f/rr;
      float cf = CB_F*invr*fc;
      float s1_, c1_;
      sincosf(PI_F*0.2f*rr, &s1_, &c1_);
      float sb = s1_, cb = c1_;
      #pragma unroll
      for (int bb = 0; bb < NB_; bb++){
        g_ef[i*NB_ + bb] = cf*sb;
        float ns = sb*c1_ + cb*s1_;
        float nc = cb*c1_ - sb*s1_;
        sb = ns; cb = nc;
      }
    }
    return;
  }
  if (b == 625){
    __shared__ int cnt[NE_];
    __shared__ int off[NE_+1];
    __shared__ int fill[NE_];
    int tid = threadIdx.x;
    if (tid < NE_) cnt[tid] = 0;
    __syncthreads();
    for (int n = tid; n < NN; n += 256) atomicAdd(&cnt[nz[n]], 1);
    __syncthreads();
    if (tid == 0){
      int acc = 0;
      for (int z = 0; z < NE_; z++){ off[z] = acc; g_zoff[z] = acc; acc += cnt[z]; }
      off[NE_] = acc; g_zoff[NE_] = acc;
    }
    __syncthreads();
    if (tid < NE_) fill[tid] = off[tid];
    __syncthreads();
    for (int n = tid; n < NN; n += 256){
      int p = atomicAdd(&fill[nz[n]], 1);
      g_zperm[p] = n;
    }
    return;
  }
  int bb = b - 626;
  for (int id = bb*256 + threadIdx.x; id < 26*KK; id += 52*256){
    int j = id >> 14;
    int rem = id & (KK-1);
    int n = rem >> 7, k = rem & 127;
    const float* W; int trans;
    if (j < 12){ W = WF + j*KK; trans = 0; }
    else if (j == 12){ W = Wms2; trans = 0; }
    else if (j < 25){ W = WF + (j-13)*KK; trans = 1; }
    else { W = Wms2; trans = 1; }
    float v = trans ? W[n*K + k] : W[k*K + n];
    __nv_bfloat16 h = __float2bfloat16(v);
    __nv_bfloat16 l = __float2bfloat16(v - __bfloat162float(h));
    g_Bh[(size_t)j*KK + rem] = h;
    g_Bl[(size_t)j*KK + rem] = l;
  }
}

/* ---------- big tensor GEMM core (512 thr, per-group barriers) ----------- */
__device__ __forceinline__ void tgemm_core_big(char* smc, const int* __restrict__ rowIdx,
    const float* __restrict__ A, float* __restrict__ C, int bidx, float alpha, int accum,
    const float* __restrict__ tab, const int* __restrict__ nz, const float* __restrict__ bias){
  int tid = threadIdx.x;
  {
    const uint4* gh = (const uint4*)(g_Bh + (size_t)bidx*KK);
    const uint4* gl = (const uint4*)(g_Bl + (size_t)bidx*KK);
    #pragma unroll
    for (int i = 0; i < 4; i++){
      int idx = tid + i*512;
      int row = idx >> 4, q = idx & 15;
      uint4 vh = gh[idx], vl = gl[idx];
      *(uint4*)(smc + W_H_B + row*PITCH_B + q*16) = vh;
      *(uint4*)(smc + W_L_B + row*PITCH_B + q*16) = vl;
    }
  }
  __syncthreads();

  int warp = tid >> 5, lane = tid & 31;
  int grp = warp & 3;
  int mrow0 = grp*16;
  int ncol0 = (warp >> 2)*32;
  int gtid = (warp >> 2)*32 + lane;
  int barid = grp + 1;
  int quad = lane >> 3, rin = lane & 7;
  uint32_t smbase = smem_u32(smc);
  uint32_t aoff = (uint32_t)(rin + (quad & 1)*8)*PITCH_B + (uint32_t)((quad >> 1)*8)*2;
  uint32_t ahb = smbase + A_H_B + (uint32_t)mrow0*PITCH_B + aoff;
  uint32_t alb = smbase + A_L_B + (uint32_t)mrow0*PITCH_B + aoff;
  uint32_t boff = (uint32_t)(rin + (quad >> 1)*8)*PITCH_B + (uint32_t)((quad & 1)*8)*2;
  uint32_t whb = smbase + W_H_B + (uint32_t)ncol0*PITCH_B + boff;
  uint32_t wlb = smbase + W_L_B + (uint32_t)ncol0*PITCH_B + boff;
  int g = lane >> 2, tg = lane & 3;

  #pragma unroll
  for (int qtr = 0; qtr < 4; qtr++){
    #pragma unroll
    for (int i = 0; i < 4; i++){
      int idx = gtid + i*128;
      int row16 = idx >> 5, c4 = (idx & 31)*4;
      int row = mrow0 + row16;
      int gr = rowIdx[qtr*64 + row];
      float4 v = (gr >= 0) ? *(const float4*)&A[(size_t)gr*K + c4] : make_float4(0.f,0.f,0.f,0.f);
      __nv_bfloat16 h0=__float2bfloat16(v.x), h1=__float2bfloat16(v.y);
      __nv_bfloat16 h2=__float2bfloat16(v.z), h3=__float2bfloat16(v.w);
      __nv_bfloat16 l0=__float2bfloat16(v.x-__bfloat162float(h0));
      __nv_bfloat16 l1=__float2bfloat16(v.y-__bfloat162float(h1));
      __nv_bfloat16 l2=__float2bfloat16(v.z-__bfloat162float(h2));
      __nv_bfloat16 l3=__float2bfloat16(v.w-__bfloat162float(h3));
      *(uint2*)(smc + A_H_B + row*PITCH_B + c4*2) = make_uint2(pk_bf2(h0,h1), pk_bf2(h2,h3));
      *(uint2*)(smc + A_L_B + row*PITCH_B + c4*2) = make_uint2(pk_bf2(l0,l1), pk_bf2(l2,l3));
    }
    BARSYNC(barid, 128);

    float c[4][4];
    #pragma unroll
    for (int nt = 0; nt < 4; nt++){ c[nt][0]=0.f; c[nt][1]=0.f; c[nt][2]=0.f; c[nt][3]=0.f; }

    #pragma unroll
    for (int kt = 0; kt < 8; kt++){
      uint32_t kb = (uint32_t)kt*32;
      uint32_t ah[4], al[4];
      LDM4(ah, ahb + kb);
      LDM4(al, alb + kb);
      #pragma unroll
      for (int s = 0; s < 2; s++){
        uint32_t bh[4], bl[4];
        LDM4(bh, whb + kb + (uint32_t)s*16*PITCH_B);
        LDM4(bl, wlb + kb + (uint32_t)s*16*PITCH_B);
        MMA16816(c[s*2],   ah, bh[0], bh[1]);
        MMA16816(c[s*2],   ah, bl[0], bl[1]);
        MMA16816(c[s*2],   al, bh[0], bh[1]);
        MMA16816(c[s*2+1], ah, bh[2], bh[3]);
        MMA16816(c[s*2+1], ah, bl[2], bl[3]);
        MMA16816(c[s*2+1], al, bh[2], bh[3]);
      }
    }

    #pragma unroll
    for (int hr = 0; hr < 2; hr++){
      int lrow = mrow0 + g + hr*8;
      int grow = rowIdx[qtr*64 + lrow];
      if (grow >= 0){
        const float* trow = 0;
        if (tab) trow = nz ? tab + (size_t)nz[grow]*K : tab;
        #pragma unroll
        for (int nt = 0; nt < 4; nt++){
          int col = ncol0 + nt*8 + tg*2;
          float v0 = alpha*c[nt][hr*2+0];
          float v1 = alpha*c[nt][hr*2+1];
          if (trow){ v0 += trow[col]; v1 += trow[col+1]; }
          if (bias){ v0 += alpha*bias[col]; v1 += alpha*bias[col+1]; }
          if (accum){ float2 o = *(const float2*)&C[(size_t)grow*K + col]; v0 += o.x; v1 += o.y; }
          *(float2*)&C[(size_t)grow*K + col] = make_float2(v0, v1);
        }
      }
    }
    if (qtr < 3) BARSYNC(barid, 128);
  }
}

/* ---------- small tensor GEMM core (256 thr, per-group barriers) --------- */
__device__ __forceinline__ void tgemm_core_sm(char* smc, const int* __restrict__ rowIdx,
    const float* __restrict__ A, float* __restrict__ C, int bidx, float alpha, int accum,
    const float* __restrict__ tab, const int* __restrict__ nz, const float* __restrict__ bias){
  int tid = threadIdx.x;
  {
    const uint4* gh = (const uint4*)(g_Bh + (size_t)bidx*KK);
    const uint4* gl = (const uint4*)(g_Bl + (size_t)bidx*KK);
    #pragma unroll
    for (int i = 0; i < 8; i++){
      int idx = tid + i*256;
      int row = idx >> 4, q = idx & 15;
      uint4 vh = gh[idx], vl = gl[idx];
      *(uint4*)(smc + W_H_B + row*PITCH_B + q*16) = vh;
      *(uint4*)(smc + W_L_B + row*PITCH_B + q*16) = vl;
    }
  }
  __syncthreads();

  int warp = tid >> 5, lane = tid & 31;
  int grp = warp & 3;
  int mrow0 = grp*16;
  int ncol0 = (warp >> 2)*64;
  int gtid = (warp >> 2)*32 + lane;
  int barid = grp + 1;
  int quad = lane >> 3, rin = lane & 7;
  uint32_t smbase = smem_u32(smc);
  uint32_t aoff = (uint32_t)(rin + (quad & 1)*8)*PITCH_B + (uint32_t)((quad >> 1)*8)*2;
  uint32_t ahb = smbase + A_H_B + (uint32_t)mrow0*PITCH_B + aoff;
  uint32_t alb = smbase + A_L_B + (uint32_t)mrow0*PITCH_B + aoff;
  uint32_t boff = (uint32_t)(rin + (quad >> 1)*8)*PITCH_B + (uint32_t)((quad & 1)*8)*2;
  uint32_t whb = smbase + W_H_B + (uint32_t)ncol0*PITCH_B + boff;
  uint32_t wlb = smbase + W_L_B + (uint32_t)ncol0*PITCH_B + boff;
  int g = lane >> 2, tg = lane & 3;

  #pragma unroll
  for (int half = 0; half < 2; half++){
    #pragma unroll
    for (int i = 0; i < 8; i++){
      int idx = gtid + i*64;
      int row16 = idx >> 5, c4 = (idx & 31)*4;
      int row = mrow0 + row16;
      int gr = rowIdx[half*64 + row];
      float4 v = (gr >= 0) ? *(const float4*)&A[(size_t)gr*K + c4] : make_float4(0.f,0.f,0.f,0.f);
      __nv_bfloat16 h0=__float2bfloat16(v.x), h1=__float2bfloat16(v.y);
      __nv_bfloat16 h2=__float2bfloat16(v.z), h3=__float2bfloat16(v.w);
      __nv_bfloat16 l0=__float2bfloat16(v.x-__bfloat162float(h0));
      __nv_bfloat16 l1=__float2bfloat16(v.y-__bfloat162float(h1));
      __nv_bfloat16 l2=__float2bfloat16(v.z-__bfloat162float(h2));
      __nv_bfloat16 l3=__float2bfloat16(v.w-__bfloat162float(h3));
      *(uint2*)(smc + A_H_B + row*PITCH_B + c4*2) = make_uint2(pk_bf2(h0,h1), pk_bf2(h2,h3));
      *(uint2*)(smc + A_L_B + row*PITCH_B + c4*2) = make_uint2(pk_bf2(l0,l1), pk_bf2(l2,l3));
    }
    BARSYNC(barid, 64);

    float c[8][4];
    #pragma unroll
    for (int nt = 0; nt < 8; nt++){ c[nt][0]=0.f; c[nt][1]=0.f; c[nt][2]=0.f; c[nt][3]=0.f; }

    #pragma unroll
    for (int kt = 0; kt < 8; kt++){
      uint32_t kb = (uint32_t)kt*32;
      uint32_t ah[4], al[4];
      LDM4(ah, ahb + kb);
      LDM4(al, alb + kb);
      #pragma unroll
      for (int nt2 = 0; nt2 < 4; nt2++){
        uint32_t bh[4], bl[4];
        LDM4(bh, whb + kb + (uint32_t)nt2*16*PITCH_B);
        LDM4(bl, wlb + kb + (uint32_t)nt2*16*PITCH_B);
        MMA16816(c[nt2*2],   ah, bh[0], bh[1]);
        MMA16816(c[nt2*2],   ah, bl[0], bl[1]);
        MMA16816(c[nt2*2],   al, bh[0], bh[1]);
        MMA16816(c[nt2*2+1], ah, bh[2], bh[3]);
        MMA16816(c[nt2*2+1], ah, bl[2], bl[3]);
        MMA16816(c[nt2*2+1], al, bh[2], bh[3]);
      }
    }

    #pragma unroll
    for (int hr = 0; hr < 2; hr++){
      int lrow = mrow0 + g + hr*8;
      int grow = rowIdx[half*64 + lrow];
      if (grow >= 0){
        const float* trow = 0;
        if (tab) trow = nz ? tab + (size_t)nz[grow]*K : tab;
        #pragma unroll
        for (int nt = 0; nt < 8; nt++){
          int col = ncol0 + nt*8 + tg*2;
          float v0 = alpha*c[nt][hr*2+0];
          float v1 = alpha*c[nt][hr*2+1];
          if (trow){ v0 += trow[col]; v1 += trow[col+1]; }
          if (bias){ v0 += alpha*bias[col]; v1 += alpha*bias[col+1]; }
          if (accum){ float2 o = *(const float2*)&C[(size_t)grow*K + col]; v0 += o.x; v1 += o.y; }
          *(float2*)&C[(size_t)grow*K + col] = make_float2(v0, v1);
        }
      }
    }
    if (half < 1) BARSYNC(barid, 64);
  }
}

/* ------ multi-op tensor GEMM: kind 0=linear 1=grouped 2=e1 --------------- */
#define MAXOPS 4
struct TOps {
  int count;
  int tiles[MAXOPS];
  int kind[MAXOPS];
  int bidx[MAXOPS];
  const float* A[MAXOPS];
  float* C[MAXOPS];
  const float* table[MAXOPS];
  const float* bias[MAXOPS];
  int M[MAXOPS];
  int accum[MAXOPS];
  int useNz[MAXOPS];
  float alpha[MAXOPS];
};

__global__ void __launch_bounds__(512) tgemm_big_kernel(TOps P, const int* __restrict__ node_z,
    const int* __restrict__ batch, const float* __restrict__ ae){
  int b = blockIdx.x, op = 0;
  while (b >= P.tiles[op]){ b -= P.tiles[op]; op++; }
  int kind = P.kind[op];
  if (kind == 2){
    int gt = b*512 + threadIdx.x;
    int n = gt >> 5, lane = gt & 31;
    if (n >= NN) return;
    float acc = 0.f;
    #pragma unroll
    for (int c = lane; c < K; c += 32) acc = fmaf(g_A0[n*K + c], g_u[c], acc);
    #pragma unroll
    for (int o = 16; o; o >>= 1) acc += __shfl_down_sync(0xffffffffu, acc, o);
    if (lane == 0){
      int zz = node_z[n];
      atomicAdd(&g_e1[batch[n]], ALPHA_*acc + g_t1[zz]);
      atomicAdd(&g_e0[batch[n]], ae[zz]);
    }
    return;
  }
  extern __shared__ char smc[];
  int* rowIdx = (int*)(smc + ROWIDX_B);
  int bidx = P.bidx[op];
  const float* tab = P.table[op];
  const int* nz = 0;
  if (kind == 0){
    int base = b*TNB, M = P.M[op];
    if (threadIdx.x < TNB) rowIdx[threadIdx.x] = (base + (int)threadIdx.x < M) ? base + threadIdx.x : -1;
    nz = P.useNz[op] ? node_z : 0;
  } else {
    int z = b / GTZ_BIG;
    int m0 = (b - z*GTZ_BIG)*TNB;
    int start = g_zoff[z], cnt = g_zoff[z+1] - start;
    if (m0 >= cnt) return;
    if (threadIdx.x < TNB) rowIdx[threadIdx.x] = (m0 + (int)threadIdx.x < cnt) ? g_zperm[start + m0 + threadIdx.x] : -1;
    bidx += z;
    if (tab) tab = tab + (size_t)z*K;
  }
  __syncthreads();
  tgemm_core_big(smc, rowIdx, P.A[op], P.C[op], bidx, P.alpha[op], P.accum[op], tab, nz, P.bias[op]);
}

__global__ void __launch_bounds__(256) tgemm_sm_kernel(TOps P, const int* __restrict__ node_z){
  int b = blockIdx.x, op = 0;
  while (b >= P.tiles[op]){ b -= P.tiles[op]; op++; }
  int kind = P.kind[op];
  extern __shared__ char smc[];
  int* rowIdx = (int*)(smc + ROWIDX_B);
  int bidx = P.bidx[op];
  const float* tab = P.table[op];
  const int* nz = 0;
  if (kind == 0){
    int base = b*TNS, M = P.M[op];
    if (threadIdx.x < TNS) rowIdx[threadIdx.x] = (base + (int)threadIdx.x < M) ? base + threadIdx.x : -1;
    nz = P.useNz[op] ? node_z : 0;
  } else {
    int z = b / GTZ_SM;
    int m0 = (b - z*GTZ_SM)*TNS;
    int start = g_zoff[z], cnt = g_zoff[z+1] - start;
    if (m0 >= cnt) return;
    if (threadIdx.x < TNS) rowIdx[threadIdx.x] = (m0 + (int)threadIdx.x < cnt) ? g_zperm[start + m0 + threadIdx.x] : -1;
    bidx += z;
    if (tab) tab = tab + (size_t)z*K;
  }
  __syncthreads();
  tgemm_core_sm(smc, rowIdx, P.A[op], P.C[op], bidx, P.alpha[op], P.accum[op], tab, nz, P.bias[op]);
}

/* --------------- layer-1 messages: 2 edges per 256-thread block ---------- */
__global__ void __launch_bounds__(256) msg1_kernel(const float* __restrict__ R1){
  int c = threadIdx.x & 127;
  int sub = threadIdx.x >> 7;
  float r1a[NB_], r1b[NB_];
  #pragma unroll
  for (int b = 0; b < NB_; b++){ r1a[b]=R1[b*256 + c]; r1b[b]=R1[b*256 + 128 + c]; }
  int nact = g_nact;
  for (int e = blockIdx.x*2 + sub; e < nact; e += gridDim.x*2){
    int rcv = g_ercv[e], zs = g_ezsnd[e];
    float y0=g_Y1[e*3+0], y1=g_Y1[e*3+1], y2=g_Y1[e*3+2];
    float w0=0.f, w1=0.f;
    #pragma unroll
    for (int b = 0; b < NB_; b++){ float efb=g_ef[e*NB_+b]; w0=fmaf(efb,r1a[b],w0); w1=fmaf(efb,r1b[b],w1); }
    float sj = g_sU1[zs*K + c];
    atomicAdd(&g_A0[rcv*K + c], w0*sj);
    float t = w1*sj;
    atomicAdd(&g_A1[rcv*K + c],        t*y0);
    atomicAdd(&g_A1[NK + rcv*K + c],   t*y1);
    atomicAdd(&g_A1[2*NK + rcv*K + c], t*y2);
  }
}

/* ------ layer-2 messages: 2 edges per block + Dsj2/Dvj zero blocks ------- */
#define MSG2_EB 1024
#define MSG2_ZB 512
__global__ void __launch_bounds__(256) msg2_kernel(const float* __restrict__ R2){
  if (blockIdx.x >= MSG2_EB){
    /* zero Dsj2 (NK) + Dvj (3NK) ahead of bwd2 */
    int zb = blockIdx.x - MSG2_EB;
    float4 z4 = make_float4(0.f,0.f,0.f,0.f);
    for (int i = zb*256 + threadIdx.x; i < NK/4; i += MSG2_ZB*256)
      ((float4*)g_Dsj2)[i] = z4;
    for (int i = zb*256 + threadIdx.x; i < 3*NK/4; i += MSG2_ZB*256)
      ((float4*)g_Dvj)[i] = z4;
    return;
  }
  int c = threadIdx.x & 127;
  int sub = threadIdx.x >> 7;
  float r2a[NB_], r2b[NB_];
  #pragma unroll
  for (int b = 0; b < NB_; b++){ r2a[b]=R2[b*512 + c]; r2b[b]=R2[b*512 + 128 + c]; }
  int nact = g_nact;
  for (int e = blockIdx.x*2 + sub; e < nact; e += MSG2_EB*2){
    int snd = g_esnd[e], rcv = g_ercv[e];
    float y0=g_Y1[e*3+0], y1=g_Y1[e*3+1], y2=g_Y1[e*3+2];
    float w00=0.f, w110=0.f;
    #pragma unroll
    for (int b = 0; b < NB_; b++){ float efb=g_ef[e*NB_+b]; w00=fmaf(efb,r2a[b],w00); w110=fmaf(efb,r2b[b],w110); }
    float sj = g_sU2[snd*K + c];
    float vj0=g_vU2[snd*K+c], vj1=g_vU2[NK+snd*K+c], vj2=g_vU2[2*NK+snd*K+c];
    float dot = vj0*y0 + vj1*y1 + vj2*y2;
    float m = fmaf(w00, sj, w110*dot*INV_SQ3);
    atomicAdd(&g_A2[rcv*K + c], m);
  }
}

/* ----------------------- MLP head: e2 + ds2 ------------------------------ */
__global__ void __launch_bounds__(128) mlp_kernel(const float* __restrict__ Wmlp,
    const float* __restrict__ wout, const int* __restrict__ batch){
  __shared__ float srow[K];
  __shared__ float gj[16];
  __shared__ float hpart[16];
  int tid = threadIdx.x;
  for (int n = blockIdx.x; n < NN; n += gridDim.x){
    srow[tid] = g_s2[n*K + tid];
    __syncthreads();
    if (tid < 16){
      float uu = 0.f;
      for (int c = 0; c < K; c++) uu = fmaf(srow[c], Wmlp[c*16 + tid], uu);
      float sig = 1.f/(1.f + __expf(-uu));
      hpart[tid] = uu*sig*wout[tid];
      gj[tid] = wout[tid]*sig*(1.f + uu*(1.f - sig));
    }
    __syncthreads();
    if (tid == 0){
      float s = 0.f;
      #pragma unroll
      for (int j = 0; j < 16; j++) s += hpart[j];
      atomicAdd(&g_e2[batch[n]], s);
    }
    float ds = 0.f;
    #pragma unroll
    for (int j = 0; j < 16; j++) ds = fmaf(Wmlp[tid*16 + j], gj[j], ds);
    g_ds2[n*K + tid] = ds;
    __syncthreads();
  }
}

/* --------------- backward layer-2: 2 edges per 256-thread block ---------- */
__device__ __forceinline__ float warpsum(float v){
  #pragma unroll
  for (int o = 16; o; o >>= 1) v += __shfl_down_sync(0xffffffffu, v, o);
  return v;
}

__global__ void __launch_bounds__(256) bwd2_kernel(const float* __restrict__ R2){
  __shared__ float red[2][4][11];
  int tid = threadIdx.x;
  int c = tid & 127;
  int sub = tid >> 7;
  int warp = (tid >> 5) & 3, lane = tid & 31;
  float r2a[NB_], r2b[NB_];
  #pragma unroll
  for (int b = 0; b < NB_; b++){ r2a[b]=R2[b*512 + c]; r2b[b]=R2[b*512 + 128 + c]; }
  int nact = g_nact;
  for (int base = blockIdx.x*2; base < nact; base += gridDim.x*2){
    int e = base + sub;
    bool act = (e < nact);
    float y0=0.f, y1=0.f, y2=0.f, dm=0.f, sj=0.f, vj0=0.f, vj1=0.f, vj2=0.f;
    float w00=0.f, w110=0.f;
    int snd=0;
    if (act){
      snd = g_esnd[e];
      int rcv = g_ercv[e];
      y0=g_Y1[e*3+0]; y1=g_Y1[e*3+1]; y2=g_Y1[e*3+2];
      #pragma unroll
      for (int b = 0; b < NB_; b++){ float efb=g_ef[e*NB_+b]; w00=fmaf(efb,r2a[b],w00); w110=fmaf(efb,r2b[b],w110); }
      dm = g_dA2[rcv*K + c];
      sj = g_sU2[snd*K + c];
      vj0=g_vU2[snd*K+c]; vj1=g_vU2[NK+snd*K+c]; vj2=g_vU2[2*NK+snd*K+c];
    }
    float dot = vj0*y0 + vj1*y1 + vj2*y2;
    float ddot = dm*w110*INV_SQ3;
    if (act){
      atomicAdd(&g_Dsj2[snd*K + c], dm*w00);
      atomicAdd(&g_Dvj[snd*K + c],        ddot*y0);
      atomicAdd(&g_Dvj[NK + snd*K + c],   ddot*y1);
      atomicAdd(&g_Dvj[2*NK + snd*K + c], ddot*y2);
    }
    float p[11];
    float dw00 = dm*sj, dw110 = dm*dot*INV_SQ3;
    #pragma unroll
    for (int b = 0; b < NB_; b++) p[b] = fmaf(dw00, r2a[b], dw110*r2b[b]);
    p[8] = ddot*vj0; p[9] = ddot*vj1; p[10] = ddot*vj2;
    #pragma unroll
    for (int k = 0; k < 11; k++){
      float v = warpsum(p[k]);
      if (lane == 0) red[sub][warp][k] = v;
    }
    __syncthreads();
    if (c < 11 && act){
      float v = red[sub][0][c] + red[sub][1][c] + red[sub][2][c] + red[sub][3][c];
      if (c < 8) g_def[e*NB_ + c] = v;
      else       g_dY1b[e*3 + (c-8)] = v;
    }
    __syncthreads();
  }
}

/* --- backward layer-1 + fused geometry backward + forces + finalize ------ */
__global__ void __launch_bounds__(256) bwd1_kernel(const float* __restrict__ R1,
    float* __restrict__ F, float* __restrict__ out){
  if (blockIdx.x == gridDim.x - 1){
    int g = threadIdx.x;
    if (g < GG){
      float a = g_e0[g], b = g_e1[g], c = g_e2[g];
      out[g] = a + b + c;
      out[GG + g*3 + 0] = a;
      out[GG + g*3 + 1] = b;
      out[GG + g*3 + 2] = c;
    }
    return;
  }
  __shared__ float red[2][4][11];
  int tid = threadIdx.x;
  int c = tid & 127;
  int sub = tid >> 7;
  int warp = (tid >> 5) & 3, lane = tid & 31;
  float r1a[NB_], r1b[NB_];
  #pragma unroll
  for (int b = 0; b < NB_; b++){ r1a[b]=R1[b*256 + c]; r1b[b]=R1[b*256 + 128 + c]; }
  int nact = g_nact;
  int nblocks = gridDim.x - 1;
  for (int base = blockIdx.x*2; base < nact; base += nblocks*2){
    int e = base + sub;
    bool act = (e < nact);
    float y0=0.f, y1=0.f, y2=0.f;
    float w1=0.f, dm0=0.f, dm10=0.f, dm11=0.f, dm12=0.f, sj=0.f;
    if (act){
      int rcv = g_ercv[e], zs = g_ezsnd[e];
      y0=g_Y1[e*3+0]; y1=g_Y1[e*3+1]; y2=g_Y1[e*3+2];
      #pragma unroll
      for (int b = 0; b < NB_; b++){ float efb=g_ef[e*NB_+b]; w1 = fmaf(efb, r1b[b], w1); }
      dm0 = g_dA0[rcv*K + c];
      dm10 = g_dA1[rcv*K + c];
      dm11 = g_dA1[NK + rcv*K + c];
      dm12 = g_dA1[2*NK + rcv*K + c];
      sj = g_sU1[zs*K + c];
    }
    float dw0 = dm0*sj;
    float t = dm10*y0 + dm11*y1 + dm12*y2;
    float dw1 = t*sj;
    float p[11];
    #pragma unroll
    for (int b = 0; b < NB_; b++) p[b] = fmaf(dw0, r1a[b], dw1*r1b[b]);
    float ws = w1*sj;
    p[8] = dm10*ws; p[9] = dm11*ws; p[10] = dm12*ws;
    #pragma unroll
    for (int k = 0; k < 11; k++){
      float v = warpsum(p[k]);
      if (lane == 0) red[sub][warp][k] = v;
    }
    __syncthreads();
    if (c == 0 && act){
      /* total def/dY1 = bwd2 partial (gmem) + layer-1 partial (smem) */
      float def_t[NB_], dY[3];
      #pragma unroll
      for (int k = 0; k < NB_; k++)
        def_t[k] = g_def[e*NB_ + k] + red[sub][0][k] + red[sub][1][k] + red[sub][2][k] + red[sub][3][k];
      #pragma unroll
      for (int j = 0; j < 3; j++)
        dY[j] = g_dY1b[e*3 + j] + red[sub][0][8+j] + red[sub][1][8+j] + red[sub][2][8+j] + red[sub][3][8+j];
      /* geometry backward (inlined) */
      float rr = g_r[e];
      float yy0=g_Y1[e*3+0], yy1=g_Y1[e*3+1], yy2=g_Y1[e*3+2];
      float v0 = yy0*rr*INV_SQ3, v1 = yy1*rr*INV_SQ3, v2 = yy2*rr*INV_SQ3;
      float x = rr*0.2f;
      float x2=x*x, x4=x2*x2, x5=x4*x;
      float fc = 1.f + x5*(-21.f + x*(35.f - 15.f*x));
      float omx = 1.f - x;
      float dfcdr = -21.f*x4*omx*omx;
      float invr = 1.f/rr;
      float s1_, c1_;
      sincosf(PI_F*0.2f*rr, &s1_, &c1_);
      float sb = s1_, cb = c1_;
      float dr = 0.f;
      #pragma unroll
      for (int b = 0; b < NB_; b++){
        float a = (float)(b+1)*(PI_F*0.2f);
        float debdr = CB_F*((a*cb*rr - sb)*invr*invr*fc + sb*invr*dfcdr);
        dr = fmaf(def_t[b], debdr, dr);
        float ns = sb*c1_ + cb*s1_;
        float nc = cb*c1_ - sb*s1_;
        sb = ns; cb = nc;
      }
      float vd = v0*dY[0] + v1*dY[1] + v2*dY[2];
      float c1c = SQ3F*invr;
      float c2c = SQ3F*vd*invr*invr*invr;
      float dv0 = dr*v0*invr + c1c*dY[0] - c2c*v0;
      float dv1 = dr*v1*invr + c1c*dY[1] - c2c*v1;
      float dv2 = dr*v2*invr + c1c*dY[2] - c2c*v2;
      int snd = g_esnd[e], rcv = g_ercv[e];
      atomicAdd(&F[snd*3+0],  dv0); atomicAdd(&F[snd*3+1],  dv1); atomicAdd(&F[snd*3+2],  dv2);
      atomicAdd(&F[rcv*3+0], -dv0); atomicAdd(&F[rcv*3+1], -dv1); atomicAdd(&F[rcv*3+2], -dv2);
    }
    __syncthreads();
  }
}

/* ------------------------------ host helpers ----------------------------- */
static void tops_init(TOps& P){ P.count = 0; }
static void tops_add(TOps& P, int kind, int tiles, int bidx, const float* A, float* C,
                     int M, float alpha, int accum, const float* table, int useNz,
                     const float* bias){
  int i = P.count++;
  P.kind[i]=kind; P.tiles[i]=tiles; P.bidx[i]=bidx; P.A[i]=A; P.C[i]=C; P.M[i]=M;
  P.alpha[i]=alpha; P.accum[i]=accum; P.table[i]=table; P.useNz[i]=useNz; P.bias[i]=bias;
}
static int tops_total(const TOps& P){
  int t = 0; for (int i = 0; i < P.count; i++) t += P.tiles[i];
  return t;
}

/* ------------------------------ launch ----------------------------------- */
extern "C" void kernel_launch(void* const* d_in, const int* in_sizes, int n_in,
                              void* d_out, int out_size){
  const float *positions, *shifts, *ae, *We, *R1, *Wu1, *Wms1, *Wmv1, *Wsk1, *wr1;
  const float *R2, *Wu2s, *Wu2v, *Wms2, *Wsk2, *Wmlp, *wout;
  const int *edge_index, *node_z, *batch;

  if (in_sizes[2] == 2*EE){  /* setup_inputs dict order */
    positions=(const float*)d_in[0]; shifts=(const float*)d_in[1];
    edge_index=(const int*)d_in[2]; node_z=(const int*)d_in[3]; batch=(const int*)d_in[4];
    ae=(const float*)d_in[5]; We=(const float*)d_in[6]; R1=(const float*)d_in[7];
    Wu1=(const float*)d_in[8]; Wms1=(const float*)d_in[9]; Wmv1=(const float*)d_in[10];
    Wsk1=(const float*)d_in[11]; wr1=(const float*)d_in[12]; R2=(const float*)d_in[13];
    Wu2s=(const float*)d_in[14]; Wu2v=(const float*)d_in[15]; Wms2=(const float*)d_in[16];
    Wsk2=(const float*)d_in[17]; Wmlp=(const float*)d_in[18]; wout=(const float*)d_in[19];
  } else {                   /* reference signature order */
    positions=(const float*)d_in[0]; shifts=(const float*)d_in[1];
    ae=(const float*)d_in[2]; We=(const float*)d_in[3]; R1=(const float*)d_in[4];
    Wu1=(const float*)d_in[5]; Wms1=(const float*)d_in[6]; Wmv1=(const float*)d_in[7];
    Wsk1=(const float*)d_in[8]; wr1=(const float*)d_in[9]; R2=(const float*)d_in[10];
    Wu2s=(const float*)d_in[11]; Wu2v=(const float*)d_in[12]; Wms2=(const float*)d_in[13];
    Wsk2=(const float*)d_in[14]; Wmlp=(const float*)d_in[15]; wout=(const float*)d_in[16];
    edge_index=(const int*)d_in[17]; node_z=(const int*)d_in[18]; batch=(const int*)d_in[19];
  }
  float* out = (float*)d_out;

  float *p_A0,*p_A1,*p_sU2,*p_vU2,*p_A2,*p_s2,*p_ds2,*p_dA2,*p_Dsj2,*p_Dvj,*p_dA0,*p_dA1;
  float *p_WF,*p_tabU2,*p_tabS2,*p_u;
  cudaGetSymbolAddress((void**)&p_A0, g_A0);     cudaGetSymbolAddress((void**)&p_A1, g_A1);
  cudaGetSymbolAddress((void**)&p_sU2, g_sU2);   cudaGetSymbolAddress((void**)&p_vU2, g_vU2);
  cudaGetSymbolAddress((void**)&p_A2, g_A2);     cudaGetSymbolAddress((void**)&p_s2, g_s2);
  cudaGetSymbolAddress((void**)&p_ds2, g_ds2);   cudaGetSymbolAddress((void**)&p_dA2, g_dA2);
  cudaGetSymbolAddress((void**)&p_Dsj2, g_Dsj2); cudaGetSymbolAddress((void**)&p_Dvj, g_Dvj);
  cudaGetSymbolAddress((void**)&p_dA0, g_dA0);   cudaGetSymbolAddress((void**)&p_dA1, g_dA1);
  cudaGetSymbolAddress((void**)&p_WF, g_WF);     cudaGetSymbolAddress((void**)&p_tabU2, g_tabU2);
  cudaGetSymbolAddress((void**)&p_tabS2, g_tabS2); cudaGetSymbolAddress((void**)&p_u, g_u);

  cudaFuncSetAttribute(tgemm_big_kernel, cudaFuncAttributeMaxDynamicSharedMemorySize, TG_SMEM);
  cudaFuncSetAttribute(tgemm_sm_kernel,  cudaFuncAttributeMaxDynamicSharedMemorySize, TG_SMEM);

  /* 1: init = zero (no Dsj2/Dvj) + tables + fp32 weight GEMMs */
  {
    GOps P; P.count = 0;
    int i;
    i = P.count++; P.A[i]=Wms1; P.B[i]=Wu2s; P.C[i]=p_WF;      P.M[i]=K; P.tiles[i]=2;
    i = P.count++; P.A[i]=Wmv1; P.B[i]=Wu2v; P.C[i]=p_WF + KK; P.M[i]=K; P.tiles[i]=2;
    for (int z = 0; z < NE_; z++){
      i = P.count++; P.A[i]=Wms1; P.B[i]=Wsk2 + z*KK; P.C[i]=p_WF + (2+z)*KK; P.M[i]=K; P.tiles[i]=2;
    }
    init_kernel<<<ZB + 11 + 24, 256>>>(out, out_size, P, We, Wu1, Wsk1, Wu2s, Wsk2, Wms1, wr1);
  }
  /* 2: work1 = geom + z-prep + weight conversion */
  work1_kernel<<<625 + 1 + 52, 256>>>(positions, shifts, edge_index, node_z, p_WF, Wms2);
  /* 3 */
  msg1_kernel<<<1024, 256>>>(R1);
  /* 4: stage C = sU2, vU2, grouped s2, e1+e0 — BIG tiles */
  {
    TOps P; tops_init(P);
    tops_add(P, 0, CDIV(NN,TNB),   0, p_A0, p_sU2, NN,   ALPHA_, 0, p_tabU2, 1, 0);
    tops_add(P, 0, CDIV(3*NN,TNB), 1, p_A1, p_vU2, 3*NN, ALPHA_, 0, 0, 0, 0);
    tops_add(P, 1, GTZ_BIG*NE_,    2, p_A0, p_s2,  NN,   ALPHA_, 0, p_tabS2, 0, 0);
    tops_add(P, 2, CDIV(NN*32,512), 0, 0, 0, NN, 0.f, 0, 0, 0, 0);
    tgemm_big_kernel<<<tops_total(P), 512, TG_SMEM>>>(P, node_z, batch, ae);
  }
  /* 5: msg2 edges + Dsj2/Dvj zero blocks */
  msg2_kernel<<<MSG2_EB + MSG2_ZB, 256>>>(R2);
  /* 6: s2 += a*A2@Wms2 — SMALL tiles */
  {
    TOps P; tops_init(P);
    tops_add(P, 0, CDIV(NN,TNS), 12, p_A2, p_s2, NN, ALPHA_, 1, 0, 0, 0);
    tgemm_sm_kernel<<<tops_total(P), 256, TG_SMEM>>>(P, node_z);
  }
  /* 7 */
  mlp_kernel<<<2048, 128>>>(Wmlp, wout, batch);
  /* 8: dA2 = a*ds2@Wms2^T ; grouped dA0 = a*ds2@WF2z^T — SMALL tiles */
  {
    TOps P; tops_init(P);
    tops_add(P, 0, CDIV(NN,TNS), 25, p_ds2, p_dA2, NN, ALPHA_, 0, 0, 0, 0);
    tops_add(P, 1, GTZ_SM*NE_,   15, p_ds2, p_dA0, NN, ALPHA_, 0, 0, 0, 0);
    tgemm_sm_kernel<<<tops_total(P), 256, TG_SMEM>>>(P, node_z);
  }
  /* 9 */
  bwd2_kernel<<<1024, 256>>>(R2);
  /* 10: dA0 += a*(Dsj2@WF1^T + u^T) ; dA1 = a*Dvj@Wfuse^T — SMALL tiles */
  {
    TOps P; tops_init(P);
    tops_add(P, 0, CDIV(NN,TNS),   13, p_Dsj2, p_dA0, NN,   ALPHA_, 1, 0, 0, p_u);
    tops_add(P, 0, CDIV(3*NN,TNS), 14, p_Dvj,  p_dA1, 3*NN, ALPHA_, 0, 0, 0, 0);
    tgemm_sm_kernel<<<tops_total(P), 256, TG_SMEM>>>(P, node_z);
  }
  /* 11: bwd1 + fused geometry backward + forces + finalize */
  bwd1_kernel<<<1024 + 1, 256>>>(R1, out + GG + 3*GG, out);
}

// round 16
// speedup vs baseline: 1.1192x; 1.0474x over previous
#include <cuda_runtime.h>
#include <cuda_bf16.h>
#include <math.h>
#include <stdint.h>

#define K 128
#define KK (K*K)
#define NN 10000
#define EE 160000
#define NE_ 10
#define NB_ 8
#define GG 16
#define NK (NN*K)
#define TM 64
#define TNB 256
#define TNS 128
#define GTZ_BIG 40
#define GTZ_SM  79

#define SQ3F 1.7320508075688772f
#define INV_SQ3 0.5773502691896258f
#define PI_F 3.14159265358979323846f
#define CB_F 0.6324555320336759f
#define ALPHA_ (1.0f/16.0f)
#define CDIV(a,b) (((a)+(b)-1)/(b))

/* ---- smem layout for tensor GEMM: W full, A in 64-row buffers ----------- */
#define PITCH_B 272
#define W_H_B 0
#define W_L_B 34816
#define A_H_B 69632
#define A_L_B 87040
#define ROWIDX_B 104448
#define TG_SMEM 105472       /* 103 KB -> 2 CTAs/SM */

__device__ __forceinline__ uint32_t smem_u32(const void* p){
  uint32_t a;
  asm("{ .reg .u64 t; cvta.to.shared.u64 t, %1; cvt.u32.u64 %0, t; }" : "=r"(a) : "l"(p));
  return a;
}
#define LDM4(r, addr) \
  asm volatile("ldmatrix.sync.aligned.m8n8.x4.shared.b16 {%0,%1,%2,%3}, [%4];" \
    : "=r"((r)[0]),"=r"((r)[1]),"=r"((r)[2]),"=r"((r)[3]) : "r"(addr))
#define MMA16816(c, a, b0, b1) \
  asm volatile("mma.sync.aligned.m16n8k16.row.col.f32.bf16.bf16.f32 " \
    "{%0,%1,%2,%3}, {%4,%5,%6,%7}, {%8,%9}, {%0,%1,%2,%3};" \
    : "+f"((c)[0]),"+f"((c)[1]),"+f"((c)[2]),"+f"((c)[3]) \
    : "r"((a)[0]),"r"((a)[1]),"r"((a)[2]),"r"((a)[3]), "r"(b0),"r"(b1))
#define BARSYNC(id, cnt) asm volatile("bar.sync %0, %1;" :: "r"(id), "r"(cnt) : "memory")

__device__ __forceinline__ uint32_t pk_bf2(__nv_bfloat16 a, __nv_bfloat16 b){
  return (uint32_t)__bfloat16_as_ushort(a) | ((uint32_t)__bfloat16_as_ushort(b) << 16);
}

/* ------------------- device scratch (no allocs allowed) ------------------ */
__device__ float g_sU1[NE_*K];
__device__ float g_tabU2[NE_*K];
__device__ float g_tabS2[NE_*K];
__device__ float g_t1[NE_];
__device__ float g_u[K];
__device__ float g_r[EE];
__device__ float g_Y1[EE*3];
__device__ float g_ef[EE*NB_];
__device__ int   g_esnd[EE], g_ercv[EE], g_ezsnd[EE];
__device__ int   g_nact;
__device__ float g_A0[NK];
__device__ float g_A1[3*NK];
__device__ float g_sU2[NK];
__device__ float g_vU2[3*NK];
__device__ float g_A2[NK];
__device__ float g_s2[NK];
__device__ float g_ds2[NK];
__device__ float g_dA2[NK];
__device__ float g_Dsj2[NK];
__device__ float g_Dvj[3*NK];
__device__ float g_dA0[NK];
__device__ float g_dA1[3*NK];
__device__ float g_def[EE*NB_];
__device__ float g_dY1b[EE*3];
__device__ float g_e0[GG], g_e1[GG], g_e2[GG];
__device__ float g_WF[12*KK];
__device__ __nv_bfloat16 g_Bh[26*KK];
__device__ __nv_bfloat16 g_Bl[26*KK];
__device__ int g_zoff[NE_+1], g_zperm[NN];

/* -------- fp32 multi-op GEMM struct (weight precompute) ------------------ */
#define MAXG 12
struct GOps {
  int count;
  int tiles[MAXG];
  const float* A[MAXG];
  const float* B[MAXG];
  float* C[MAXG];
  int M[MAXG];
};

/* ==== init: zero (A0/A1/A2/out/e, NOT Dsj2/Dvj) + tables + weight GEMMs == */
#define ZB 1024
__global__ void __launch_bounds__(256) init_kernel(float* __restrict__ out, int out_size, GOps P,
    const float* __restrict__ We, const float* __restrict__ Wu1, const float* __restrict__ Wsk1,
    const float* __restrict__ Wu2s, const float* __restrict__ Wsk2, const float* __restrict__ Wms1,
    const float* __restrict__ wr1){
  __shared__ char ubuf[32768];
  int b = blockIdx.x;
  int tid = threadIdx.x;
  if (b < ZB){
    float4 z4 = make_float4(0.f,0.f,0.f,0.f);
    int g0 = b*256 + tid;
    for (int i = g0; i < 3*NK/4; i += ZB*256) ((float4*)g_A1)[i] = z4;
    for (int i = g0; i < NK/4; i += ZB*256){ ((float4*)g_A0)[i] = z4; ((float4*)g_A2)[i] = z4; }
    for (int i = g0; i < out_size; i += ZB*256) out[i] = 0.f;
    if (b == 0 && tid < GG){ g_e0[tid]=0.f; g_e1[tid]=0.f; g_e2[tid]=0.f; }
    if (b == 0 && tid == 0) g_nact = 0;
    return;
  }
  if (b < ZB + 11){
    int z = b - ZB;
    if (tid >= 128) return;
    int d = tid;
    float* sh  = (float*)ubuf;
    float* red = (float*)(ubuf + 512);
    if (z == NE_){
      float a = 0.f;
      for (int m = 0; m < K; m++) a = fmaf(Wms1[d*K + m], wr1[m], a);
      g_u[d] = a;
      return;
    }
    float a = 0.f, bb = 0.f;
    for (int c = 0; c < K; c++){
      float s = We[z*K + c];
      a  = fmaf(s, Wu1[c*K + d], a);
      bb = fmaf(s, Wsk1[(z*K + c)*K + d], bb);
    }
    g_sU1[z*K + d] = a;
    sh[d] = bb;
    __syncthreads();
    float t2 = 0.f, t3 = 0.f;
    for (int c = 0; c < K; c++){
      float s = sh[c];
      t2 = fmaf(s, Wu2s[c*K + d], t2);
      t3 = fmaf(s, Wsk2[(z*K + c)*K + d], t3);
    }
    g_tabU2[z*K + d] = t2;
    g_tabS2[z*K + d] = t3;
    float p = sh[d]*wr1[d];
    #pragma unroll
    for (int o = 16; o; o >>= 1) p += __shfl_down_sync(0xffffffffu, p, o);
    if ((d & 31) == 0) red[d >> 5] = p;
    __syncthreads();
    if (d == 0) g_t1[z] = red[0] + red[1] + red[2] + red[3];
    return;
  }
  b -= (ZB + 11);
  int op = 0;
  while (b >= P.tiles[op]){ b -= P.tiles[op]; op++; }
  typedef float (*AsT)[K];
  AsT As = (AsT)ubuf;
  int d = tid & 127;
  int g = tid >> 7;
  int M = P.M[op];
  const float* __restrict__ A = P.A[op];
  int base0 = b*TM;
  #pragma unroll 4
  for (int i = 0; i < 32; i++){
    int r = g*32 + i;
    As[r][d] = (base0 + r < M) ? A[(base0 + r)*K + d] : 0.f;
  }
  __syncthreads();
  const float* __restrict__ B = P.B[op];
  float acc[32];
  #pragma unroll
  for (int i = 0; i < 32; i++) acc[i] = 0.f;
  for (int c = 0; c < K; c += 4){
    float b0=B[c*K+d], b1=B[(c+1)*K+d], b2=B[(c+2)*K+d], b3=B[(c+3)*K+d];
    #pragma unroll
    for (int i = 0; i < 32; i++){
      float4 av = *(const float4*)&As[g*32 + i][c];
      acc[i] = fmaf(av.x,b0,fmaf(av.y,b1,fmaf(av.z,b2,fmaf(av.w,b3,acc[i]))));
    }
  }
  float* __restrict__ C = P.C[op];
  int base = base0 + g*32;
  for (int i = 0; i < 32; i++){
    int n = base + i;
    if (n >= M) break;
    C[n*K + d] = acc[i];
  }
}

/* ============ work1: geom + conv (split bf16) + z count/scan/scatter ===== */
__global__ void __launch_bounds__(256) work1_kernel(const float* __restrict__ pos,
    const float* __restrict__ shifts, const int* __restrict__ ei, const int* __restrict__ nz,
    const float* __restrict__ WF, const float* __restrict__ Wms2){
  int b = blockIdx.x;
  if (b < 625){
    int e = b*256 + threadIdx.x;
    if (e >= EE) return;
    int s = ei[e], rc = ei[EE + e];
    float vx = pos[rc*3+0] - pos[s*3+0] + shifts[e*3+0];
    float vy = pos[rc*3+1] - pos[s*3+1] + shifts[e*3+1];
    float vz = pos[rc*3+2] - pos[s*3+2] + shifts[e*3+2];
    float rr = sqrtf(vx*vx + vy*vy + vz*vz + 1e-12f);
    if (rr < 5.0f){
      int i = atomicAdd(&g_nact, 1);
      g_esnd[i]=s; g_ercv[i]=rc; g_ezsnd[i]=nz[s];
      g_r[i]=rr;
      float inv = SQ3F / rr;
      g_Y1[i*3+0]=vx*inv; g_Y1[i*3+1]=vy*inv; g_Y1[i*3+2]=vz*inv;
      float x = rr*0.2f;
      float x2=x*x, x4=x2*x2, x5=x4*x;
      float fc = 1.f + x5*(-21.f + x*(35.f - 15.f*x));
      float invr = 1.f/rr;
      float cf = CB_F*invr*fc;
      float s1_, c1_;
      sincosf(PI_F*0.2f*rr, &s1_, &c1_);
      float sb = s1_, cb = c1_;
      #pragma unroll
      for (int bb = 0; bb < NB_; bb++){
        g_ef[i*NB_ + bb] = cf*sb;
        float ns = sb*c1_ + cb*s1_;
        float nc = cb*c1_ - sb*s1_;
        sb = ns; cb = nc;
      }
    }
    return;
  }
  if (b == 625){
    __shared__ int cnt[NE_];
    __shared__ int off[NE_+1];
    __shared__ int fill[NE_];
    int tid = threadIdx.x;
    if (tid < NE_) cnt[tid] = 0;
    __syncthreads();
    for (int n = tid; n < NN; n += 256) atomicAdd(&cnt[nz[n]], 1);
    __syncthreads();
    if (tid == 0){
      int acc = 0;
      for (int z = 0; z < NE_; z++){ off[z] = acc; g_zoff[z] = acc; acc += cnt[z]; }
      off[NE_] = acc; g_zoff[NE_] = acc;
    }
    __syncthreads();
    if (tid < NE_) fill[tid] = off[tid];
    __syncthreads();
    for (int n = tid; n < NN; n += 256){
      int p = atomicAdd(&fill[nz[n]], 1);
      g_zperm[p] = n;
    }
    return;
  }
  int bb = b - 626;
  for (int id = bb*256 + threadIdx.x; id < 26*KK; id += 52*256){
    int j = id >> 14;
    int rem = id & (KK-1);
    int n = rem >> 7, k = rem & 127;
    const float* W; int trans;
    if (j < 12){ W = WF + j*KK; trans = 0; }
    else if (j == 12){ W = Wms2; trans = 0; }
    else if (j < 25){ W = WF + (j-13)*KK; trans = 1; }
    else { W = Wms2; trans = 1; }
    float v = trans ? W[n*K + k] : W[k*K + n];
    __nv_bfloat16 h = __float2bfloat16(v);
    __nv_bfloat16 l = __float2bfloat16(v - __bfloat162float(h));
    g_Bh[(size_t)j*KK + rem] = h;
    g_Bl[(size_t)j*KK + rem] = l;
  }
}

/* ---------- big tensor GEMM core (512 thr, per-group barriers) ----------- */
__device__ __forceinline__ void tgemm_core_big(char* smc, const int* __restrict__ rowIdx,
    const float* __restrict__ A, float* __restrict__ C, int bidx, float alpha, int accum,
    const float* __restrict__ tab, const int* __restrict__ nz, const float* __restrict__ bias){
  int tid = threadIdx.x;
  {
    const uint4* gh = (const uint4*)(g_Bh + (size_t)bidx*KK);
    const uint4* gl = (const uint4*)(g_Bl + (size_t)bidx*KK);
    #pragma unroll
    for (int i = 0; i < 4; i++){
      int idx = tid + i*512;
      int row = idx >> 4, q = idx & 15;
      uint4 vh = gh[idx], vl = gl[idx];
      *(uint4*)(smc + W_H_B + row*PITCH_B + q*16) = vh;
      *(uint4*)(smc + W_L_B + row*PITCH_B + q*16) = vl;
    }
  }
  __syncthreads();

  int warp = tid >> 5, lane = tid & 31;
  int grp = warp & 3;
  int mrow0 = grp*16;
  int ncol0 = (warp >> 2)*32;
  int gtid = (warp >> 2)*32 + lane;
  int barid = grp + 1;
  int quad = lane >> 3, rin = lane & 7;
  uint32_t smbase = smem_u32(smc);
  uint32_t aoff = (uint32_t)(rin + (quad & 1)*8)*PITCH_B + (uint32_t)((quad >> 1)*8)*2;
  uint32_t ahb = smbase + A_H_B + (uint32_t)mrow0*PITCH_B + aoff;
  uint32_t alb = smbase + A_L_B + (uint32_t)mrow0*PITCH_B + aoff;
  uint32_t boff = (uint32_t)(rin + (quad >> 1)*8)*PITCH_B + (uint32_t)((quad & 1)*8)*2;
  uint32_t whb = smbase + W_H_B + (uint32_t)ncol0*PITCH_B + boff;
  uint32_t wlb = smbase + W_L_B + (uint32_t)ncol0*PITCH_B + boff;
  int g = lane >> 2, tg = lane & 3;

  #pragma unroll
  for (int qtr = 0; qtr < 4; qtr++){
    #pragma unroll
    for (int i = 0; i < 4; i++){
      int idx = gtid + i*128;
      int row16 = idx >> 5, c4 = (idx & 31)*4;
      int row = mrow0 + row16;
      int gr = rowIdx[qtr*64 + row];
      float4 v = (gr >= 0) ? *(const float4*)&A[(size_t)gr*K + c4] : make_float4(0.f,0.f,0.f,0.f);
      __nv_bfloat16 h0=__float2bfloat16(v.x), h1=__float2bfloat16(v.y);
      __nv_bfloat16 h2=__float2bfloat16(v.z), h3=__float2bfloat16(v.w);
      __nv_bfloat16 l0=__float2bfloat16(v.x-__bfloat162float(h0));
      __nv_bfloat16 l1=__float2bfloat16(v.y-__bfloat162float(h1));
      __nv_bfloat16 l2=__float2bfloat16(v.z-__bfloat162float(h2));
      __nv_bfloat16 l3=__float2bfloat16(v.w-__bfloat162float(h3));
      *(uint2*)(smc + A_H_B + row*PITCH_B + c4*2) = make_uint2(pk_bf2(h0,h1), pk_bf2(h2,h3));
      *(uint2*)(smc + A_L_B + row*PITCH_B + c4*2) = make_uint2(pk_bf2(l0,l1), pk_bf2(l2,l3));
    }
    BARSYNC(barid, 128);

    float c[4][4];
    #pragma unroll
    for (int nt = 0; nt < 4; nt++){ c[nt][0]=0.f; c[nt][1]=0.f; c[nt][2]=0.f; c[nt][3]=0.f; }

    #pragma unroll
    for (int kt = 0; kt < 8; kt++){
      uint32_t kb = (uint32_t)kt*32;
      uint32_t ah[4], al[4];
      LDM4(ah, ahb + kb);
      LDM4(al, alb + kb);
      #pragma unroll
      for (int s = 0; s < 2; s++){
        uint32_t bh[4], bl[4];
        LDM4(bh, whb + kb + (uint32_t)s*16*PITCH_B);
        LDM4(bl, wlb + kb + (uint32_t)s*16*PITCH_B);
        MMA16816(c[s*2],   ah, bh[0], bh[1]);
        MMA16816(c[s*2],   ah, bl[0], bl[1]);
        MMA16816(c[s*2],   al, bh[0], bh[1]);
        MMA16816(c[s*2+1], ah, bh[2], bh[3]);
        MMA16816(c[s*2+1], ah, bl[2], bl[3]);
        MMA16816(c[s*2+1], al, bh[2], bh[3]);
      }
    }

    #pragma unroll
    for (int hr = 0; hr < 2; hr++){
      int lrow = mrow0 + g + hr*8;
      int grow = rowIdx[qtr*64 + lrow];
      if (grow >= 0){
        const float* trow = 0;
        if (tab) trow = nz ? tab + (size_t)nz[grow]*K : tab;
        #pragma unroll
        for (int nt = 0; nt < 4; nt++){
          int col = ncol0 + nt*8 + tg*2;
          float v0 = alpha*c[nt][hr*2+0];
          float v1 = alpha*c[nt][hr*2+1];
          if (trow){ v0 += trow[col]; v1 += trow[col+1]; }
          if (bias){ v0 += alpha*bias[col]; v1 += alpha*bias[col+1]; }
          if (accum){ float2 o = *(const float2*)&C[(size_t)grow*K + col]; v0 += o.x; v1 += o.y; }
          *(float2*)&C[(size_t)grow*K + col] = make_float2(v0, v1);
        }
      }
    }
    if (qtr < 3) BARSYNC(barid, 128);
  }
}

/* ---------- small tensor GEMM core (256 thr, per-group barriers, -------
   with register prefetch of the next half's A rows) ---------------------- */
__device__ __forceinline__ void tgemm_core_sm(char* smc, const int* __restrict__ rowIdx,
    const float* __restrict__ A, float* __restrict__ C, int bidx, float alpha, int accum,
    const float* __restrict__ tab, const int* __restrict__ nz, const float* __restrict__ bias){
  int tid = threadIdx.x;
  {
    const uint4* gh = (const uint4*)(g_Bh + (size_t)bidx*KK);
    const uint4* gl = (const uint4*)(g_Bl + (size_t)bidx*KK);
    #pragma unroll
    for (int i = 0; i < 8; i++){
      int idx = tid + i*256;
      int row = idx >> 4, q = idx & 15;
      uint4 vh = gh[idx], vl = gl[idx];
      *(uint4*)(smc + W_H_B + row*PITCH_B + q*16) = vh;
      *(uint4*)(smc + W_L_B + row*PITCH_B + q*16) = vl;
    }
  }
  __syncthreads();

  int warp = tid >> 5, lane = tid & 31;
  int grp = warp & 3;
  int mrow0 = grp*16;
  int ncol0 = (warp >> 2)*64;
  int gtid = (warp >> 2)*32 + lane;
  int barid = grp + 1;
  int quad = lane >> 3, rin = lane & 7;
  uint32_t smbase = smem_u32(smc);
  uint32_t aoff = (uint32_t)(rin + (quad & 1)*8)*PITCH_B + (uint32_t)((quad >> 1)*8)*2;
  uint32_t ahb = smbase + A_H_B + (uint32_t)mrow0*PITCH_B + aoff;
  uint32_t alb = smbase + A_L_B + (uint32_t)mrow0*PITCH_B + aoff;
  uint32_t boff = (uint32_t)(rin + (quad >> 1)*8)*PITCH_B + (uint32_t)((quad & 1)*8)*2;
  uint32_t whb = smbase + W_H_B + (uint32_t)ncol0*PITCH_B + boff;
  uint32_t wlb = smbase + W_L_B + (uint32_t)ncol0*PITCH_B + boff;
  int g = lane >> 2, tg = lane & 3;

  /* prefetch half 0 A rows into registers */
  float4 pre[8];
  #pragma unroll
  for (int i = 0; i < 8; i++){
    int idx = gtid + i*64;
    int row = mrow0 + (idx >> 5), c4 = (idx & 31)*4;
    int gr = rowIdx[row];
    pre[i] = (gr >= 0) ? *(const float4*)&A[(size_t)gr*K + c4] : make_float4(0.f,0.f,0.f,0.f);
  }

  #pragma unroll
  for (int half = 0; half < 2; half++){
    /* convert prefetched regs -> smem */
    #pragma unroll
    for (int i = 0; i < 8; i++){
      int idx = gtid + i*64;
      int row = mrow0 + (idx >> 5), c4 = (idx & 31)*4;
      float4 v = pre[i];
      __nv_bfloat16 h0=__float2bfloat16(v.x), h1=__float2bfloat16(v.y);
      __nv_bfloat16 h2=__float2bfloat16(v.z), h3=__float2bfloat16(v.w);
      __nv_bfloat16 l0=__float2bfloat16(v.x-__bfloat162float(h0));
      __nv_bfloat16 l1=__float2bfloat16(v.y-__bfloat162float(h1));
      __nv_bfloat16 l2=__float2bfloat16(v.z-__bfloat162float(h2));
      __nv_bfloat16 l3=__float2bfloat16(v.w-__bfloat162float(h3));
      *(uint2*)(smc + A_H_B + row*PITCH_B + c4*2) = make_uint2(pk_bf2(h0,h1), pk_bf2(h2,h3));
      *(uint2*)(smc + A_L_B + row*PITCH_B + c4*2) = make_uint2(pk_bf2(l0,l1), pk_bf2(l2,l3));
    }
    BARSYNC(barid, 64);

    /* issue LDGs for the next half now; they fly during the MMA loop */
    if (half < 1){
      #pragma unroll
      for (int i = 0; i < 8; i++){
        int idx = gtid + i*64;
        int row = mrow0 + (idx >> 5), c4 = (idx & 31)*4;
        int gr = rowIdx[64 + row];
        pre[i] = (gr >= 0) ? *(const float4*)&A[(size_t)gr*K + c4] : make_float4(0.f,0.f,0.f,0.f);
      }
    }

    float c[8][4];
    #pragma unroll
    for (int nt = 0; nt < 8; nt++){ c[nt][0]=0.f; c[nt][1]=0.f; c[nt][2]=0.f; c[nt][3]=0.f; }

    #pragma unroll
    for (int kt = 0; kt < 8; kt++){
      uint32_t kb = (uint32_t)kt*32;
      uint32_t ah[4], al[4];
      LDM4(ah, ahb + kb);
      LDM4(al, alb + kb);
      #pragma unroll
      for (int nt2 = 0; nt2 < 4; nt2++){
        uint32_t bh[4], bl[4];
        LDM4(bh, whb + kb + (uint32_t)nt2*16*PITCH_B);
        LDM4(bl, wlb + kb + (uint32_t)nt2*16*PITCH_B);
        MMA16816(c[nt2*2],   ah, bh[0], bh[1]);
        MMA16816(c[nt2*2],   ah, bl[0], bl[1]);
        MMA16816(c[nt2*2],   al, bh[0], bh[1]);
        MMA16816(c[nt2*2+1], ah, bh[2], bh[3]);
        MMA16816(c[nt2*2+1], ah, bl[2], bl[3]);
        MMA16816(c[nt2*2+1], al, bh[2], bh[3]);
      }
    }

    #pragma unroll
    for (int hr = 0; hr < 2; hr++){
      int lrow = mrow0 + g + hr*8;
      int grow = rowIdx[half*64 + lrow];
      if (grow >= 0){
        const float* trow = 0;
        if (tab) trow = nz ? tab + (size_t)nz[grow]*K : tab;
        #pragma unroll
        for (int nt = 0; nt < 8; nt++){
          int col = ncol0 + nt*8 + tg*2;
          float v0 = alpha*c[nt][hr*2+0];
          float v1 = alpha*c[nt][hr*2+1];
          if (trow){ v0 += trow[col]; v1 += trow[col+1]; }
          if (bias){ v0 += alpha*bias[col]; v1 += alpha*bias[col+1]; }
          if (accum){ float2 o = *(const float2*)&C[(size_t)grow*K + col]; v0 += o.x; v1 += o.y; }
          *(float2*)&C[(size_t)grow*K + col] = make_float2(v0, v1);
        }
      }
    }
    if (half < 1) BARSYNC(barid, 64);
  }
}

/* ------ multi-op tensor GEMM: kind 0=linear 1=grouped 2=e1 --------------- */
#define MAXOPS 4
struct TOps {
  int count;
  int tiles[MAXOPS];
  int kind[MAXOPS];
  int bidx[MAXOPS];
  const float* A[MAXOPS];
  float* C[MAXOPS];
  const float* table[MAXOPS];
  const float* bias[MAXOPS];
  int M[MAXOPS];
  int accum[MAXOPS];
  int useNz[MAXOPS];
  float alpha[MAXOPS];
};

__global__ void __launch_bounds__(512) tgemm_big_kernel(TOps P, const int* __restrict__ node_z,
    const int* __restrict__ batch, const float* __restrict__ ae){
  int b = blockIdx.x, op = 0;
  while (b >= P.tiles[op]){ b -= P.tiles[op]; op++; }
  int kind = P.kind[op];
  if (kind == 2){
    int gt = b*512 + threadIdx.x;
    int n = gt >> 5, lane = gt & 31;
    if (n >= NN) return;
    float acc = 0.f;
    #pragma unroll
    for (int c = lane; c < K; c += 32) acc = fmaf(g_A0[n*K + c], g_u[c], acc);
    #pragma unroll
    for (int o = 16; o; o >>= 1) acc += __shfl_down_sync(0xffffffffu, acc, o);
    if (lane == 0){
      int zz = node_z[n];
      atomicAdd(&g_e1[batch[n]], ALPHA_*acc + g_t1[zz]);
      atomicAdd(&g_e0[batch[n]], ae[zz]);
    }
    return;
  }
  extern __shared__ char smc[];
  int* rowIdx = (int*)(smc + ROWIDX_B);
  int bidx = P.bidx[op];
  const float* tab = P.table[op];
  const int* nz = 0;
  if (kind == 0){
    int base = b*TNB, M = P.M[op];
    if (threadIdx.x < TNB) rowIdx[threadIdx.x] = (base + (int)threadIdx.x < M) ? base + threadIdx.x : -1;
    nz = P.useNz[op] ? node_z : 0;
  } else {
    int z = b / GTZ_BIG;
    int m0 = (b - z*GTZ_BIG)*TNB;
    int start = g_zoff[z], cnt = g_zoff[z+1] - start;
    if (m0 >= cnt) return;
    if (threadIdx.x < TNB) rowIdx[threadIdx.x] = (m0 + (int)threadIdx.x < cnt) ? g_zperm[start + m0 + threadIdx.x] : -1;
    bidx += z;
    if (tab) tab = tab + (size_t)z*K;
  }
  __syncthreads();
  tgemm_core_big(smc, rowIdx, P.A[op], P.C[op], bidx, P.alpha[op], P.accum[op], tab, nz, P.bias[op]);
}

__global__ void __launch_bounds__(256) tgemm_sm_kernel(TOps P, const int* __restrict__ node_z){
  int b = blockIdx.x, op = 0;
  while (b >= P.tiles[op]){ b -= P.tiles[op]; op++; }
  int kind = P.kind[op];
  extern __shared__ char smc[];
  int* rowIdx = (int*)(smc + ROWIDX_B);
  int bidx = P.bidx[op];
  const float* tab = P.table[op];
  const int* nz = 0;
  if (kind == 0){
    int base = b*TNS, M = P.M[op];
    if (threadIdx.x < TNS) rowIdx[threadIdx.x] = (base + (int)threadIdx.x < M) ? base + threadIdx.x : -1;
    nz = P.useNz[op] ? node_z : 0;
  } else {
    int z = b / GTZ_SM;
    int m0 = (b - z*GTZ_SM)*TNS;
    int start = g_zoff[z], cnt = g_zoff[z+1] - start;
    if (m0 >= cnt) return;
    if (threadIdx.x < TNS) rowIdx[threadIdx.x] = (m0 + (int)threadIdx.x < cnt) ? g_zperm[start + m0 + threadIdx.x] : -1;
    bidx += z;
    if (tab) tab = tab + (size_t)z*K;
  }
  __syncthreads();
  tgemm_core_sm(smc, rowIdx, P.A[op], P.C[op], bidx, P.alpha[op], P.accum[op], tab, nz, P.bias[op]);
}

/* --------------- layer-1 messages: 2 edges per 256-thread block ---------- */
__global__ void __launch_bounds__(256) msg1_kernel(const float* __restrict__ R1){
  int c = threadIdx.x & 127;
  int sub = threadIdx.x >> 7;
  float r1a[NB_], r1b[NB_];
  #pragma unroll
  for (int b = 0; b < NB_; b++){ r1a[b]=R1[b*256 + c]; r1b[b]=R1[b*256 + 128 + c]; }
  int nact = g_nact;
  for (int e = blockIdx.x*2 + sub; e < nact; e += gridDim.x*2){
    int rcv = g_ercv[e], zs = g_ezsnd[e];
    float y0=g_Y1[e*3+0], y1=g_Y1[e*3+1], y2=g_Y1[e*3+2];
    float w0=0.f, w1=0.f;
    #pragma unroll
    for (int b = 0; b < NB_; b++){ float efb=g_ef[e*NB_+b]; w0=fmaf(efb,r1a[b],w0); w1=fmaf(efb,r1b[b],w1); }
    float sj = g_sU1[zs*K + c];
    atomicAdd(&g_A0[rcv*K + c], w0*sj);
    float t = w1*sj;
    atomicAdd(&g_A1[rcv*K + c],        t*y0);
    atomicAdd(&g_A1[NK + rcv*K + c],   t*y1);
    atomicAdd(&g_A1[2*NK + rcv*K + c], t*y2);
  }
}

/* ------ layer-2 messages: 2 edges per block + Dsj2/Dvj zero blocks ------- */
#define MSG2_EB 1024
#define MSG2_ZB 512
__global__ void __launch_bounds__(256) msg2_kernel(const float* __restrict__ R2){
  if (blockIdx.x >= MSG2_EB){
    int zb = blockIdx.x - MSG2_EB;
    float4 z4 = make_float4(0.f,0.f,0.f,0.f);
    for (int i = zb*256 + threadIdx.x; i < NK/4; i += MSG2_ZB*256)
      ((float4*)g_Dsj2)[i] = z4;
    for (int i = zb*256 + threadIdx.x; i < 3*NK/4; i += MSG2_ZB*256)
      ((float4*)g_Dvj)[i] = z4;
    return;
  }
  int c = threadIdx.x & 127;
  int sub = threadIdx.x >> 7;
  float r2a[NB_], r2b[NB_];
  #pragma unroll
  for (int b = 0; b < NB_; b++){ r2a[b]=R2[b*512 + c]; r2b[b]=R2[b*512 + 128 + c]; }
  int nact = g_nact;
  for (int e = blockIdx.x*2 + sub; e < nact; e += MSG2_EB*2){
    int snd = g_esnd[e], rcv = g_ercv[e];
    float y0=g_Y1[e*3+0], y1=g_Y1[e*3+1], y2=g_Y1[e*3+2];
    float w00=0.f, w110=0.f;
    #pragma unroll
    for (int b = 0; b < NB_; b++){ float efb=g_ef[e*NB_+b]; w00=fmaf(efb,r2a[b],w00); w110=fmaf(efb,r2b[b],w110); }
    float sj = g_sU2[snd*K + c];
    float vj0=g_vU2[snd*K+c], vj1=g_vU2[NK+snd*K+c], vj2=g_vU2[2*NK+snd*K+c];
    float dot = vj0*y0 + vj1*y1 + vj2*y2;
    float m = fmaf(w00, sj, w110*dot*INV_SQ3);
    atomicAdd(&g_A2[rcv*K + c], m);
  }
}

/* ----------------------- MLP head: e2 + ds2 ------------------------------ */
__global__ void __launch_bounds__(128) mlp_kernel(const float* __restrict__ Wmlp,
    const float* __restrict__ wout, const int* __restrict__ batch){
  __shared__ float srow[K];
  __shared__ float gj[16];
  __shared__ float hpart[16];
  int tid = threadIdx.x;
  for (int n = blockIdx.x; n < NN; n += gridDim.x){
    srow[tid] = g_s2[n*K + tid];
    __syncthreads();
    if (tid < 16){
      float uu = 0.f;
      for (int c = 0; c < K; c++) uu = fmaf(srow[c], Wmlp[c*16 + tid], uu);
      float sig = 1.f/(1.f + __expf(-uu));
      hpart[tid] = uu*sig*wout[tid];
      gj[tid] = wout[tid]*sig*(1.f + uu*(1.f - sig));
    }
    __syncthreads();
    if (tid == 0){
      float s = 0.f;
      #pragma unroll
      for (int j = 0; j < 16; j++) s += hpart[j];
      atomicAdd(&g_e2[batch[n]], s);
    }
    float ds = 0.f;
    #pragma unroll
    for (int j = 0; j < 16; j++) ds = fmaf(Wmlp[tid*16 + j], gj[j], ds);
    g_ds2[n*K + tid] = ds;
    __syncthreads();
  }
}

/* --------------- backward layer-2: 2 edges per 256-thread block ---------- */
__device__ __forceinline__ float warpsum(float v){
  #pragma unroll
  for (int o = 16; o; o >>= 1) v += __shfl_down_sync(0xffffffffu, v, o);
  return v;
}

__global__ void __launch_bounds__(256) bwd2_kernel(const float* __restrict__ R2){
  __shared__ float red[2][4][11];
  int tid = threadIdx.x;
  int c = tid & 127;
  int sub = tid >> 7;
  int warp = (tid >> 5) & 3, lane = tid & 31;
  float r2a[NB_], r2b[NB_];
  #pragma unroll
  for (int b = 0; b < NB_; b++){ r2a[b]=R2[b*512 + c]; r2b[b]=R2[b*512 + 128 + c]; }
  int nact = g_nact;
  for (int base = blockIdx.x*2; base < nact; base += gridDim.x*2){
    int e = base + sub;
    bool act = (e < nact);
    float y0=0.f, y1=0.f, y2=0.f, dm=0.f, sj=0.f, vj0=0.f, vj1=0.f, vj2=0.f;
    float w00=0.f, w110=0.f;
    int snd=0;
    if (act){
      snd = g_esnd[e];
      int rcv = g_ercv[e];
      y0=g_Y1[e*3+0]; y1=g_Y1[e*3+1]; y2=g_Y1[e*3+2];
      #pragma unroll
      for (int b = 0; b < NB_; b++){ float efb=g_ef[e*NB_+b]; w00=fmaf(efb,r2a[b],w00); w110=fmaf(efb,r2b[b],w110); }
      dm = g_dA2[rcv*K + c];
      sj = g_sU2[snd*K + c];
      vj0=g_vU2[snd*K+c]; vj1=g_vU2[NK+snd*K+c]; vj2=g_vU2[2*NK+snd*K+c];
    }
    float dot = vj0*y0 + vj1*y1 + vj2*y2;
    float ddot = dm*w110*INV_SQ3;
    if (act){
      atomicAdd(&g_Dsj2[snd*K + c], dm*w00);
      atomicAdd(&g_Dvj[snd*K + c],        ddot*y0);
      atomicAdd(&g_Dvj[NK + snd*K + c],   ddot*y1);
      atomicAdd(&g_Dvj[2*NK + snd*K + c], ddot*y2);
    }
    float p[11];
    float dw00 = dm*sj, dw110 = dm*dot*INV_SQ3;
    #pragma unroll
    for (int b = 0; b < NB_; b++) p[b] = fmaf(dw00, r2a[b], dw110*r2b[b]);
    p[8] = ddot*vj0; p[9] = ddot*vj1; p[10] = ddot*vj2;
    #pragma unroll
    for (int k = 0; k < 11; k++){
      float v = warpsum(p[k]);
      if (lane == 0) red[sub][warp][k] = v;
    }
    __syncthreads();
    if (c < 11 && act){
      float v = red[sub][0][c] + red[sub][1][c] + red[sub][2][c] + red[sub][3][c];
      if (c < 8) g_def[e*NB_ + c] = v;
      else       g_dY1b[e*3 + (c-8)] = v;
    }
    __syncthreads();
  }
}

/* --- backward layer-1 + fused geometry backward + forces + finalize ------ */
__global__ void __launch_bounds__(256) bwd1_kernel(const float* __restrict__ R1,
    float* __restrict__ F, float* __restrict__ out){
  if (blockIdx.x == gridDim.x - 1){
    int g = threadIdx.x;
    if (g < GG){
      float a = g_e0[g], b = g_e1[g], c = g_e2[g];
      out[g] = a + b + c;
      out[GG + g*3 + 0] = a;
      out[GG + g*3 + 1] = b;
      out[GG + g*3 + 2] = c;
    }
    return;
  }
  __shared__ float red[2][4][11];
  int tid = threadIdx.x;
  int c = tid & 127;
  int sub = tid >> 7;
  int warp = (tid >> 5) & 3, lane = tid & 31;
  float r1a[NB_], r1b[NB_];
  #pragma unroll
  for (int b = 0; b < NB_; b++){ r1a[b]=R1[b*256 + c]; r1b[b]=R1[b*256 + 128 + c]; }
  int nact = g_nact;
  int nblocks = gridDim.x - 1;
  for (int base = blockIdx.x*2; base < nact; base += nblocks*2){
    int e = base + sub;
    bool act = (e < nact);
    float y0=0.f, y1=0.f, y2=0.f;
    float w1=0.f, dm0=0.f, dm10=0.f, dm11=0.f, dm12=0.f, sj=0.f;
    if (act){
      int rcv = g_ercv[e], zs = g_ezsnd[e];
      y0=g_Y1[e*3+0]; y1=g_Y1[e*3+1]; y2=g_Y1[e*3+2];
      #pragma unroll
      for (int b = 0; b < NB_; b++){ float efb=g_ef[e*NB_+b]; w1 = fmaf(efb, r1b[b], w1); }
      dm0 = g_dA0[rcv*K + c];
      dm10 = g_dA1[rcv*K + c];
      dm11 = g_dA1[NK + rcv*K + c];
      dm12 = g_dA1[2*NK + rcv*K + c];
      sj = g_sU1[zs*K + c];
    }
    float dw0 = dm0*sj;
    float t = dm10*y0 + dm11*y1 + dm12*y2;
    float dw1 = t*sj;
    float p[11];
    #pragma unroll
    for (int b = 0; b < NB_; b++) p[b] = fmaf(dw0, r1a[b], dw1*r1b[b]);
    float ws = w1*sj;
    p[8] = dm10*ws; p[9] = dm11*ws; p[10] = dm12*ws;
    #pragma unroll
    for (int k = 0; k < 11; k++){
      float v = warpsum(p[k]);
      if (lane == 0) red[sub][warp][k] = v;
    }
    __syncthreads();
    if (c == 0 && act){
      float def_t[NB_], dY[3];
      #pragma unroll
      for (int k = 0; k < NB_; k++)
        def_t[k] = g_def[e*NB_ + k] + red[sub][0][k] + red[sub][1][k] + red[sub][2][k] + red[sub][3][k];
      #pragma unroll
      for (int j = 0; j < 3; j++)
        dY[j] = g_dY1b[e*3 + j] + red[sub][0][8+j] + red[sub][1][8+j] + red[sub][2][8+j] + red[sub][3][8+j];
      float rr = g_r[e];
      float yy0=g_Y1[e*3+0], yy1=g_Y1[e*3+1], yy2=g_Y1[e*3+2];
      float v0 = yy0*rr*INV_SQ3, v1 = yy1*rr*INV_SQ3, v2 = yy2*rr*INV_SQ3;
      float x = rr*0.2f;
      float x2=x*x, x4=x2*x2, x5=x4*x;
      float fc = 1.f + x5*(-21.f + x*(35.f - 15.f*x));
      float omx = 1.f - x;
      float dfcdr = -21.f*x4*omx*omx;
      float invr = 1.f/rr;
      float s1_, c1_;
      sincosf(PI_F*0.2f*rr, &s1_, &c1_);
      float sb = s1_, cb = c1_;
      float dr = 0.f;
      #pragma unroll
      for (int b = 0; b < NB_; b++){
        float a = (float)(b+1)*(PI_F*0.2f);
        float debdr = CB_F*((a*cb*rr - sb)*invr*invr*fc + sb*invr*dfcdr);
        dr = fmaf(def_t[b], debdr, dr);
        float ns = sb*c1_ + cb*s1_;
        float nc = cb*c1_ - sb*s1_;
        sb = ns; cb = nc;
      }
      float vd = v0*dY[0] + v1*dY[1] + v2*dY[2];
      float c1c = SQ3F*invr;
      float c2c = SQ3F*vd*invr*invr*invr;
      float dv0 = dr*v0*invr + c1c*dY[0] - c2c*v0;
      float dv1 = dr*v1*invr + c1c*dY[1] - c2c*v1;
      float dv2 = dr*v2*invr + c1c*dY[2] - c2c*v2;
      int snd = g_esnd[e], rcv = g_ercv[e];
      atomicAdd(&F[snd*3+0],  dv0); atomicAdd(&F[snd*3+1],  dv1); atomicAdd(&F[snd*3+2],  dv2);
      atomicAdd(&F[rcv*3+0], -dv0); atomicAdd(&F[rcv*3+1], -dv1); atomicAdd(&F[rcv*3+2], -dv2);
    }
    __syncthreads();
  }
}

/* ------------------------------ host helpers ----------------------------- */
static void tops_init(TOps& P){ P.count = 0; }
static void tops_add(TOps& P, int kind, int tiles, int bidx, const float* A, float* C,
                     int M, float alpha, int accum, const float* table, int useNz,
                     const float* bias){
  int i = P.count++;
  P.kind[i]=kind; P.tiles[i]=tiles; P.bidx[i]=bidx; P.A[i]=A; P.C[i]=C; P.M[i]=M;
  P.alpha[i]=alpha; P.accum[i]=accum; P.table[i]=table; P.useNz[i]=useNz; P.bias[i]=bias;
}
static int tops_total(const TOps& P){
  int t = 0; for (int i = 0; i < P.count; i++) t += P.tiles[i];
  return t;
}

/* ------------------------------ launch ----------------------------------- */
extern "C" void kernel_launch(void* const* d_in, const int* in_sizes, int n_in,
                              void* d_out, int out_size){
  const float *positions, *shifts, *ae, *We, *R1, *Wu1, *Wms1, *Wmv1, *Wsk1, *wr1;
  const float *R2, *Wu2s, *Wu2v, *Wms2, *Wsk2, *Wmlp, *wout;
  const int *edge_index, *node_z, *batch;

  if (in_sizes[2] == 2*EE){  /* setup_inputs dict order */
    positions=(const float*)d_in[0]; shifts=(const float*)d_in[1];
    edge_index=(const int*)d_in[2]; node_z=(const int*)d_in[3]; batch=(const int*)d_in[4];
    ae=(const float*)d_in[5]; We=(const float*)d_in[6]; R1=(const float*)d_in[7];
    Wu1=(const float*)d_in[8]; Wms1=(const float*)d_in[9]; Wmv1=(const float*)d_in[10];
    Wsk1=(const float*)d_in[11]; wr1=(const float*)d_in[12]; R2=(const float*)d_in[13];
    Wu2s=(const float*)d_in[14]; Wu2v=(const float*)d_in[15]; Wms2=(const float*)d_in[16];
    Wsk2=(const float*)d_in[17]; Wmlp=(const float*)d_in[18]; wout=(const float*)d_in[19];
  } else {                   /* reference signature order */
    positions=(const float*)d_in[0]; shifts=(const float*)d_in[1];
    ae=(const float*)d_in[2]; We=(const float*)d_in[3]; R1=(const float*)d_in[4];
    Wu1=(const float*)d_in[5]; Wms1=(const float*)d_in[6]; Wmv1=(const float*)d_in[7];
    Wsk1=(const float*)d_in[8]; wr1=(const float*)d_in[9]; R2=(const float*)d_in[10];
    Wu2s=(const float*)d_in[11]; Wu2v=(const float*)d_in[12]; Wms2=(const float*)d_in[13];
    Wsk2=(const float*)d_in[14]; Wmlp=(const float*)d_in[15]; wout=(const float*)d_in[16];
    edge_index=(const int*)d_in[17]; node_z=(const int*)d_in[18]; batch=(const int*)d_in[19];
  }
  float* out = (float*)d_out;

  float *p_A0,*p_A1,*p_sU2,*p_vU2,*p_A2,*p_s2,*p_ds2,*p_dA2,*p_Dsj2,*p_Dvj,*p_dA0,*p_dA1;
  float *p_WF,*p_tabU2,*p_tabS2,*p_u;
  cudaGetSymbolAddress((void**)&p_A0, g_A0);     cudaGetSymbolAddress((void**)&p_A1, g_A1);
  cudaGetSymbolAddress((void**)&p_sU2, g_sU2);   cudaGetSymbolAddress((void**)&p_vU2, g_vU2);
  cudaGetSymbolAddress((void**)&p_A2, g_A2);     cudaGetSymbolAddress((void**)&p_s2, g_s2);
  cudaGetSymbolAddress((void**)&p_ds2, g_ds2);   cudaGetSymbolAddress((void**)&p_dA2, g_dA2);
  cudaGetSymbolAddress((void**)&p_Dsj2, g_Dsj2); cudaGetSymbolAddress((void**)&p_Dvj, g_Dvj);
  cudaGetSymbolAddress((void**)&p_dA0, g_dA0);   cudaGetSymbolAddress((void**)&p_dA1, g_dA1);
  cudaGetSymbolAddress((void**)&p_WF, g_WF);     cudaGetSymbolAddress((void**)&p_tabU2, g_tabU2);
  cudaGetSymbolAddress((void**)&p_tabS2, g_tabS2); cudaGetSymbolAddress((void**)&p_u, g_u);

  cudaFuncSetAttribute(tgemm_big_kernel, cudaFuncAttributeMaxDynamicSharedMemorySize, TG_SMEM);
  cudaFuncSetAttribute(tgemm_sm_kernel,  cudaFuncAttributeMaxDynamicSharedMemorySize, TG_SMEM);

  /* 1: init = zero (no Dsj2/Dvj) + tables + fp32 weight GEMMs */
  {
    GOps P; P.count = 0;
    int i;
    i = P.count++; P.A[i]=Wms1; P.B[i]=Wu2s; P.C[i]=p_WF;      P.M[i]=K; P.tiles[i]=2;
    i = P.count++; P.A[i]=Wmv1; P.B[i]=Wu2v; P.C[i]=p_WF + KK; P.M[i]=K; P.tiles[i]=2;
    for (int z = 0; z < NE_; z++){
      i = P.count++; P.A[i]=Wms1; P.B[i]=Wsk2 + z*KK; P.C[i]=p_WF + (2+z)*KK; P.M[i]=K; P.tiles[i]=2;
    }
    init_kernel<<<ZB + 11 + 24, 256>>>(out, out_size, P, We, Wu1, Wsk1, Wu2s, Wsk2, Wms1, wr1);
  }
  /* 2: work1 = geom + z-prep + weight conversion */
  work1_kernel<<<625 + 1 + 52, 256>>>(positions, shifts, edge_index, node_z, p_WF, Wms2);
  /* 3 */
  msg1_kernel<<<1024, 256>>>(R1);
  /* 4: stage C = sU2, vU2, grouped s2, e1+e0 — BIG tiles */
  {
    TOps P; tops_init(P);
    tops_add(P, 0, CDIV(NN,TNB),   0, p_A0, p_sU2, NN,   ALPHA_, 0, p_tabU2, 1, 0);
    tops_add(P, 0, CDIV(3*NN,TNB), 1, p_A1, p_vU2, 3*NN, ALPHA_, 0, 0, 0, 0);
    tops_add(P, 1, GTZ_BIG*NE_,    2, p_A0, p_s2,  NN,   ALPHA_, 0, p_tabS2, 0, 0);
    tops_add(P, 2, CDIV(NN*32,512), 0, 0, 0, NN, 0.f, 0, 0, 0, 0);
    tgemm_big_kernel<<<tops_total(P), 512, TG_SMEM>>>(P, node_z, batch, ae);
  }
  /* 5: msg2 edges + Dsj2/Dvj zero blocks */
  msg2_kernel<<<MSG2_EB + MSG2_ZB, 256>>>(R2);
  /* 6: s2 += a*A2@Wms2 — SMALL tiles */
  {
    TOps P; tops_init(P);
    tops_add(P, 0, CDIV(NN,TNS), 12, p_A2, p_s2, NN, ALPHA_, 1, 0, 0, 0);
    tgemm_sm_kernel<<<tops_total(P), 256, TG_SMEM>>>(P, node_z);
  }
  /* 7 */
  mlp_kernel<<<2048, 128>>>(Wmlp, wout, batch);
  /* 8: dA2 = a*ds2@Wms2^T ; grouped dA0 = a*ds2@WF2z^T — SMALL tiles */
  {
    TOps P; tops_init(P);
    tops_add(P, 0, CDIV(NN,TNS), 25, p_ds2, p_dA2, NN, ALPHA_, 0, 0, 0, 0);
    tops_add(P, 1, GTZ_SM*NE_,   15, p_ds2, p_dA0, NN, ALPHA_, 0, 0, 0, 0);
    tgemm_sm_kernel<<<tops_total(P), 256, TG_SMEM>>>(P, node_z);
  }
  /* 9 */
  bwd2_kernel<<<1024, 256>>>(R2);
  /* 10: dA0 += a*(Dsj2@WF1^T + u^T) ; dA1 = a*Dvj@Wfuse^T — SMALL tiles */
  {
    TOps P; tops_init(P);
    tops_add(P, 0, CDIV(NN,TNS),   13, p_Dsj2, p_dA0, NN,   ALPHA_, 1, 0, 0, p_u);
    tops_add(P, 0, CDIV(3*NN,TNS), 14, p_Dvj,  p_dA1, 3*NN, ALPHA_, 0, 0, 0, 0);
    tgemm_sm_kernel<<<tops_total(P), 256, TG_SMEM>>>(P, node_z);
  }
  /* 11: bwd1 + fused geometry backward + forces + finalize */
  bwd1_kernel<<<1024 + 1, 256>>>(R1, out + GG + 3*GG, out);
}